// round 6
// baseline (speedup 1.0000x reference)
#include <cuda_runtime.h>
#include <cuda_bf16.h>
#include <math.h>
#include <stdint.h>

#define BB 4
#define TT 1024
#define SS 1024
#define DD 1024
#define HH 16
#define DKD 64
#define DFFN 4096
#define LN_EPS 1e-6f

// ===================== scratch (no allocations) =====================
__device__ float g_v [BB*TT*DD];
__device__ float g_t1[BB*TT*DD];
__device__ float g_x1[BB*TT*DD];
__device__ float g_x2[BB*TT*DD];
__device__ float g_st[64ULL * 1024 * 2];          // per (z,q): max, inv_sum

__device__ __nv_bfloat16 g_a3 [4096ULL * 3072];   // activations [M,3K] (hi|lo|hi)
__device__ __nv_bfloat16 g_q3 [4096ULL * 3072];   // Q split A-fmt
__device__ __nv_bfloat16 g_k3 [4096ULL * 3072];   // K split B-fmt (hi|hi|lo)
__device__ __nv_bfloat16 g_ff3[4096ULL * 12288];
__device__ __nv_bfloat16 g_vt3[4096ULL * 3072];   // V^T split per (b,h): [64 d][hi|hi|lo seq]
#define W3D (1024ULL*3072)
#define W1OFF (8*W3D)
#define W2OFF (8*W3D + 4096ULL*3072)
__device__ __nv_bfloat16 g_wt3[8*W3D + 4096ULL*3072 + 1024ULL*12288];

// ===================== helpers =====================
__device__ __forceinline__ uint32_t pack_hi2(float x, float y) {
    __nv_bfloat16 a = __float2bfloat16(x), b = __float2bfloat16(y);
    return (uint32_t)__bfloat16_as_ushort(a) | ((uint32_t)__bfloat16_as_ushort(b) << 16);
}
__device__ __forceinline__ uint32_t pack_lo2(float x, float y) {
    __nv_bfloat16 a = __float2bfloat16(x), b = __float2bfloat16(y);
    __nv_bfloat16 ra = __float2bfloat16(x - __bfloat162float(a));
    __nv_bfloat16 rb = __float2bfloat16(y - __bfloat162float(b));
    return (uint32_t)__bfloat16_as_ushort(ra) | ((uint32_t)__bfloat16_as_ushort(rb) << 16);
}
__device__ __forceinline__ void mma_bf16(
    float* d, const uint32_t* a, const uint32_t* b)
{
    asm volatile(
        "mma.sync.aligned.m16n8k16.row.col.f32.bf16.bf16.f32 "
        "{%0,%1,%2,%3}, {%4,%5,%6,%7}, {%8,%9}, {%0,%1,%2,%3};"
        : "+f"(d[0]), "+f"(d[1]), "+f"(d[2]), "+f"(d[3])
        : "r"(a[0]), "r"(a[1]), "r"(a[2]), "r"(a[3]), "r"(b[0]), "r"(b[1]));
}
__device__ __forceinline__ uint32_t smem_u32(const void* p) {
    uint32_t a;
    asm("{ .reg .u64 t; cvta.to.shared.u64 t, %1; cvt.u32.u64 %0, t; }" : "=r"(a) : "l"(p));
    return a;
}
__device__ __forceinline__ void cp16(uint32_t s, const void* g) {
    asm volatile("cp.async.cg.shared.global [%0], [%1], 16;" :: "r"(s), "l"(g));
}
#define CP_COMMIT() asm volatile("cp.async.commit_group;" ::: "memory")
#define CP_WAIT2()  asm volatile("cp.async.wait_group 2;" ::: "memory")
__device__ __forceinline__ void ldm4(uint32_t& r0, uint32_t& r1, uint32_t& r2, uint32_t& r3, uint32_t a) {
    asm volatile("ldmatrix.sync.aligned.m8n8.x4.shared.b16 {%0,%1,%2,%3}, [%4];"
        : "=r"(r0), "=r"(r1), "=r"(r2), "=r"(r3) : "r"(a));
}

// ===================== split/convert kernels =====================
__global__ __launch_bounds__(256) void split_act(
    const float* __restrict__ A, __nv_bfloat16* __restrict__ O)
{
    const int K = 1024;
    size_t idx = (size_t)blockIdx.x * 256 + threadIdx.x;
    size_t base = idx << 2;
    size_t m = base >> 10;
    int k = (int)(base & (size_t)(K - 1));
    float4 v = *(const float4*)(A + base);
    uint2 hh, ll;
    hh.x = pack_hi2(v.x, v.y); hh.y = pack_hi2(v.z, v.w);
    ll.x = pack_lo2(v.x, v.y); ll.y = pack_lo2(v.z, v.w);
    __nv_bfloat16* row = O + m * (size_t)(3 * K);
    *(uint2*)(row + k)         = hh;
    *(uint2*)(row + K + k)     = ll;
    *(uint2*)(row + 2 * K + k) = hh;
}

__global__ void split_w(
    const float* __restrict__ W, __nv_bfloat16* __restrict__ O, int K, int N)
{
    __shared__ float t[32][33];
    int k = blockIdx.y * 32 + threadIdx.y;
    int n = blockIdx.x * 32 + threadIdx.x;
    t[threadIdx.y][threadIdx.x] = W[(size_t)k * N + n];
    __syncthreads();
    int nn = blockIdx.x * 32 + threadIdx.y;
    int kk = blockIdx.y * 32 + threadIdx.x;
    float v = t[threadIdx.x][threadIdx.y];
    __nv_bfloat16 h = __float2bfloat16(v);
    __nv_bfloat16 l = __float2bfloat16(v - __bfloat162float(h));
    size_t ro = (size_t)nn * (size_t)(3 * K);
    O[ro + kk]         = h;
    O[ro + K + kk]     = h;
    O[ro + 2 * K + kk] = l;
}

__global__ void vt_split(
    const float* __restrict__ V, __nv_bfloat16* __restrict__ VT3)
{
    __shared__ float t[32][33];
    const int b = blockIdx.z;
    int k = blockIdx.x * 32 + threadIdx.y;
    int d = blockIdx.y * 32 + threadIdx.x;
    t[threadIdx.y][threadIdx.x] = V[((size_t)(b * TT + k)) * DD + d];
    __syncthreads();
    int dg = blockIdx.y * 32 + threadIdx.y;
    int kg = blockIdx.x * 32 + threadIdx.x;
    float v = t[threadIdx.x][threadIdx.y];
    __nv_bfloat16 h = __float2bfloat16(v);
    __nv_bfloat16 l = __float2bfloat16(v - __bfloat162float(h));
    int hh = dg >> 6, dk = dg & 63;
    size_t row = ((size_t)(b * HH + hh) * 64 + dk) * 3072;
    VT3[row + kg]        = h;
    VT3[row + 1024 + kg] = h;
    VT3[row + 2048 + kg] = l;
}

// ===================== HMMA GEMM, cp.async pipelined =====================
#define PADK 40
#define STAGES 4
#define SSTRIDE (2 * 128 * PADK * 2)
#define GEMM_SMEM (STAGES * SSTRIDE)

__global__ __launch_bounds__(256) void gemm_mma(
    const __nv_bfloat16* __restrict__ A3, const __nv_bfloat16* __restrict__ WT3,
    const float* __restrict__ bias, float* __restrict__ C,
    __nv_bfloat16* __restrict__ O3, int N, int K3, int relu, int ofmt)
{
    extern __shared__ char dsm[];
    const uint32_t sb = smem_u32(dsm);
    const int tid = threadIdx.x;
    const int lane = tid & 31, wid = tid >> 5;
    const int wm = wid >> 2, wn = wid & 3;
    const int grp = lane >> 2, tg = lane & 3;

    const size_t arow0 = (size_t)blockIdx.y * 128;
    const size_t bcol0 = (size_t)blockIdx.x * 128;

    const int r0 = tid >> 2, s0c = (tid & 3) * 8;
    const int r1 = r0 + 64;
    const __nv_bfloat16* gA0 = A3  + (arow0 + r0) * (size_t)K3 + s0c;
    const __nv_bfloat16* gA1 = A3  + (arow0 + r1) * (size_t)K3 + s0c;
    const __nv_bfloat16* gB0 = WT3 + (bcol0 + r0) * (size_t)K3 + s0c;
    const __nv_bfloat16* gB1 = WT3 + (bcol0 + r1) * (size_t)K3 + s0c;
    const uint32_t so0 = (uint32_t)(r0 * PADK + s0c) * 2;
    const uint32_t so1 = (uint32_t)(r1 * PADK + s0c) * 2;

    const uint32_t aLM = (uint32_t)(((wm * 64) + (lane & 15)) * PADK + (lane >> 4) * 8) * 2;
    const uint32_t bLM = (uint32_t)(((wn * 32) + (lane & 15)) * PADK + (lane >> 4) * 8) * 2;

    float acc[4][4][4];
    #pragma unroll
    for (int i = 0; i < 4; i++)
        #pragma unroll
        for (int j = 0; j < 4; j++)
            #pragma unroll
            for (int q = 0; q < 4; q++) acc[i][j][q] = 0.f;

    const int NC = K3 >> 5;

    auto issue = [&](int c, int s) {
        uint32_t ab = sb + s * SSTRIDE;
        uint32_t bb = ab + 128 * PADK * 2;
        size_t off = (size_t)c * 32;
        cp16(ab + so0, gA0 + off);
        cp16(ab + so1, gA1 + off);
        cp16(bb + so0, gB0 + off);
        cp16(bb + so1, gB1 + off);
        CP_COMMIT();
    };

    issue(0, 0); issue(1, 1); issue(2, 2);

    for (int c = 0; c < NC; c++) {
        CP_WAIT2();
        __syncthreads();
        const int nxt = c + 3;
        if (nxt < NC) issue(nxt, nxt & 3); else CP_COMMIT();

        const uint32_t As0 = sb + (c & 3) * SSTRIDE;
        const uint32_t Bs0 = As0 + 128 * PADK * 2;
        #pragma unroll
        for (int ks = 0; ks < 2; ks++) {
            const uint32_t ko = ks * 32;
            uint32_t a[4][4], b[4][2];
            #pragma unroll
            for (int ms = 0; ms < 4; ms++)
                ldm4(a[ms][0], a[ms][1], a[ms][2], a[ms][3],
                     As0 + aLM + ms * (16 * PADK * 2) + ko);
            ldm4(b[0][0], b[1][0], b[0][1], b[1][1], Bs0 + bLM + ko);
            ldm4(b[2][0], b[3][0], b[2][1], b[3][1], Bs0 + bLM + 16 * PADK * 2 + ko);
            #pragma unroll
            for (int ms = 0; ms < 4; ms++)
                #pragma unroll
                for (int ns = 0; ns < 4; ns++)
                    mma_bf16(acc[ms][ns], a[ms], b[ns]);
        }
    }

    if (O3) {
        const size_t rstride = (size_t)3 * N;
        #pragma unroll
        for (int ms = 0; ms < 4; ms++) {
            const size_t rr0 = arow0 + wm * 64 + ms * 16 + grp;
            #pragma unroll
            for (int ns = 0; ns < 4; ns++) {
                const size_t cc = bcol0 + wn * 32 + ns * 8 + tg * 2;
                float bx = bias[cc], by = bias[cc + 1];
                float v0 = acc[ms][ns][0] + bx;
                float v1 = acc[ms][ns][1] + by;
                float v2 = acc[ms][ns][2] + bx;
                float v3 = acc[ms][ns][3] + by;
                if (relu) {
                    v0 = fmaxf(v0, 0.f); v1 = fmaxf(v1, 0.f);
                    v2 = fmaxf(v2, 0.f); v3 = fmaxf(v3, 0.f);
                }
                uint32_t h01 = pack_hi2(v0, v1), l01 = pack_lo2(v0, v1);
                uint32_t h23 = pack_hi2(v2, v3), l23 = pack_lo2(v2, v3);
                __nv_bfloat16* R0 = O3 + rr0 * rstride;
                __nv_bfloat16* R1 = O3 + (rr0 + 8) * rstride;
                if (ofmt == 0) {
                    *(uint32_t*)(R0 + cc)         = h01;
                    *(uint32_t*)(R0 + N + cc)     = l01;
                    *(uint32_t*)(R0 + 2 * N + cc) = h01;
                    *(uint32_t*)(R1 + cc)         = h23;
                    *(uint32_t*)(R1 + N + cc)     = l23;
                    *(uint32_t*)(R1 + 2 * N + cc) = h23;
                } else {
                    *(uint32_t*)(R0 + cc)         = h01;
                    *(uint32_t*)(R0 + N + cc)     = h01;
                    *(uint32_t*)(R0 + 2 * N + cc) = l01;
                    *(uint32_t*)(R1 + cc)         = h23;
                    *(uint32_t*)(R1 + N + cc)     = h23;
                    *(uint32_t*)(R1 + 2 * N + cc) = l23;
                }
            }
        }
    } else {
        #pragma unroll
        for (int ms = 0; ms < 4; ms++) {
            const size_t rr0 = arow0 + wm * 64 + ms * 16 + grp;
            #pragma unroll
            for (int ns = 0; ns < 4; ns++) {
                const size_t cc = bcol0 + wn * 32 + ns * 8 + tg * 2;
                float bx = bias[cc], by = bias[cc + 1];
                float v0 = acc[ms][ns][0] + bx;
                float v1 = acc[ms][ns][1] + by;
                float v2 = acc[ms][ns][2] + bx;
                float v3 = acc[ms][ns][3] + by;
                if (relu) {
                    v0 = fmaxf(v0, 0.f); v1 = fmaxf(v1, 0.f);
                    v2 = fmaxf(v2, 0.f); v3 = fmaxf(v3, 0.f);
                }
                *(float2*)(C + rr0 * N + cc)       = make_float2(v0, v1);
                *(float2*)(C + (rr0 + 8) * N + cc) = make_float2(v2, v3);
            }
        }
    }
}

// ===================== flash attention =====================
// Both kernels: q-tile 128, 8 warps each owning 16 q rows (full 64-k per warp).
// S-mma structure MUST be identical in both kernels (bit-exact recompute).
#define FSP 200
#define STATS_SMEM ((128 + 64) * FSP * 2)
#define AV_SMEM    ((128 + 64 + 64) * FSP * 2)

__global__ __launch_bounds__(256) void flash_stats(
    const __nv_bfloat16* __restrict__ Q3, const __nv_bfloat16* __restrict__ K3,
    float* __restrict__ st, int causal)
{
    extern __shared__ __nv_bfloat16 sm[];
    __nv_bfloat16* Qs = sm;               // [128][FSP]
    __nv_bfloat16* Ks = sm + 128 * FSP;   // [64][FSP]
    const int z = blockIdx.y, b = z >> 4, h = z & 15;
    const int q0 = blockIdx.x * 128;
    const int tid = threadIdx.x, lane = tid & 31, wid = tid >> 5;
    const int grp = lane >> 2, tg = lane & 3;

    for (int i = tid; i < 3072; i += 256) {
        int r = i / 24, rem = i - r * 24;
        int seg = rem >> 3, j = rem & 7;
        uint4 v = *(const uint4*)(Q3 + ((size_t)(b * TT + q0 + r)) * 3072 + seg * 1024 + h * 64 + j * 8);
        *(uint4*)(Qs + r * FSP + seg * 64 + j * 8) = v;
    }

    const uint32_t QsU = smem_u32(Qs), KsU = smem_u32(Ks);
    const uint32_t aLM = QsU + (uint32_t)((wid * 16 + (lane & 15)) * FSP + (lane >> 4) * 8) * 2;
    const uint32_t bB  = KsU + (uint32_t)(((lane & 15)) * FSP + (lane >> 4) * 8) * 2;

    float m[2] = {-1e30f, -1e30f}, s[2] = {0.f, 0.f};
    const int qr = q0 + wid * 16 + grp;
    const int ktend = causal ? ((q0 >> 6) + 2) : 16;

    for (int kt = 0; kt < ktend; kt++) {
        const int k0 = kt * 64;
        __syncthreads();
        for (int i = tid; i < 1536; i += 256) {
            int r = i / 24, rem = i - r * 24;
            int seg = rem >> 3, j = rem & 7;
            uint4 v = *(const uint4*)(K3 + ((size_t)(b * TT + k0 + r)) * 3072 + seg * 1024 + h * 64 + j * 8);
            *(uint4*)(Ks + r * FSP + seg * 64 + j * 8) = v;
        }
        __syncthreads();

        float acc[8][4];
        #pragma unroll
        for (int ni = 0; ni < 8; ni++)
            #pragma unroll
            for (int q = 0; q < 4; q++) acc[ni][q] = 0.f;

        #pragma unroll
        for (int ks = 0; ks < 12; ks++) {
            const uint32_t ko = ks * 32;
            uint32_t a[4], bb[8][2];
            ldm4(a[0], a[1], a[2], a[3], aLM + ko);
            #pragma unroll
            for (int nb = 0; nb < 4; nb++)
                ldm4(bb[nb*2][0], bb[nb*2+1][0], bb[nb*2][1], bb[nb*2+1][1],
                     bB + nb * (16 * FSP * 2) + ko);
            #pragma unroll
            for (int ni = 0; ni < 8; ni++)
                mma_bf16(acc[ni], a, bb[ni]);
        }

        const int mask_tile = causal && (k0 + 63 > q0);
        #pragma unroll
        for (int half = 0; half < 2; half++) {
            const int q = qr + half * 8;
            float vv[16];
            float tm = -1e30f;
            #pragma unroll
            for (int ni = 0; ni < 8; ni++) {
                #pragma unroll
                for (int e = 0; e < 2; e++) {
                    float v = acc[ni][half * 2 + e] * 0.125f;
                    int k = k0 + ni * 8 + tg * 2 + e;
                    if (mask_tile && k > q) v = -1e30f;
                    vv[ni * 2 + e] = v;
                    tm = fmaxf(tm, v);
                }
            }
            float mn = fmaxf(m[half], tm);
            float as = 0.f;
            #pragma unroll
            for (int i = 0; i < 16; i++) as += __expf(vv[i] - mn);
            s[half] = s[half] * __expf(m[half] - mn) + as;
            m[half] = mn;
        }
    }

    #pragma unroll
    for (int half = 0; half < 2; half++) {
        #pragma unroll
        for (int o = 1; o <= 2; o <<= 1) {
            float mo = __shfl_xor_sync(0xffffffffu, m[half], o);
            float so = __shfl_xor_sync(0xffffffffu, s[half], o);
            float mn = fmaxf(m[half], mo);
            s[half] = s[half] * __expf(m[half] - mn) + so * __expf(mo - mn);
            m[half] = mn;
        }
        if (tg == 0) {
            int q = qr + half * 8;
            st[((size_t)z * TT + q) * 2]     = m[half];
            st[((size_t)z * TT + q) * 2 + 1] = 1.0f / s[half];
        }
    }
}

__global__ __launch_bounds__(256) void flash_av(
    const __nv_bfloat16* __restrict__ Q3, const __nv_bfloat16* __restrict__ K3,
    const __nv_bfloat16* __restrict__ VT3, const float* __restrict__ st,
    float* __restrict__ Pout, __nv_bfloat16* __restrict__ A3out, int causal)
{
    extern __shared__ __nv_bfloat16 sm[];
    __nv_bfloat16* Qs = sm;
    __nv_bfloat16* Ks = sm + 128 * FSP;
    __nv_bfloat16* Vs = sm + (128 + 64) * FSP;
    const int z = blockIdx.y, b = z >> 4, h = z & 15;
    const int q0 = blockIdx.x * 128;
    const int tid = threadIdx.x, lane = tid & 31, wid = tid >> 5;
    const int grp = lane >> 2, tg = lane & 3;

    for (int i = tid; i < 3072; i += 256) {
        int r = i / 24, rem = i - r * 24;
        int seg = rem >> 3, j = rem & 7;
        uint4 v = *(const uint4*)(Q3 + ((size_t)(b * TT + q0 + r)) * 3072 + seg * 1024 + h * 64 + j * 8);
        *(uint4*)(Qs + r * FSP + seg * 64 + j * 8) = v;
    }

    const uint32_t QsU = smem_u32(Qs), KsU = smem_u32(Ks), VsU = smem_u32(Vs);
    const uint32_t aLM = QsU + (uint32_t)((wid * 16 + (lane & 15)) * FSP + (lane >> 4) * 8) * 2;
    const uint32_t bB  = KsU + (uint32_t)(((lane & 15)) * FSP + (lane >> 4) * 8) * 2;
    const uint32_t vB  = VsU + (uint32_t)(((lane & 15)) * FSP + (lane >> 4) * 8) * 2;

    const int qr = q0 + wid * 16 + grp;
    const float m0 = st[((size_t)z * TT + qr) * 2];
    const float i0 = st[((size_t)z * TT + qr) * 2 + 1];
    const float m1 = st[((size_t)z * TT + qr + 8) * 2];
    const float i1 = st[((size_t)z * TT + qr + 8) * 2 + 1];
    float* P0 = Pout + ((size_t)z * TT + qr) * TT;
    float* P1 = P0 + 8 * TT;

    float accO[8][4];
    #pragma unroll
    for (int ni = 0; ni < 8; ni++)
        #pragma unroll
        for (int q = 0; q < 4; q++) accO[ni][q] = 0.f;

    const int ktend = causal ? ((q0 >> 6) + 2) : 16;
    for (int kt = 0; kt < ktend; kt++) {
        const int k0 = kt * 64;
        __syncthreads();
        for (int i = tid; i < 1536; i += 256) {
            int r = i / 24, rem = i - r * 24;
            int seg = rem >> 3, j = rem & 7;
            uint4 kv = *(const uint4*)(K3 + ((size_t)(b * TT + k0 + r)) * 3072 + seg * 1024 + h * 64 + j * 8);
            *(uint4*)(Ks + r * FSP + seg * 64 + j * 8) = kv;
            uint4 vv = *(const uint4*)(VT3 + ((size_t)z * 64 + r) * 3072 + seg * 1024 + k0 + j * 8);
            *(uint4*)(Vs + r * FSP + seg * 64 + j * 8) = vv;
        }
        __syncthreads();

        float acc[8][4];
        #pragma unroll
        for (int ni = 0; ni < 8; ni++)
            #pragma unroll
            for (int q = 0; q < 4; q++) acc[ni][q] = 0.f;

        #pragma unroll
        for (int ks = 0; ks < 12; ks++) {
            const uint32_t ko = ks * 32;
            uint32_t a[4], bb[8][2];
            ldm4(a[0], a[1], a[2], a[3], aLM + ko);
            #pragma unroll
            for (int nb = 0; nb < 4; nb++)
                ldm4(bb[nb*2][0], bb[nb*2+1][0], bb[nb*2][1], bb[nb*2+1][1],
                     bB + nb * (16 * FSP * 2) + ko);
            #pragma unroll
            for (int ni = 0; ni < 8; ni++)
                mma_bf16(acc[ni], a, bb[ni]);
        }

        // softmax-apply + P write + register pack
        const int mask_tile = causal && (k0 + 63 > q0);
        uint32_t ph[16], pl[16];
        #pragma unroll
        for (int ni = 0; ni < 8; ni++) {
            float p[4];
            #pragma unroll
            for (int e = 0; e < 2; e++) {
                int k = k0 + ni * 8 + tg * 2 + e;
                float v0 = acc[ni][e] * 0.125f;
                float v1 = acc[ni][2 + e] * 0.125f;
                p[e]     = (mask_tile && k > qr)     ? 0.f : __expf(v0 - m0) * i0;
                p[2 + e] = (mask_tile && k > qr + 8) ? 0.f : __expf(v1 - m1) * i1;
            }
            *(float2*)(P0 + k0 + ni * 8 + tg * 2) = make_float2(p[0], p[1]);
            *(float2*)(P1 + k0 + ni * 8 + tg * 2) = make_float2(p[2], p[3]);
            int c = ni >> 1, slot = (ni & 1) * 2;
            ph[c * 4 + slot]     = pack_hi2(p[0], p[1]);
            ph[c * 4 + slot + 1] = pack_hi2(p[2], p[3]);
            pl[c * 4 + slot]     = pack_lo2(p[0], p[1]);
            pl[c * 4 + slot + 1] = pack_lo2(p[2], p[3]);
        }

        // O += P @ V  (A from registers, B from Vs)
        #pragma unroll
        for (int ks = 0; ks < 12; ks++) {
            const uint32_t ko = ks * 32;
            const uint32_t* af = (ks < 4) ? &ph[ks * 4] : (ks < 8 ? &pl[(ks - 4) * 4] : &ph[(ks - 8) * 4]);
            uint32_t vb[8][2];
            #pragma unroll
            for (int nb = 0; nb < 4; nb++)
                ldm4(vb[nb*2][0], vb[nb*2+1][0], vb[nb*2][1], vb[nb*2+1][1],
                     vB + nb * (16 * FSP * 2) + ko);
            #pragma unroll
            for (int ni = 0; ni < 8; ni++)
                mma_bf16(accO[ni], af, vb[ni]);
        }
    }

    // zero upper-triangle P region (causal)
    if (causal) {
        const int kend = ktend * 64;
        const int Z = TT - kend;
        if (Z > 0) {
            const int zw = Z >> 2;
            const int n4 = 128 * zw;
            const float4 z4 = make_float4(0.f, 0.f, 0.f, 0.f);
            for (int i = tid; i < n4; i += 256) {
                int r = i / zw, c = kend + (i - r * zw) * 4;
                *(float4*)(Pout + ((size_t)z * TT + q0 + r) * TT + c) = z4;
            }
        }
    }

    // O -> A3 split (hi|lo|hi), head slice
    __nv_bfloat16* R0 = A3out + (size_t)(b * TT + qr) * 3072;
    __nv_bfloat16* R1 = R0 + 8 * 3072;
    #pragma unroll
    for (int ni = 0; ni < 8; ni++) {
        const int cc = h * 64 + ni * 8 + tg * 2;
        float v0 = accO[ni][0], v1 = accO[ni][1];
        float v2 = accO[ni][2], v3 = accO[ni][3];
        *(uint32_t*)(R0 + cc)        = pack_hi2(v0, v1);
        *(uint32_t*)(R0 + 1024 + cc) = pack_lo2(v0, v1);
        *(uint32_t*)(R0 + 2048 + cc) = pack_hi2(v0, v1);
        *(uint32_t*)(R1 + cc)        = pack_hi2(v2, v3);
        *(uint32_t*)(R1 + 1024 + cc) = pack_lo2(v2, v3);
        *(uint32_t*)(R1 + 2048 + cc) = pack_hi2(v2, v3);
    }
}

// ===================== residual add + LayerNorm =====================
__global__ __launch_bounds__(256) void add_ln(
    const float* __restrict__ X, const float* __restrict__ Dl,
    const float* __restrict__ g, const float* __restrict__ be,
    float* __restrict__ O, __nv_bfloat16* __restrict__ S3)
{
    const int row = blockIdx.x;
    const float* x  = X  + (size_t)row * DD;
    const float* dl = Dl + (size_t)row * DD;
    const int tid = threadIdx.x;

    float v[4];
    float s = 0.f;
    #pragma unroll
    for (int i = 0; i < 4; i++) {
        int c = tid + i * 256;
        v[i] = x[c] + dl[c];
        s += v[i];
    }
    __shared__ float red[8];
    #pragma unroll
    for (int o = 16; o > 0; o >>= 1) s += __shfl_xor_sync(0xffffffffu, s, o);
    if ((tid & 31) == 0) red[tid >> 5] = s;
    __syncthreads();
    s = 0.f;
    #pragma unroll
    for (int w = 0; w < 8; w++) s += red[w];
    float mean = s * (1.0f / 1024.0f);

    float qq = 0.f;
    #pragma unroll
    for (int i = 0; i < 4; i++) { float d = v[i] - mean; qq += d * d; }
    __syncthreads();
    #pragma unroll
    for (int o = 16; o > 0; o >>= 1) qq += __shfl_xor_sync(0xffffffffu, qq, o);
    if ((tid & 31) == 0) red[tid >> 5] = qq;
    __syncthreads();
    qq = 0.f;
    #pragma unroll
    for (int w = 0; w < 8; w++) qq += red[w];

    float stdv = sqrtf(qq * (1.0f / 1023.0f));
    float inv = 1.0f / (stdv + LN_EPS);
    __nv_bfloat16* R = S3 ? (S3 + (size_t)row * 3072) : (__nv_bfloat16*)0;
    #pragma unroll
    for (int i = 0; i < 4; i++) {
        int c = tid + i * 256;
        float o = g[c] * (v[i] - mean) * inv + be[c];
        O[(size_t)row * DD + c] = o;
        if (R) {
            __nv_bfloat16 h = __float2bfloat16(o);
            __nv_bfloat16 l = __float2bfloat16(o - __bfloat162float(h));
            R[c]        = h;
            R[1024 + c] = l;
            R[2048 + c] = h;
        }
    }
}

// ===================== orchestration =====================
extern "C" void kernel_launch(void* const* d_in, const int* in_sizes, int n_in,
                              void* d_out, int out_size)
{
    const float* x        = (const float*)d_in[0];
    const float* enc      = (const float*)d_in[1];
    const float* wq_s = (const float*)d_in[4],  *bq_s = (const float*)d_in[5];
    const float* wk_s = (const float*)d_in[6],  *bk_s = (const float*)d_in[7];
    const float* wv_s = (const float*)d_in[8],  *bv_s = (const float*)d_in[9];
    const float* wo_s = (const float*)d_in[10], *bo_s = (const float*)d_in[11];
    const float* wq_c = (const float*)d_in[12], *bq_c = (const float*)d_in[13];
    const float* wk_c = (const float*)d_in[14], *bk_c = (const float*)d_in[15];
    const float* wv_c = (const float*)d_in[16], *bv_c = (const float*)d_in[17];
    const float* wo_c = (const float*)d_in[18], *bo_c = (const float*)d_in[19];
    const float* w1   = (const float*)d_in[20], *b1   = (const float*)d_in[21];
    const float* w2   = (const float*)d_in[22], *b2   = (const float*)d_in[23];
    const float* g1   = (const float*)d_in[24], *be1  = (const float*)d_in[25];
    const float* g2   = (const float*)d_in[26], *be2  = (const float*)d_in[27];
    const float* g3   = (const float*)d_in[28], *be3  = (const float*)d_in[29];

    float* out     = (float*)d_out;
    float* self_w  = out + (size_t)BB * TT * DD;
    float* cross_w = self_w + (size_t)BB * HH * TT * TT;

    float *V, *T1, *X1, *X2, *ST;
    __nv_bfloat16 *A3, *Q3, *K3, *FF3, *WT3, *VT3;
    cudaGetSymbolAddress((void**)&V,   g_v);
    cudaGetSymbolAddress((void**)&T1,  g_t1);
    cudaGetSymbolAddress((void**)&X1,  g_x1);
    cudaGetSymbolAddress((void**)&X2,  g_x2);
    cudaGetSymbolAddress((void**)&ST,  g_st);
    cudaGetSymbolAddress((void**)&A3,  g_a3);
    cudaGetSymbolAddress((void**)&Q3,  g_q3);
    cudaGetSymbolAddress((void**)&K3,  g_k3);
    cudaGetSymbolAddress((void**)&FF3, g_ff3);
    cudaGetSymbolAddress((void**)&WT3, g_wt3);
    cudaGetSymbolAddress((void**)&VT3, g_vt3);

    cudaFuncSetAttribute(gemm_mma,    cudaFuncAttributeMaxDynamicSharedMemorySize, GEMM_SMEM);
    cudaFuncSetAttribute(flash_stats, cudaFuncAttributeMaxDynamicSharedMemorySize, STATS_SMEM);
    cudaFuncSetAttribute(flash_av,    cudaFuncAttributeMaxDynamicSharedMemorySize, AV_SMEM);

    const int M = BB * TT;
    dim3 blk(256);
    dim3 tp32(32, 32);
    dim3 gD(DD / 128, M / 128);
    dim3 gF(DFFN / 128, M / 128);
    dim3 flG(TT / 128, BB * HH);
    dim3 vtG(TT / 32, DD / 32, BB);
    dim3 lnG(M);
    const int ACT_BLKS = M * DD / 4 / 256;
    float* NC = (float*)0;
    __nv_bfloat16* NO3 = (__nv_bfloat16*)0;

    // ---- weight transpose + split ----
    split_w<<<dim3(32, 32), tp32>>>(wq_s, WT3 + 0 * W3D, DD, DD);
    split_w<<<dim3(32, 32), tp32>>>(wk_s, WT3 + 1 * W3D, DD, DD);
    split_w<<<dim3(32, 32), tp32>>>(wv_s, WT3 + 2 * W3D, DD, DD);
    split_w<<<dim3(32, 32), tp32>>>(wo_s, WT3 + 3 * W3D, DD, DD);
    split_w<<<dim3(32, 32), tp32>>>(wq_c, WT3 + 4 * W3D, DD, DD);
    split_w<<<dim3(32, 32), tp32>>>(wk_c, WT3 + 5 * W3D, DD, DD);
    split_w<<<dim3(32, 32), tp32>>>(wv_c, WT3 + 6 * W3D, DD, DD);
    split_w<<<dim3(32, 32), tp32>>>(wo_c, WT3 + 7 * W3D, DD, DD);
    split_w<<<dim3(128, 32), tp32>>>(w1, WT3 + W1OFF, DD, DFFN);
    split_w<<<dim3(32, 128), tp32>>>(w2, WT3 + W2OFF, DFFN, DD);

    // ---- self attention ----
    split_act<<<ACT_BLKS, blk>>>(x, A3);
    gemm_mma<<<gD, blk, GEMM_SMEM>>>(A3, WT3 + 0 * W3D, bq_s, NC, Q3, DD, 3072, 0, 0);
    gemm_mma<<<gD, blk, GEMM_SMEM>>>(A3, WT3 + 1 * W3D, bk_s, NC, K3, DD, 3072, 0, 1);
    gemm_mma<<<gD, blk, GEMM_SMEM>>>(A3, WT3 + 2 * W3D, bv_s, V, NO3, DD, 3072, 0, 0);
    vt_split<<<vtG, tp32>>>(V, VT3);
    flash_stats<<<flG, blk, STATS_SMEM>>>(Q3, K3, ST, 1);
    flash_av<<<flG, blk, AV_SMEM>>>(Q3, K3, VT3, ST, self_w, A3, 1);
    gemm_mma<<<gD, blk, GEMM_SMEM>>>(A3, WT3 + 3 * W3D, bo_s, T1, NO3, DD, 3072, 0, 0);
    add_ln<<<lnG, blk>>>(x, T1, g1, be1, X1, A3);

    // ---- cross attention ----
    gemm_mma<<<gD, blk, GEMM_SMEM>>>(A3, WT3 + 4 * W3D, bq_c, NC, Q3, DD, 3072, 0, 0);
    split_act<<<ACT_BLKS, blk>>>(enc, A3);
    gemm_mma<<<gD, blk, GEMM_SMEM>>>(A3, WT3 + 5 * W3D, bk_c, NC, K3, DD, 3072, 0, 1);
    gemm_mma<<<gD, blk, GEMM_SMEM>>>(A3, WT3 + 6 * W3D, bv_c, V, NO3, DD, 3072, 0, 0);
    vt_split<<<vtG, tp32>>>(V, VT3);
    flash_stats<<<flG, blk, STATS_SMEM>>>(Q3, K3, ST, 0);
    flash_av<<<flG, blk, AV_SMEM>>>(Q3, K3, VT3, ST, cross_w, A3, 0);
    gemm_mma<<<gD, blk, GEMM_SMEM>>>(A3, WT3 + 7 * W3D, bo_c, T1, NO3, DD, 3072, 0, 0);
    add_ln<<<lnG, blk>>>(X1, T1, g2, be2, X2, A3);

    // ---- feed-forward ----
    gemm_mma<<<gF, blk, GEMM_SMEM>>>(A3, WT3 + W1OFF, b1, NC, FF3, DFFN, 3072, 1, 0);
    gemm_mma<<<gD, blk, GEMM_SMEM>>>(FF3, WT3 + W2OFF, b2, T1, NO3, DD, 12288, 0, 0);
    add_ln<<<lnG, blk>>>(X2, T1, g3, be3, out, NO3);

    (void)in_sizes; (void)n_in; (void)out_size;
}

// round 7
// speedup vs baseline: 1.0103x; 1.0103x over previous
#include <cuda_runtime.h>
#include <cuda_bf16.h>
#include <math.h>
#include <stdint.h>

#define BB 4
#define TT 1024
#define SS 1024
#define DD 1024
#define HH 16
#define DKD 64
#define DFFN 4096
#define LN_EPS 1e-6f

// ===================== scratch (no allocations) =====================
__device__ float g_v [BB*TT*DD];
__device__ float g_t1[BB*TT*DD];
__device__ float g_x1[BB*TT*DD];
__device__ float g_x2[BB*TT*DD];

__device__ __nv_bfloat16 g_a3 [4096ULL * 3072];   // activations [M,3K] (hi|lo|hi)
__device__ __nv_bfloat16 g_q3 [4096ULL * 3072];   // Q split A-fmt (hi|lo|hi)
__device__ __nv_bfloat16 g_k3 [4096ULL * 3072];   // K split B-fmt (hi|hi|lo)
__device__ __nv_bfloat16 g_ff3[4096ULL * 12288];
__device__ __nv_bfloat16 g_vt3[4096ULL * 3072];   // V^T split per (b,h): [64 d][hi|hi|lo seq]
#define W3D (1024ULL*3072)
#define W1OFF (8*W3D)
#define W2OFF (8*W3D + 4096ULL*3072)
__device__ __nv_bfloat16 g_wt3[8*W3D + 4096ULL*3072 + 1024ULL*12288];

// ===================== helpers =====================
__device__ __forceinline__ uint32_t pack_hi2(float x, float y) {
    __nv_bfloat16 a = __float2bfloat16(x), b = __float2bfloat16(y);
    return (uint32_t)__bfloat16_as_ushort(a) | ((uint32_t)__bfloat16_as_ushort(b) << 16);
}
__device__ __forceinline__ uint32_t pack_lo2(float x, float y) {
    __nv_bfloat16 a = __float2bfloat16(x), b = __float2bfloat16(y);
    __nv_bfloat16 ra = __float2bfloat16(x - __bfloat162float(a));
    __nv_bfloat16 rb = __float2bfloat16(y - __bfloat162float(b));
    return (uint32_t)__bfloat16_as_ushort(ra) | ((uint32_t)__bfloat16_as_ushort(rb) << 16);
}
__device__ __forceinline__ void mma_bf16(
    float* d, const uint32_t* a, const uint32_t* b)
{
    asm volatile(
        "mma.sync.aligned.m16n8k16.row.col.f32.bf16.bf16.f32 "
        "{%0,%1,%2,%3}, {%4,%5,%6,%7}, {%8,%9}, {%0,%1,%2,%3};"
        : "+f"(d[0]), "+f"(d[1]), "+f"(d[2]), "+f"(d[3])
        : "r"(a[0]), "r"(a[1]), "r"(a[2]), "r"(a[3]), "r"(b[0]), "r"(b[1]));
}
__device__ __forceinline__ uint32_t smem_u32(const void* p) {
    uint32_t a;
    asm("{ .reg .u64 t; cvta.to.shared.u64 t, %1; cvt.u32.u64 %0, t; }" : "=r"(a) : "l"(p));
    return a;
}
__device__ __forceinline__ void cp16(uint32_t s, const void* g) {
    asm volatile("cp.async.cg.shared.global [%0], [%1], 16;" :: "r"(s), "l"(g));
}
#define CP_COMMIT() asm volatile("cp.async.commit_group;" ::: "memory")
#define CP_WAIT2()  asm volatile("cp.async.wait_group 2;" ::: "memory")
__device__ __forceinline__ void ldm4(uint32_t& r0, uint32_t& r1, uint32_t& r2, uint32_t& r3, uint32_t a) {
    asm volatile("ldmatrix.sync.aligned.m8n8.x4.shared.b16 {%0,%1,%2,%3}, [%4];"
        : "=r"(r0), "=r"(r1), "=r"(r2), "=r"(r3) : "r"(a));
}

// ===================== split/convert kernels =====================
__global__ __launch_bounds__(256) void split_act(
    const float* __restrict__ A, __nv_bfloat16* __restrict__ O)
{
    const int K = 1024;
    size_t idx = (size_t)blockIdx.x * 256 + threadIdx.x;
    size_t base = idx << 2;
    size_t m = base >> 10;
    int k = (int)(base & (size_t)(K - 1));
    float4 v = *(const float4*)(A + base);
    uint2 hh, ll;
    hh.x = pack_hi2(v.x, v.y); hh.y = pack_hi2(v.z, v.w);
    ll.x = pack_lo2(v.x, v.y); ll.y = pack_lo2(v.z, v.w);
    __nv_bfloat16* row = O + m * (size_t)(3 * K);
    *(uint2*)(row + k)         = hh;
    *(uint2*)(row + K + k)     = ll;
    *(uint2*)(row + 2 * K + k) = hh;
}

__global__ void split_w(
    const float* __restrict__ W, __nv_bfloat16* __restrict__ O, int K, int N)
{
    __shared__ float t[32][33];
    int k = blockIdx.y * 32 + threadIdx.y;
    int n = blockIdx.x * 32 + threadIdx.x;
    t[threadIdx.y][threadIdx.x] = W[(size_t)k * N + n];
    __syncthreads();
    int nn = blockIdx.x * 32 + threadIdx.y;
    int kk = blockIdx.y * 32 + threadIdx.x;
    float v = t[threadIdx.x][threadIdx.y];
    __nv_bfloat16 h = __float2bfloat16(v);
    __nv_bfloat16 l = __float2bfloat16(v - __bfloat162float(h));
    size_t ro = (size_t)nn * (size_t)(3 * K);
    O[ro + kk]         = h;
    O[ro + K + kk]     = h;
    O[ro + 2 * K + kk] = l;
}

__global__ void vt_split(
    const float* __restrict__ V, __nv_bfloat16* __restrict__ VT3)
{
    __shared__ float t[32][33];
    const int b = blockIdx.z;
    int k = blockIdx.x * 32 + threadIdx.y;
    int d = blockIdx.y * 32 + threadIdx.x;
    t[threadIdx.y][threadIdx.x] = V[((size_t)(b * TT + k)) * DD + d];
    __syncthreads();
    int dg = blockIdx.y * 32 + threadIdx.y;
    int kg = blockIdx.x * 32 + threadIdx.x;
    float v = t[threadIdx.x][threadIdx.y];
    __nv_bfloat16 h = __float2bfloat16(v);
    __nv_bfloat16 l = __float2bfloat16(v - __bfloat162float(h));
    int hh = dg >> 6, dk = dg & 63;
    size_t row = ((size_t)(b * HH + hh) * 64 + dk) * 3072;
    VT3[row + kg]        = h;
    VT3[row + 1024 + kg] = h;
    VT3[row + 2048 + kg] = l;
}

// ===================== HMMA GEMM, cp.async pipelined =====================
#define PADK 40
#define STAGES 4
#define SSTRIDE (2 * 128 * PADK * 2)
#define GEMM_SMEM (STAGES * SSTRIDE)

__global__ __launch_bounds__(256) void gemm_mma(
    const __nv_bfloat16* __restrict__ A3, const __nv_bfloat16* __restrict__ WT3,
    const float* __restrict__ bias, float* __restrict__ C,
    __nv_bfloat16* __restrict__ O3, int N, int K3, int relu, int ofmt)
{
    extern __shared__ char dsm[];
    const uint32_t sb = smem_u32(dsm);
    const int tid = threadIdx.x;
    const int lane = tid & 31, wid = tid >> 5;
    const int wm = wid >> 2, wn = wid & 3;
    const int grp = lane >> 2, tg = lane & 3;

    const size_t arow0 = (size_t)blockIdx.y * 128;
    const size_t bcol0 = (size_t)blockIdx.x * 128;

    const int r0 = tid >> 2, s0c = (tid & 3) * 8;
    const int r1 = r0 + 64;
    const __nv_bfloat16* gA0 = A3  + (arow0 + r0) * (size_t)K3 + s0c;
    const __nv_bfloat16* gA1 = A3  + (arow0 + r1) * (size_t)K3 + s0c;
    const __nv_bfloat16* gB0 = WT3 + (bcol0 + r0) * (size_t)K3 + s0c;
    const __nv_bfloat16* gB1 = WT3 + (bcol0 + r1) * (size_t)K3 + s0c;
    const uint32_t so0 = (uint32_t)(r0 * PADK + s0c) * 2;
    const uint32_t so1 = (uint32_t)(r1 * PADK + s0c) * 2;

    const uint32_t aLM = (uint32_t)(((wm * 64) + (lane & 15)) * PADK + (lane >> 4) * 8) * 2;
    const uint32_t bLM = (uint32_t)(((wn * 32) + (lane & 15)) * PADK + (lane >> 4) * 8) * 2;

    float acc[4][4][4];
    #pragma unroll
    for (int i = 0; i < 4; i++)
        #pragma unroll
        for (int j = 0; j < 4; j++)
            #pragma unroll
            for (int q = 0; q < 4; q++) acc[i][j][q] = 0.f;

    const int NC = K3 >> 5;

    auto issue = [&](int c, int s) {
        uint32_t ab = sb + s * SSTRIDE;
        uint32_t bb = ab + 128 * PADK * 2;
        size_t off = (size_t)c * 32;
        cp16(ab + so0, gA0 + off);
        cp16(ab + so1, gA1 + off);
        cp16(bb + so0, gB0 + off);
        cp16(bb + so1, gB1 + off);
        CP_COMMIT();
    };

    issue(0, 0); issue(1, 1); issue(2, 2);

    for (int c = 0; c < NC; c++) {
        CP_WAIT2();
        __syncthreads();
        const int nxt = c + 3;
        if (nxt < NC) issue(nxt, nxt & 3); else CP_COMMIT();

        const uint32_t As0 = sb + (c & 3) * SSTRIDE;
        const uint32_t Bs0 = As0 + 128 * PADK * 2;
        #pragma unroll
        for (int ks = 0; ks < 2; ks++) {
            const uint32_t ko = ks * 32;
            uint32_t a[4][4], b[4][2];
            #pragma unroll
            for (int ms = 0; ms < 4; ms++)
                ldm4(a[ms][0], a[ms][1], a[ms][2], a[ms][3],
                     As0 + aLM + ms * (16 * PADK * 2) + ko);
            ldm4(b[0][0], b[1][0], b[0][1], b[1][1], Bs0 + bLM + ko);
            ldm4(b[2][0], b[3][0], b[2][1], b[3][1], Bs0 + bLM + 16 * PADK * 2 + ko);
            #pragma unroll
            for (int ms = 0; ms < 4; ms++)
                #pragma unroll
                for (int ns = 0; ns < 4; ns++)
                    mma_bf16(acc[ms][ns], a[ms], b[ns]);
        }
    }

    if (O3) {
        const size_t rstride = (size_t)3 * N;
        #pragma unroll
        for (int ms = 0; ms < 4; ms++) {
            const size_t rr0 = arow0 + wm * 64 + ms * 16 + grp;
            #pragma unroll
            for (int ns = 0; ns < 4; ns++) {
                const size_t cc = bcol0 + wn * 32 + ns * 8 + tg * 2;
                float bx = bias[cc], by = bias[cc + 1];
                float v0 = acc[ms][ns][0] + bx;
                float v1 = acc[ms][ns][1] + by;
                float v2 = acc[ms][ns][2] + bx;
                float v3 = acc[ms][ns][3] + by;
                if (relu) {
                    v0 = fmaxf(v0, 0.f); v1 = fmaxf(v1, 0.f);
                    v2 = fmaxf(v2, 0.f); v3 = fmaxf(v3, 0.f);
                }
                uint32_t h01 = pack_hi2(v0, v1), l01 = pack_lo2(v0, v1);
                uint32_t h23 = pack_hi2(v2, v3), l23 = pack_lo2(v2, v3);
                __nv_bfloat16* R0 = O3 + rr0 * rstride;
                __nv_bfloat16* R1 = O3 + (rr0 + 8) * rstride;
                if (ofmt == 0) {
                    *(uint32_t*)(R0 + cc)         = h01;
                    *(uint32_t*)(R0 + N + cc)     = l01;
                    *(uint32_t*)(R0 + 2 * N + cc) = h01;
                    *(uint32_t*)(R1 + cc)         = h23;
                    *(uint32_t*)(R1 + N + cc)     = l23;
                    *(uint32_t*)(R1 + 2 * N + cc) = h23;
                } else {
                    *(uint32_t*)(R0 + cc)         = h01;
                    *(uint32_t*)(R0 + N + cc)     = h01;
                    *(uint32_t*)(R0 + 2 * N + cc) = l01;
                    *(uint32_t*)(R1 + cc)         = h23;
                    *(uint32_t*)(R1 + N + cc)     = h23;
                    *(uint32_t*)(R1 + 2 * N + cc) = l23;
                }
            }
        }
    } else {
        #pragma unroll
        for (int ms = 0; ms < 4; ms++) {
            const size_t rr0 = arow0 + wm * 64 + ms * 16 + grp;
            #pragma unroll
            for (int ns = 0; ns < 4; ns++) {
                const size_t cc = bcol0 + wn * 32 + ns * 8 + tg * 2;
                float bx = bias[cc], by = bias[cc + 1];
                float v0 = acc[ms][ns][0] + bx;
                float v1 = acc[ms][ns][1] + by;
                float v2 = acc[ms][ns][2] + bx;
                float v3 = acc[ms][ns][3] + by;
                if (relu) {
                    v0 = fmaxf(v0, 0.f); v1 = fmaxf(v1, 0.f);
                    v2 = fmaxf(v2, 0.f); v3 = fmaxf(v3, 0.f);
                }
                *(float2*)(C + rr0 * N + cc)       = make_float2(v0, v1);
                *(float2*)(C + (rr0 + 8) * N + cc) = make_float2(v2, v3);
            }
        }
    }
}

// ===================== attention scores (HMMA, pre-split inputs) ============
#define SPADK 200
#define SCORES_SMEM ((128 + 64) * SPADK * 2)
__global__ __launch_bounds__(256) void attn_scores_mma(
    const __nv_bfloat16* __restrict__ Q3, const __nv_bfloat16* __restrict__ K3,
    float* __restrict__ Sc, int causal)
{
    extern __shared__ __nv_bfloat16 sm[];
    __nv_bfloat16* As = sm;                 // [128][SPADK]  Q: [hi|lo|hi]
    __nv_bfloat16* Bs = sm + 128 * SPADK;   // [64][SPADK]   K: [hi|hi|lo]
    const int z = blockIdx.z, b = z >> 4, h = z & 15;
    const int q0 = blockIdx.y * 128, k0 = blockIdx.x * 64;
    if (causal && k0 >= q0 + 128) return;

    const int tid = threadIdx.x, lane = tid & 31, wid = tid >> 5;
    const int wm = wid >> 1, wn = wid & 1;
    const int grp = lane >> 2, tg = lane & 3;

    // coalesced uint4 copies of pre-split slices (head h)
    for (int i = tid; i < 3072; i += 256) {
        int r = i / 24, rem = i - r * 24;
        int seg = rem >> 3, j = rem & 7;
        uint4 v = *(const uint4*)(Q3 + ((size_t)(b * TT + q0 + r)) * 3072 + seg * 1024 + h * 64 + j * 8);
        *(uint4*)(As + r * SPADK + seg * 64 + j * 8) = v;
    }
    for (int i = tid; i < 1536; i += 256) {
        int r = i / 24, rem = i - r * 24;
        int seg = rem >> 3, j = rem & 7;
        uint4 v = *(const uint4*)(K3 + ((size_t)(b * TT + k0 + r)) * 3072 + seg * 1024 + h * 64 + j * 8);
        *(uint4*)(Bs + r * SPADK + seg * 64 + j * 8) = v;
    }
    __syncthreads();

    const uint32_t AsU = smem_u32(As), BsU = smem_u32(Bs);
    const uint32_t aLM = AsU + (uint32_t)(((wm * 32) + (lane & 15)) * SPADK + (lane >> 4) * 8) * 2;
    const uint32_t bLM = BsU + (uint32_t)(((wn * 32) + (lane & 15)) * SPADK + (lane >> 4) * 8) * 2;

    float acc[2][4][4];
    #pragma unroll
    for (int i = 0; i < 2; i++)
        #pragma unroll
        for (int j = 0; j < 4; j++)
            #pragma unroll
            for (int q = 0; q < 4; q++) acc[i][j][q] = 0.f;

    #pragma unroll
    for (int ks = 0; ks < 12; ks++) {
        const uint32_t ko = ks * 32;
        uint32_t a[2][4], bfr[4][2];
        #pragma unroll
        for (int mi = 0; mi < 2; mi++)
            ldm4(a[mi][0], a[mi][1], a[mi][2], a[mi][3],
                 aLM + mi * (16 * SPADK * 2) + ko);
        ldm4(bfr[0][0], bfr[1][0], bfr[0][1], bfr[1][1], bLM + ko);
        ldm4(bfr[2][0], bfr[3][0], bfr[2][1], bfr[3][1], bLM + 16 * SPADK * 2 + ko);
        #pragma unroll
        for (int mi = 0; mi < 2; mi++)
            #pragma unroll
            for (int ni = 0; ni < 4; ni++)
                mma_bf16(acc[mi][ni], a[mi], bfr[ni]);
    }

    float* Out = Sc + ((size_t)z * TT + q0) * TT + k0;
    #pragma unroll
    for (int mi = 0; mi < 2; mi++) {
        const size_t r = wm * 32 + mi * 16 + grp;
        #pragma unroll
        for (int ni = 0; ni < 4; ni++) {
            const size_t c = wn * 32 + ni * 8 + tg * 2;
            *(float2*)(Out + r * TT + c) =
                make_float2(acc[mi][ni][0] * 0.125f, acc[mi][ni][1] * 0.125f);
            *(float2*)(Out + (r + 8) * TT + c) =
                make_float2(acc[mi][ni][2] * 0.125f, acc[mi][ni][3] * 0.125f);
        }
    }
}

// ===================== attn @ V (HMMA + pre-transposed V) =====================
#define AV_SMEM ((64 + 64) * SPADK * 2)
__global__ __launch_bounds__(256) void attn_av_mma(
    const float* __restrict__ P, const __nv_bfloat16* __restrict__ VT3,
    __nv_bfloat16* __restrict__ A3out, int causal)
{
    extern __shared__ __nv_bfloat16 sm[];
    __nv_bfloat16* As = sm;                // [64][SPADK]  P: [hi|lo|hi]
    __nv_bfloat16* Bs = sm + 64 * SPADK;   // [64][SPADK]  V^T: [hi|hi|lo]
    const int z = blockIdx.y, b = z >> 4, h = z & 15;
    const int q0 = blockIdx.x * 64;

    const int tid = threadIdx.x, lane = tid & 31, wid = tid >> 5;
    const int wm = wid >> 1, wn = wid & 1;
    const int grp = lane >> 2, tg = lane & 3;

    const __nv_bfloat16* Vt = VT3 + (size_t)z * 64 * 3072;

    const uint32_t AsU = smem_u32(As), BsU = smem_u32(Bs);
    const uint32_t aLM = AsU + (uint32_t)(((wm * 16) + (lane & 15)) * SPADK + (lane >> 4) * 8) * 2;
    const uint32_t bLM = BsU + (uint32_t)(((wn * 32) + (lane & 15)) * SPADK + (lane >> 4) * 8) * 2;

    float acc[4][4];
    #pragma unroll
    for (int i = 0; i < 4; i++)
        #pragma unroll
        for (int j = 0; j < 4; j++) acc[i][j] = 0.f;

    const int kend = causal ? (q0 + 64) : TT;
    for (int k0 = 0; k0 < kend; k0 += 64) {
        const float* Pb = P + ((size_t)z * TT + q0) * TT + k0;
        #pragma unroll
        for (int i = 0; i < 4; i++) {
            int f = tid + i * 256;
            int r = f >> 4, c = (f & 15) << 2;
            float4 pv = *(const float4*)(Pb + (size_t)r * TT + c);
            uint2 hh, ll;
            hh.x = pack_hi2(pv.x, pv.y); hh.y = pack_hi2(pv.z, pv.w);
            ll.x = pack_lo2(pv.x, pv.y); ll.y = pack_lo2(pv.z, pv.w);
            __nv_bfloat16* R = As + r * SPADK;
            *(uint2*)(R + c)       = hh;
            *(uint2*)(R + 64 + c)  = ll;
            *(uint2*)(R + 128 + c) = hh;
        }
        #pragma unroll
        for (int i = 0; i < 6; i++) {
            int idx = tid + i * 256;
            int d = idx / 24, rem = idx - d * 24;
            int band = rem >> 3, j = rem & 7;
            uint4 v = *(const uint4*)(Vt + (size_t)d * 3072 + band * 1024 + k0 + j * 8);
            *(uint4*)(Bs + d * SPADK + band * 64 + j * 8) = v;
        }
        __syncthreads();
        #pragma unroll
        for (int ks = 0; ks < 12; ks++) {
            const uint32_t ko = ks * 32;
            uint32_t a[4], bfr[4][2];
            ldm4(a[0], a[1], a[2], a[3], aLM + ko);
            ldm4(bfr[0][0], bfr[1][0], bfr[0][1], bfr[1][1], bLM + ko);
            ldm4(bfr[2][0], bfr[3][0], bfr[2][1], bfr[3][1], bLM + 16 * SPADK * 2 + ko);
            #pragma unroll
            for (int ni = 0; ni < 4; ni++)
                mma_bf16(acc[ni], a, bfr[ni]);
        }
        __syncthreads();
    }

    const size_t m0 = (size_t)b * TT + q0 + wm * 16 + grp;
    const size_t m1 = m0 + 8;
    __nv_bfloat16* R0 = A3out + m0 * 3072;
    __nv_bfloat16* R1 = A3out + m1 * 3072;
    #pragma unroll
    for (int ni = 0; ni < 4; ni++) {
        const int cc = h * DKD + wn * 32 + ni * 8 + tg * 2;
        float v0 = acc[ni][0], v1 = acc[ni][1];
        float v2 = acc[ni][2], v3 = acc[ni][3];
        *(uint32_t*)(R0 + cc)        = pack_hi2(v0, v1);
        *(uint32_t*)(R0 + 1024 + cc) = pack_lo2(v0, v1);
        *(uint32_t*)(R0 + 2048 + cc) = pack_hi2(v0, v1);
        *(uint32_t*)(R1 + cc)        = pack_hi2(v2, v3);
        *(uint32_t*)(R1 + 1024 + cc) = pack_lo2(v2, v3);
        *(uint32_t*)(R1 + 2048 + cc) = pack_hi2(v2, v3);
    }
}

// ===================== softmax =====================
__global__ __launch_bounds__(256) void softmax_mask(
    float* __restrict__ Sc, const int* __restrict__ mask, int mode)
{
    const int q = blockIdx.x, z = blockIdx.y;
    const int b = z >> 4;
    float* row = Sc + ((size_t)z * TT + q) * TT;
    const int tid = threadIdx.x;

    float v[4];
    float mx = -3.0e38f;
    if (mode == 0) {
        const int L = q + 1;
        #pragma unroll
        for (int i = 0; i < 4; i++) {
            int k = tid + i * 256;
            if (k < L) { v[i] = row[k]; mx = fmaxf(mx, v[i]); }
            else v[i] = -1e30f;
        }
    } else {
        #pragma unroll
        for (int i = 0; i < 4; i++) {
            int k = tid + i * 256;
            float s = row[k];
            int mv = mask[b * SS + k];
            v[i] = (mv == 0) ? -1e9f : s;
            mx = fmaxf(mx, v[i]);
        }
    }

    __shared__ float red[8];
    __shared__ float red2[8];
    #pragma unroll
    for (int o = 16; o > 0; o >>= 1) mx = fmaxf(mx, __shfl_xor_sync(0xffffffffu, mx, o));
    if ((tid & 31) == 0) red[tid >> 5] = mx;
    __syncthreads();
    mx = red[0];
    #pragma unroll
    for (int w = 1; w < 8; w++) mx = fmaxf(mx, red[w]);

    float sum = 0.f;
    if (mode == 0) {
        const int L = q + 1;
        #pragma unroll
        for (int i = 0; i < 4; i++) {
            int k = tid + i * 256;
            v[i] = (k < L) ? __expf(v[i] - mx) : 0.f;
            sum += v[i];
        }
    } else {
        #pragma unroll
        for (int i = 0; i < 4; i++) { v[i] = __expf(v[i] - mx); sum += v[i]; }
    }
    #pragma unroll
    for (int o = 16; o > 0; o >>= 1) sum += __shfl_xor_sync(0xffffffffu, sum, o);
    if ((tid & 31) == 0) red2[tid >> 5] = sum;
    __syncthreads();
    sum = 0.f;
    #pragma unroll
    for (int w = 0; w < 8; w++) sum += red2[w];
    float inv = 1.0f / sum;
    #pragma unroll
    for (int i = 0; i < 4; i++) row[tid + i * 256] = v[i] * inv;
}

// ===================== residual add + LayerNorm =====================
__global__ __launch_bounds__(256) void add_ln(
    const float* __restrict__ X, const float* __restrict__ Dl,
    const float* __restrict__ g, const float* __restrict__ be,
    float* __restrict__ O, __nv_bfloat16* __restrict__ S3)
{
    const int row = blockIdx.x;
    const float* x  = X  + (size_t)row * DD;
    const float* dl = Dl + (size_t)row * DD;
    const int tid = threadIdx.x;

    float v[4];
    float s = 0.f;
    #pragma unroll
    for (int i = 0; i < 4; i++) {
        int c = tid + i * 256;
        v[i] = x[c] + dl[c];
        s += v[i];
    }
    __shared__ float red[8];
    #pragma unroll
    for (int o = 16; o > 0; o >>= 1) s += __shfl_xor_sync(0xffffffffu, s, o);
    if ((tid & 31) == 0) red[tid >> 5] = s;
    __syncthreads();
    s = 0.f;
    #pragma unroll
    for (int w = 0; w < 8; w++) s += red[w];
    float mean = s * (1.0f / 1024.0f);

    float qq = 0.f;
    #pragma unroll
    for (int i = 0; i < 4; i++) { float d = v[i] - mean; qq += d * d; }
    __syncthreads();
    #pragma unroll
    for (int o = 16; o > 0; o >>= 1) qq += __shfl_xor_sync(0xffffffffu, qq, o);
    if ((tid & 31) == 0) red[tid >> 5] = qq;
    __syncthreads();
    qq = 0.f;
    #pragma unroll
    for (int w = 0; w < 8; w++) qq += red[w];

    float stdv = sqrtf(qq * (1.0f / 1023.0f));
    float inv = 1.0f / (stdv + LN_EPS);
    __nv_bfloat16* R = S3 ? (S3 + (size_t)row * 3072) : (__nv_bfloat16*)0;
    #pragma unroll
    for (int i = 0; i < 4; i++) {
        int c = tid + i * 256;
        float o = g[c] * (v[i] - mean) * inv + be[c];
        O[(size_t)row * DD + c] = o;
        if (R) {
            __nv_bfloat16 h = __float2bfloat16(o);
            __nv_bfloat16 l = __float2bfloat16(o - __bfloat162float(h));
            R[c]        = h;
            R[1024 + c] = l;
            R[2048 + c] = h;
        }
    }
}

// ===================== orchestration =====================
extern "C" void kernel_launch(void* const* d_in, const int* in_sizes, int n_in,
                              void* d_out, int out_size)
{
    const float* x        = (const float*)d_in[0];
    const float* enc      = (const float*)d_in[1];
    const int*   src_mask = (const int*)  d_in[2];
    const float* wq_s = (const float*)d_in[4],  *bq_s = (const float*)d_in[5];
    const float* wk_s = (const float*)d_in[6],  *bk_s = (const float*)d_in[7];
    const float* wv_s = (const float*)d_in[8],  *bv_s = (const float*)d_in[9];
    const float* wo_s = (const float*)d_in[10], *bo_s = (const float*)d_in[11];
    const float* wq_c = (const float*)d_in[12], *bq_c = (const float*)d_in[13];
    const float* wk_c = (const float*)d_in[14], *bk_c = (const float*)d_in[15];
    const float* wv_c = (const float*)d_in[16], *bv_c = (const float*)d_in[17];
    const float* wo_c = (const float*)d_in[18], *bo_c = (const float*)d_in[19];
    const float* w1   = (const float*)d_in[20], *b1   = (const float*)d_in[21];
    const float* w2   = (const float*)d_in[22], *b2   = (const float*)d_in[23];
    const float* g1   = (const float*)d_in[24], *be1  = (const float*)d_in[25];
    const float* g2   = (const float*)d_in[26], *be2  = (const float*)d_in[27];
    const float* g3   = (const float*)d_in[28], *be3  = (const float*)d_in[29];

    float* out     = (float*)d_out;
    float* self_w  = out + (size_t)BB * TT * DD;
    float* cross_w = self_w + (size_t)BB * HH * TT * TT;

    float *V, *T1, *X1, *X2;
    __nv_bfloat16 *A3, *Q3, *K3, *FF3, *WT3, *VT3;
    cudaGetSymbolAddress((void**)&V,   g_v);
    cudaGetSymbolAddress((void**)&T1,  g_t1);
    cudaGetSymbolAddress((void**)&X1,  g_x1);
    cudaGetSymbolAddress((void**)&X2,  g_x2);
    cudaGetSymbolAddress((void**)&A3,  g_a3);
    cudaGetSymbolAddress((void**)&Q3,  g_q3);
    cudaGetSymbolAddress((void**)&K3,  g_k3);
    cudaGetSymbolAddress((void**)&FF3, g_ff3);
    cudaGetSymbolAddress((void**)&WT3, g_wt3);
    cudaGetSymbolAddress((void**)&VT3, g_vt3);

    cudaFuncSetAttribute(gemm_mma,        cudaFuncAttributeMaxDynamicSharedMemorySize, GEMM_SMEM);
    cudaFuncSetAttribute(attn_scores_mma, cudaFuncAttributeMaxDynamicSharedMemorySize, SCORES_SMEM);
    cudaFuncSetAttribute(attn_av_mma,     cudaFuncAttributeMaxDynamicSharedMemorySize, AV_SMEM);

    const int M = BB * TT;
    dim3 blk(256);
    dim3 tp32(32, 32);
    dim3 gD(DD / 128, M / 128);
    dim3 gF(DFFN / 128, M / 128);
    dim3 scoreG(TT / 64, TT / 128, BB * HH);
    dim3 smaxG(TT, BB * HH);
    dim3 avG(TT / 64, BB * HH);
    dim3 vtG(TT / 32, DD / 32, BB);
    dim3 lnG(M);
    const int ACT_BLKS = M * DD / 4 / 256;
    float* NC = (float*)0;
    __nv_bfloat16* NO3 = (__nv_bfloat16*)0;

    // ---- weight transpose + split ----
    split_w<<<dim3(32, 32), tp32>>>(wq_s, WT3 + 0 * W3D, DD, DD);
    split_w<<<dim3(32, 32), tp32>>>(wk_s, WT3 + 1 * W3D, DD, DD);
    split_w<<<dim3(32, 32), tp32>>>(wv_s, WT3 + 2 * W3D, DD, DD);
    split_w<<<dim3(32, 32), tp32>>>(wo_s, WT3 + 3 * W3D, DD, DD);
    split_w<<<dim3(32, 32), tp32>>>(wq_c, WT3 + 4 * W3D, DD, DD);
    split_w<<<dim3(32, 32), tp32>>>(wk_c, WT3 + 5 * W3D, DD, DD);
    split_w<<<dim3(32, 32), tp32>>>(wv_c, WT3 + 6 * W3D, DD, DD);
    split_w<<<dim3(32, 32), tp32>>>(wo_c, WT3 + 7 * W3D, DD, DD);
    split_w<<<dim3(128, 32), tp32>>>(w1, WT3 + W1OFF, DD, DFFN);
    split_w<<<dim3(32, 128), tp32>>>(w2, WT3 + W2OFF, DFFN, DD);

    // ---- self attention ----
    split_act<<<ACT_BLKS, blk>>>(x, A3);
    gemm_mma<<<gD, blk, GEMM_SMEM>>>(A3, WT3 + 0 * W3D, bq_s, NC, Q3, DD, 3072, 0, 0);
    gemm_mma<<<gD, blk, GEMM_SMEM>>>(A3, WT3 + 1 * W3D, bk_s, NC, K3, DD, 3072, 0, 1);
    gemm_mma<<<gD, blk, GEMM_SMEM>>>(A3, WT3 + 2 * W3D, bv_s, V, NO3, DD, 3072, 0, 0);
    vt_split<<<vtG, tp32>>>(V, VT3);
    attn_scores_mma<<<scoreG, blk, SCORES_SMEM>>>(Q3, K3, self_w, 1);
    softmax_mask<<<smaxG, blk>>>(self_w, src_mask, 0);
    attn_av_mma<<<avG, blk, AV_SMEM>>>(self_w, VT3, A3, 1);
    gemm_mma<<<gD, blk, GEMM_SMEM>>>(A3, WT3 + 3 * W3D, bo_s, T1, NO3, DD, 3072, 0, 0);
    add_ln<<<lnG, blk>>>(x, T1, g1, be1, X1, A3);

    // ---- cross attention ----
    gemm_mma<<<gD, blk, GEMM_SMEM>>>(A3, WT3 + 4 * W3D, bq_c, NC, Q3, DD, 3072, 0, 0);
    split_act<<<ACT_BLKS, blk>>>(enc, A3);
    gemm_mma<<<gD, blk, GEMM_SMEM>>>(A3, WT3 + 5 * W3D, bk_c, NC, K3, DD, 3072, 0, 1);
    gemm_mma<<<gD, blk, GEMM_SMEM>>>(A3, WT3 + 6 * W3D, bv_c, V, NO3, DD, 3072, 0, 0);
    vt_split<<<vtG, tp32>>>(V, VT3);
    attn_scores_mma<<<scoreG, blk, SCORES_SMEM>>>(Q3, K3, cross_w, 0);
    softmax_mask<<<smaxG, blk>>>(cross_w, src_mask, 1);
    attn_av_mma<<<avG, blk, AV_SMEM>>>(cross_w, VT3, A3, 0);
    gemm_mma<<<gD, blk, GEMM_SMEM>>>(A3, WT3 + 7 * W3D, bo_c, T1, NO3, DD, 3072, 0, 0);
    add_ln<<<lnG, blk>>>(X1, T1, g2, be2, X2, A3);

    // ---- feed-forward ----
    gemm_mma<<<gF, blk, GEMM_SMEM>>>(A3, WT3 + W1OFF, b1, NC, FF3, DFFN, 3072, 1, 0);
    gemm_mma<<<gD, blk, GEMM_SMEM>>>(FF3, WT3 + W2OFF, b2, T1, NO3, DD, 12288, 0, 0);
    add_ln<<<lnG, blk>>>(X2, T1, g3, be3, out, NO3);

    (void)in_sizes; (void)n_in; (void)out_size;
}

// round 8
// speedup vs baseline: 1.0878x; 1.0767x over previous
#include <cuda_runtime.h>
#include <cuda_bf16.h>
#include <math.h>
#include <stdint.h>

#define BB 4
#define TT 1024
#define SS 1024
#define DD 1024
#define HH 16
#define DKD 64
#define DFFN 4096
#define LN_EPS 1e-6f

// ===================== scratch (no allocations) =====================
__device__ float g_q [BB*TT*DD];
__device__ float g_k [BB*TT*DD];
__device__ float g_v [BB*TT*DD];
__device__ float g_t1[BB*TT*DD];
__device__ float g_x1[BB*TT*DD];
__device__ float g_x2[BB*TT*DD];

__device__ __nv_bfloat16 g_a3 [4096ULL * 3072];   // activations [M,3K] (hi|lo|hi)
__device__ __nv_bfloat16 g_ff3[4096ULL * 12288];  // FF activations
__device__ __nv_bfloat16 g_vt3[4096ULL * 3072];   // V^T split per (b,h): [64 d][hi|hi|lo seq]
#define W3D (1024ULL*3072)
#define W1OFF (8*W3D)
#define W2OFF (8*W3D + 4096ULL*3072)
__device__ __nv_bfloat16 g_wt3[8*W3D + 4096ULL*3072 + 1024ULL*12288];

// ===================== helpers =====================
__device__ __forceinline__ uint32_t pack_hi2(float x, float y) {
    __nv_bfloat16 a = __float2bfloat16(x), b = __float2bfloat16(y);
    return (uint32_t)__bfloat16_as_ushort(a) | ((uint32_t)__bfloat16_as_ushort(b) << 16);
}
__device__ __forceinline__ uint32_t pack_lo2(float x, float y) {
    __nv_bfloat16 a = __float2bfloat16(x), b = __float2bfloat16(y);
    __nv_bfloat16 ra = __float2bfloat16(x - __bfloat162float(a));
    __nv_bfloat16 rb = __float2bfloat16(y - __bfloat162float(b));
    return (uint32_t)__bfloat16_as_ushort(ra) | ((uint32_t)__bfloat16_as_ushort(rb) << 16);
}
__device__ __forceinline__ void mma_bf16(
    float* d, const uint32_t* a, const uint32_t* b)
{
    asm volatile(
        "mma.sync.aligned.m16n8k16.row.col.f32.bf16.bf16.f32 "
        "{%0,%1,%2,%3}, {%4,%5,%6,%7}, {%8,%9}, {%0,%1,%2,%3};"
        : "+f"(d[0]), "+f"(d[1]), "+f"(d[2]), "+f"(d[3])
        : "r"(a[0]), "r"(a[1]), "r"(a[2]), "r"(a[3]), "r"(b[0]), "r"(b[1]));
}
__device__ __forceinline__ uint32_t smem_u32(const void* p) {
    uint32_t a;
    asm("{ .reg .u64 t; cvta.to.shared.u64 t, %1; cvt.u32.u64 %0, t; }" : "=r"(a) : "l"(p));
    return a;
}
__device__ __forceinline__ void cp16(uint32_t s, const void* g) {
    asm volatile("cp.async.cg.shared.global [%0], [%1], 16;" :: "r"(s), "l"(g));
}
#define CP_COMMIT() asm volatile("cp.async.commit_group;" ::: "memory")
#define CP_WAIT2()  asm volatile("cp.async.wait_group 2;" ::: "memory")
__device__ __forceinline__ void ldm4(uint32_t& r0, uint32_t& r1, uint32_t& r2, uint32_t& r3, uint32_t a) {
    asm volatile("ldmatrix.sync.aligned.m8n8.x4.shared.b16 {%0,%1,%2,%3}, [%4];"
        : "=r"(r0), "=r"(r1), "=r"(r2), "=r"(r3) : "r"(a));
}

// ===================== split/convert kernels =====================
__global__ __launch_bounds__(256) void split_act(
    const float* __restrict__ A, __nv_bfloat16* __restrict__ O)
{
    const int K = 1024;
    size_t idx = (size_t)blockIdx.x * 256 + threadIdx.x;
    size_t base = idx << 2;
    size_t m = base >> 10;
    int k = (int)(base & (size_t)(K - 1));
    float4 v = *(const float4*)(A + base);
    uint2 hh, ll;
    hh.x = pack_hi2(v.x, v.y); hh.y = pack_hi2(v.z, v.w);
    ll.x = pack_lo2(v.x, v.y); ll.y = pack_lo2(v.z, v.w);
    __nv_bfloat16* row = O + m * (size_t)(3 * K);
    *(uint2*)(row + k)         = hh;
    *(uint2*)(row + K + k)     = ll;
    *(uint2*)(row + 2 * K + k) = hh;
}

__global__ void split_w(
    const float* __restrict__ W, __nv_bfloat16* __restrict__ O, int K, int N)
{
    __shared__ float t[32][33];
    int k = blockIdx.y * 32 + threadIdx.y;
    int n = blockIdx.x * 32 + threadIdx.x;
    t[threadIdx.y][threadIdx.x] = W[(size_t)k * N + n];
    __syncthreads();
    int nn = blockIdx.x * 32 + threadIdx.y;
    int kk = blockIdx.y * 32 + threadIdx.x;
    float v = t[threadIdx.x][threadIdx.y];
    __nv_bfloat16 h = __float2bfloat16(v);
    __nv_bfloat16 l = __float2bfloat16(v - __bfloat162float(h));
    size_t ro = (size_t)nn * (size_t)(3 * K);
    O[ro + kk]         = h;
    O[ro + K + kk]     = h;
    O[ro + 2 * K + kk] = l;
}

__global__ void vt_split(
    const float* __restrict__ V, __nv_bfloat16* __restrict__ VT3)
{
    __shared__ float t[32][33];
    const int b = blockIdx.z;
    int k = blockIdx.x * 32 + threadIdx.y;
    int d = blockIdx.y * 32 + threadIdx.x;
    t[threadIdx.y][threadIdx.x] = V[((size_t)(b * TT + k)) * DD + d];
    __syncthreads();
    int dg = blockIdx.y * 32 + threadIdx.y;
    int kg = blockIdx.x * 32 + threadIdx.x;
    float v = t[threadIdx.x][threadIdx.y];
    __nv_bfloat16 h = __float2bfloat16(v);
    __nv_bfloat16 l = __float2bfloat16(v - __bfloat162float(h));
    int hh = dg >> 6, dk = dg & 63;
    size_t row = ((size_t)(b * HH + hh) * 64 + dk) * 3072;
    VT3[row + kg]        = h;
    VT3[row + 1024 + kg] = h;
    VT3[row + 2048 + kg] = l;
}

// ===================== HMMA GEMM, cp.async pipelined =====================
#define PADK 40
#define STAGES 4
#define SSTRIDE (2 * 128 * PADK * 2)
#define GEMM_SMEM (STAGES * SSTRIDE)

__global__ __launch_bounds__(256) void gemm_mma(
    const __nv_bfloat16* __restrict__ A3, const __nv_bfloat16* __restrict__ WT3,
    const float* __restrict__ bias, float* __restrict__ C,
    __nv_bfloat16* __restrict__ O3, int N, int K3, int relu)
{
    extern __shared__ char dsm[];
    const uint32_t sb = smem_u32(dsm);
    const int tid = threadIdx.x;
    const int lane = tid & 31, wid = tid >> 5;
    const int wm = wid >> 2, wn = wid & 3;
    const int grp = lane >> 2, tg = lane & 3;

    const size_t arow0 = (size_t)blockIdx.y * 128;
    const size_t bcol0 = (size_t)blockIdx.x * 128;

    const int r0 = tid >> 2, s0c = (tid & 3) * 8;
    const int r1 = r0 + 64;
    const __nv_bfloat16* gA0 = A3  + (arow0 + r0) * (size_t)K3 + s0c;
    const __nv_bfloat16* gA1 = A3  + (arow0 + r1) * (size_t)K3 + s0c;
    const __nv_bfloat16* gB0 = WT3 + (bcol0 + r0) * (size_t)K3 + s0c;
    const __nv_bfloat16* gB1 = WT3 + (bcol0 + r1) * (size_t)K3 + s0c;
    const uint32_t so0 = (uint32_t)(r0 * PADK + s0c) * 2;
    const uint32_t so1 = (uint32_t)(r1 * PADK + s0c) * 2;

    const uint32_t aLM = (uint32_t)(((wm * 64) + (lane & 15)) * PADK + (lane >> 4) * 8) * 2;
    const uint32_t bLM = (uint32_t)(((wn * 32) + (lane & 15)) * PADK + (lane >> 4) * 8) * 2;

    float acc[4][4][4];
    #pragma unroll
    for (int i = 0; i < 4; i++)
        #pragma unroll
        for (int j = 0; j < 4; j++)
            #pragma unroll
            for (int q = 0; q < 4; q++) acc[i][j][q] = 0.f;

    const int NC = K3 >> 5;

    auto issue = [&](int c, int s) {
        uint32_t ab = sb + s * SSTRIDE;
        uint32_t bb = ab + 128 * PADK * 2;
        size_t off = (size_t)c * 32;
        cp16(ab + so0, gA0 + off);
        cp16(ab + so1, gA1 + off);
        cp16(bb + so0, gB0 + off);
        cp16(bb + so1, gB1 + off);
        CP_COMMIT();
    };

    issue(0, 0); issue(1, 1); issue(2, 2);

    for (int c = 0; c < NC; c++) {
        CP_WAIT2();
        __syncthreads();
        const int nxt = c + 3;
        if (nxt < NC) issue(nxt, nxt & 3); else CP_COMMIT();

        const uint32_t As0 = sb + (c & 3) * SSTRIDE;
        const uint32_t Bs0 = As0 + 128 * PADK * 2;
        #pragma unroll
        for (int ks = 0; ks < 2; ks++) {
            const uint32_t ko = ks * 32;
            uint32_t a[4][4], b[4][2];
            #pragma unroll
            for (int ms = 0; ms < 4; ms++)
                ldm4(a[ms][0], a[ms][1], a[ms][2], a[ms][3],
                     As0 + aLM + ms * (16 * PADK * 2) + ko);
            ldm4(b[0][0], b[1][0], b[0][1], b[1][1], Bs0 + bLM + ko);
            ldm4(b[2][0], b[3][0], b[2][1], b[3][1], Bs0 + bLM + 16 * PADK * 2 + ko);
            #pragma unroll
            for (int ms = 0; ms < 4; ms++)
                #pragma unroll
                for (int ns = 0; ns < 4; ns++)
                    mma_bf16(acc[ms][ns], a[ms], b[ns]);
        }
    }

    if (O3) {
        const size_t rstride = (size_t)3 * N;
        #pragma unroll
        for (int ms = 0; ms < 4; ms++) {
            const size_t rr0 = arow0 + wm * 64 + ms * 16 + grp;
            #pragma unroll
            for (int ns = 0; ns < 4; ns++) {
                const size_t cc = bcol0 + wn * 32 + ns * 8 + tg * 2;
                float bx = bias[cc], by = bias[cc + 1];
                float v0 = fmaxf(acc[ms][ns][0] + bx, 0.f);
                float v1 = fmaxf(acc[ms][ns][1] + by, 0.f);
                float v2 = fmaxf(acc[ms][ns][2] + bx, 0.f);
                float v3 = fmaxf(acc[ms][ns][3] + by, 0.f);
                __nv_bfloat16* R0 = O3 + rr0 * rstride;
                __nv_bfloat16* R1 = O3 + (rr0 + 8) * rstride;
                *(uint32_t*)(R0 + cc)         = pack_hi2(v0, v1);
                *(uint32_t*)(R0 + N + cc)     = pack_lo2(v0, v1);
                *(uint32_t*)(R0 + 2 * N + cc) = pack_hi2(v0, v1);
                *(uint32_t*)(R1 + cc)         = pack_hi2(v2, v3);
                *(uint32_t*)(R1 + N + cc)     = pack_lo2(v2, v3);
                *(uint32_t*)(R1 + 2 * N + cc) = pack_hi2(v2, v3);
            }
        }
    } else {
        #pragma unroll
        for (int ms = 0; ms < 4; ms++) {
            const size_t rr0 = arow0 + wm * 64 + ms * 16 + grp;
            #pragma unroll
            for (int ns = 0; ns < 4; ns++) {
                const size_t cc = bcol0 + wn * 32 + ns * 8 + tg * 2;
                float bx = bias[cc], by = bias[cc + 1];
                float v0 = acc[ms][ns][0] + bx;
                float v1 = acc[ms][ns][1] + by;
                float v2 = acc[ms][ns][2] + bx;
                float v3 = acc[ms][ns][3] + by;
                if (relu) {
                    v0 = fmaxf(v0, 0.f); v1 = fmaxf(v1, 0.f);
                    v2 = fmaxf(v2, 0.f); v3 = fmaxf(v3, 0.f);
                }
                *(float2*)(C + rr0 * N + cc)       = make_float2(v0, v1);
                *(float2*)(C + (rr0 + 8) * N + cc) = make_float2(v2, v3);
            }
        }
    }
}

// ===================== attention scores (HMMA, in-smem split, Q-reuse) ======
// Each CTA: 128 q rows x 4 consecutive 64-k tiles (Q loaded/converted once).
#define SPADK 200
#define SCORES_SMEM ((128 + 64) * SPADK * 2)
__global__ __launch_bounds__(256) void attn_scores_mma(
    const float* __restrict__ Q, const float* __restrict__ Kv,
    float* __restrict__ Sc, int causal)
{
    extern __shared__ __nv_bfloat16 sm[];
    __nv_bfloat16* As = sm;                 // [128][SPADK]  Q: [hi|lo|hi]
    __nv_bfloat16* Bs = sm + 128 * SPADK;   // [64][SPADK]   K: [hi|hi|lo]
    const int z = blockIdx.z, b = z >> 4, h = z & 15;
    const int q0 = blockIdx.y * 128;
    const int kbase = blockIdx.x * 256;
    if (causal && kbase >= q0 + 128) return;

    const int tid = threadIdx.x, lane = tid & 31, wid = tid >> 5;
    const int wm = wid >> 1, wn = wid & 1;
    const int grp = lane >> 2, tg = lane & 3;

    const float* Qb = Q + ((size_t)(b * TT + q0)) * DD + h * DKD;

    // load + split Q once
    #pragma unroll
    for (int i = 0; i < 8; i++) {
        int f = tid + i * 256;
        int r = f >> 4, c = (f & 15) << 2;
        float4 v = *(const float4*)(Qb + (size_t)r * DD + c);
        uint2 hh, ll;
        hh.x = pack_hi2(v.x, v.y); hh.y = pack_hi2(v.z, v.w);
        ll.x = pack_lo2(v.x, v.y); ll.y = pack_lo2(v.z, v.w);
        __nv_bfloat16* R = As + r * SPADK;
        *(uint2*)(R + c)       = hh;
        *(uint2*)(R + 64 + c)  = ll;
        *(uint2*)(R + 128 + c) = hh;
    }

    const uint32_t AsU = smem_u32(As), BsU = smem_u32(Bs);
    const uint32_t aLM = AsU + (uint32_t)(((wm * 32) + (lane & 15)) * SPADK + (lane >> 4) * 8) * 2;
    const uint32_t bLM = BsU + (uint32_t)(((wn * 32) + (lane & 15)) * SPADK + (lane >> 4) * 8) * 2;

    for (int kt = 0; kt < 4; kt++) {
        const int k0 = kbase + kt * 64;
        if (causal && k0 >= q0 + 128) break;

        __syncthreads();
        const float* Kb = Kv + ((size_t)(b * TT + k0)) * DD + h * DKD;
        #pragma unroll
        for (int i = 0; i < 4; i++) {
            int f = tid + i * 256;
            int r = f >> 4, c = (f & 15) << 2;
            float4 v = *(const float4*)(Kb + (size_t)r * DD + c);
            uint2 hh, ll;
            hh.x = pack_hi2(v.x, v.y); hh.y = pack_hi2(v.z, v.w);
            ll.x = pack_lo2(v.x, v.y); ll.y = pack_lo2(v.z, v.w);
            __nv_bfloat16* R = Bs + r * SPADK;
            *(uint2*)(R + c)       = hh;
            *(uint2*)(R + 64 + c)  = hh;
            *(uint2*)(R + 128 + c) = ll;
        }
        __syncthreads();

        float acc[2][4][4];
        #pragma unroll
        for (int i = 0; i < 2; i++)
            #pragma unroll
            for (int j = 0; j < 4; j++)
                #pragma unroll
                for (int q = 0; q < 4; q++) acc[i][j][q] = 0.f;

        #pragma unroll
        for (int ks = 0; ks < 12; ks++) {
            const uint32_t ko = ks * 32;
            uint32_t a[2][4], bfr[4][2];
            #pragma unroll
            for (int mi = 0; mi < 2; mi++)
                ldm4(a[mi][0], a[mi][1], a[mi][2], a[mi][3],
                     aLM + mi * (16 * SPADK * 2) + ko);
            ldm4(bfr[0][0], bfr[1][0], bfr[0][1], bfr[1][1], bLM + ko);
            ldm4(bfr[2][0], bfr[3][0], bfr[2][1], bfr[3][1], bLM + 16 * SPADK * 2 + ko);
            #pragma unroll
            for (int mi = 0; mi < 2; mi++)
                #pragma unroll
                for (int ni = 0; ni < 4; ni++)
                    mma_bf16(acc[mi][ni], a[mi], bfr[ni]);
        }

        float* Out = Sc + ((size_t)z * TT + q0) * TT + k0;
        #pragma unroll
        for (int mi = 0; mi < 2; mi++) {
            const size_t r = wm * 32 + mi * 16 + grp;
            #pragma unroll
            for (int ni = 0; ni < 4; ni++) {
                const size_t c = wn * 32 + ni * 8 + tg * 2;
                *(float2*)(Out + r * TT + c) =
                    make_float2(acc[mi][ni][0] * 0.125f, acc[mi][ni][1] * 0.125f);
                *(float2*)(Out + (r + 8) * TT + c) =
                    make_float2(acc[mi][ni][2] * 0.125f, acc[mi][ni][3] * 0.125f);
            }
        }
    }
}

// ===================== attn @ V (HMMA + pre-transposed V) =====================
#define AV_SMEM ((64 + 64) * SPADK * 2)
__global__ __launch_bounds__(256) void attn_av_mma(
    const float* __restrict__ P, const __nv_bfloat16* __restrict__ VT3,
    __nv_bfloat16* __restrict__ A3out, int causal)
{
    extern __shared__ __nv_bfloat16 sm[];
    __nv_bfloat16* As = sm;                // [64][SPADK]  P: [hi|lo|hi]
    __nv_bfloat16* Bs = sm + 64 * SPADK;   // [64][SPADK]  V^T: [hi|hi|lo]
    const int z = blockIdx.y, b = z >> 4, h = z & 15;
    const int q0 = blockIdx.x * 64;

    const int tid = threadIdx.x, lane = tid & 31, wid = tid >> 5;
    const int wm = wid >> 1, wn = wid & 1;
    const int grp = lane >> 2, tg = lane & 3;

    const __nv_bfloat16* Vt = VT3 + (size_t)z * 64 * 3072;

    const uint32_t AsU = smem_u32(As), BsU = smem_u32(Bs);
    const uint32_t aLM = AsU + (uint32_t)(((wm * 16) + (lane & 15)) * SPADK + (lane >> 4) * 8) * 2;
    const uint32_t bLM = BsU + (uint32_t)(((wn * 32) + (lane & 15)) * SPADK + (lane >> 4) * 8) * 2;

    float acc[4][4];
    #pragma unroll
    for (int i = 0; i < 4; i++)
        #pragma unroll
        for (int j = 0; j < 4; j++) acc[i][j] = 0.f;

    const int kend = causal ? (q0 + 64) : TT;
    for (int k0 = 0; k0 < kend; k0 += 64) {
        const float* Pb = P + ((size_t)z * TT + q0) * TT + k0;
        #pragma unroll
        for (int i = 0; i < 4; i++) {
            int f = tid + i * 256;
            int r = f >> 4, c = (f & 15) << 2;
            float4 pv = *(const float4*)(Pb + (size_t)r * TT + c);
            uint2 hh, ll;
            hh.x = pack_hi2(pv.x, pv.y); hh.y = pack_hi2(pv.z, pv.w);
            ll.x = pack_lo2(pv.x, pv.y); ll.y = pack_lo2(pv.z, pv.w);
            __nv_bfloat16* R = As + r * SPADK;
            *(uint2*)(R + c)       = hh;
            *(uint2*)(R + 64 + c)  = ll;
            *(uint2*)(R + 128 + c) = hh;
        }
        #pragma unroll
        for (int i = 0; i < 6; i++) {
            int idx = tid + i * 256;
            int d = idx / 24, rem = idx - d * 24;
            int band = rem >> 3, j = rem & 7;
            uint4 v = *(const uint4*)(Vt + (size_t)d * 3072 + band * 1024 + k0 + j * 8);
            *(uint4*)(Bs + d * SPADK + band * 64 + j * 8) = v;
        }
        __syncthreads();
        #pragma unroll
        for (int ks = 0; ks < 12; ks++) {
            const uint32_t ko = ks * 32;
            uint32_t a[4], bfr[4][2];
            ldm4(a[0], a[1], a[2], a[3], aLM + ko);
            ldm4(bfr[0][0], bfr[1][0], bfr[0][1], bfr[1][1], bLM + ko);
            ldm4(bfr[2][0], bfr[3][0], bfr[2][1], bfr[3][1], bLM + 16 * SPADK * 2 + ko);
            #pragma unroll
            for (int ni = 0; ni < 4; ni++)
                mma_bf16(acc[ni], a, bfr[ni]);
        }
        __syncthreads();
    }

    const size_t m0 = (size_t)b * TT + q0 + wm * 16 + grp;
    const size_t m1 = m0 + 8;
    __nv_bfloat16* R0 = A3out + m0 * 3072;
    __nv_bfloat16* R1 = A3out + m1 * 3072;
    #pragma unroll
    for (int ni = 0; ni < 4; ni++) {
        const int cc = h * DKD + wn * 32 + ni * 8 + tg * 2;
        float v0 = acc[ni][0], v1 = acc[ni][1];
        float v2 = acc[ni][2], v3 = acc[ni][3];
        *(uint32_t*)(R0 + cc)        = pack_hi2(v0, v1);
        *(uint32_t*)(R0 + 1024 + cc) = pack_lo2(v0, v1);
        *(uint32_t*)(R0 + 2048 + cc) = pack_hi2(v0, v1);
        *(uint32_t*)(R1 + cc)        = pack_hi2(v2, v3);
        *(uint32_t*)(R1 + 1024 + cc) = pack_lo2(v2, v3);
        *(uint32_t*)(R1 + 2048 + cc) = pack_hi2(v2, v3);
    }
}

// ===================== softmax =====================
__global__ __launch_bounds__(256) void softmax_mask(
    float* __restrict__ Sc, const int* __restrict__ mask, int mode)
{
    const int q = blockIdx.x, z = blockIdx.y;
    const int b = z >> 4;
    float* row = Sc + ((size_t)z * TT + q) * TT;
    const int tid = threadIdx.x;

    float v[4];
    float mx = -3.0e38f;
    if (mode == 0) {
        const int L = q + 1;
        #pragma unroll
        for (int i = 0; i < 4; i++) {
            int k = tid + i * 256;
            if (k < L) { v[i] = row[k]; mx = fmaxf(mx, v[i]); }
            else v[i] = -1e30f;
        }
    } else {
        #pragma unroll
        for (int i = 0; i < 4; i++) {
            int k = tid + i * 256;
            float s = row[k];
            int mv = mask[b * SS + k];
            v[i] = (mv == 0) ? -1e9f : s;
            mx = fmaxf(mx, v[i]);
        }
    }

    __shared__ float red[8];
    __shared__ float red2[8];
    #pragma unroll
    for (int o = 16; o > 0; o >>= 1) mx = fmaxf(mx, __shfl_xor_sync(0xffffffffu, mx, o));
    if ((tid & 31) == 0) red[tid >> 5] = mx;
    __syncthreads();
    mx = red[0];
    #pragma unroll
    for (int w = 1; w < 8; w++) mx = fmaxf(mx, red[w]);

    float sum = 0.f;
    if (mode == 0) {
        const int L = q + 1;
        #pragma unroll
        for (int i = 0; i < 4; i++) {
            int k = tid + i * 256;
            v[i] = (k < L) ? __expf(v[i] - mx) : 0.f;
            sum += v[i];
        }
    } else {
        #pragma unroll
        for (int i = 0; i < 4; i++) { v[i] = __expf(v[i] - mx); sum += v[i]; }
    }
    #pragma unroll
    for (int o = 16; o > 0; o >>= 1) sum += __shfl_xor_sync(0xffffffffu, sum, o);
    if ((tid & 31) == 0) red2[tid >> 5] = sum;
    __syncthreads();
    sum = 0.f;
    #pragma unroll
    for (int w = 0; w < 8; w++) sum += red2[w];
    float inv = 1.0f / sum;
    #pragma unroll
    for (int i = 0; i < 4; i++) row[tid + i * 256] = v[i] * inv;
}

// ===================== residual add + LayerNorm =====================
__global__ __launch_bounds__(256) void add_ln(
    const float* __restrict__ X, const float* __restrict__ Dl,
    const float* __restrict__ g, const float* __restrict__ be,
    float* __restrict__ O, __nv_bfloat16* __restrict__ S3)
{
    const int row = blockIdx.x;
    const float* x  = X  + (size_t)row * DD;
    const float* dl = Dl + (size_t)row * DD;
    const int tid = threadIdx.x;

    float v[4];
    float s = 0.f;
    #pragma unroll
    for (int i = 0; i < 4; i++) {
        int c = tid + i * 256;
        v[i] = x[c] + dl[c];
        s += v[i];
    }
    __shared__ float red[8];
    #pragma unroll
    for (int o = 16; o > 0; o >>= 1) s += __shfl_xor_sync(0xffffffffu, s, o);
    if ((tid & 31) == 0) red[tid >> 5] = s;
    __syncthreads();
    s = 0.f;
    #pragma unroll
    for (int w = 0; w < 8; w++) s += red[w];
    float mean = s * (1.0f / 1024.0f);

    float qq = 0.f;
    #pragma unroll
    for (int i = 0; i < 4; i++) { float d = v[i] - mean; qq += d * d; }
    __syncthreads();
    #pragma unroll
    for (int o = 16; o > 0; o >>= 1) qq += __shfl_xor_sync(0xffffffffu, qq, o);
    if ((tid & 31) == 0) red[tid >> 5] = qq;
    __syncthreads();
    qq = 0.f;
    #pragma unroll
    for (int w = 0; w < 8; w++) qq += red[w];

    float stdv = sqrtf(qq * (1.0f / 1023.0f));
    float inv = 1.0f / (stdv + LN_EPS);
    __nv_bfloat16* R = S3 ? (S3 + (size_t)row * 3072) : (__nv_bfloat16*)0;
    #pragma unroll
    for (int i = 0; i < 4; i++) {
        int c = tid + i * 256;
        float o = g[c] * (v[i] - mean) * inv + be[c];
        O[(size_t)row * DD + c] = o;
        if (R) {
            __nv_bfloat16 h = __float2bfloat16(o);
            __nv_bfloat16 l = __float2bfloat16(o - __bfloat162float(h));
            R[c]        = h;
            R[1024 + c] = l;
            R[2048 + c] = h;
        }
    }
}

// ===================== orchestration =====================
extern "C" void kernel_launch(void* const* d_in, const int* in_sizes, int n_in,
                              void* d_out, int out_size)
{
    const float* x        = (const float*)d_in[0];
    const float* enc      = (const float*)d_in[1];
    const int*   src_mask = (const int*)  d_in[2];
    const float* wq_s = (const float*)d_in[4],  *bq_s = (const float*)d_in[5];
    const float* wk_s = (const float*)d_in[6],  *bk_s = (const float*)d_in[7];
    const float* wv_s = (const float*)d_in[8],  *bv_s = (const float*)d_in[9];
    const float* wo_s = (const float*)d_in[10], *bo_s = (const float*)d_in[11];
    const float* wq_c = (const float*)d_in[12], *bq_c = (const float*)d_in[13];
    const float* wk_c = (const float*)d_in[14], *bk_c = (const float*)d_in[15];
    const float* wv_c = (const float*)d_in[16], *bv_c = (const float*)d_in[17];
    const float* wo_c = (const float*)d_in[18], *bo_c = (const float*)d_in[19];
    const float* w1   = (const float*)d_in[20], *b1   = (const float*)d_in[21];
    const float* w2   = (const float*)d_in[22], *b2   = (const float*)d_in[23];
    const float* g1   = (const float*)d_in[24], *be1  = (const float*)d_in[25];
    const float* g2   = (const float*)d_in[26], *be2  = (const float*)d_in[27];
    const float* g3   = (const float*)d_in[28], *be3  = (const float*)d_in[29];

    float* out     = (float*)d_out;
    float* self_w  = out + (size_t)BB * TT * DD;
    float* cross_w = self_w + (size_t)BB * HH * TT * TT;

    float *Q, *K, *V, *T1, *X1, *X2;
    __nv_bfloat16 *A3, *FF3, *WT3, *VT3;
    cudaGetSymbolAddress((void**)&Q,   g_q);
    cudaGetSymbolAddress((void**)&K,   g_k);
    cudaGetSymbolAddress((void**)&V,   g_v);
    cudaGetSymbolAddress((void**)&T1,  g_t1);
    cudaGetSymbolAddress((void**)&X1,  g_x1);
    cudaGetSymbolAddress((void**)&X2,  g_x2);
    cudaGetSymbolAddress((void**)&A3,  g_a3);
    cudaGetSymbolAddress((void**)&FF3, g_ff3);
    cudaGetSymbolAddress((void**)&WT3, g_wt3);
    cudaGetSymbolAddress((void**)&VT3, g_vt3);

    cudaFuncSetAttribute(gemm_mma,        cudaFuncAttributeMaxDynamicSharedMemorySize, GEMM_SMEM);
    cudaFuncSetAttribute(attn_scores_mma, cudaFuncAttributeMaxDynamicSharedMemorySize, SCORES_SMEM);
    cudaFuncSetAttribute(attn_av_mma,     cudaFuncAttributeMaxDynamicSharedMemorySize, AV_SMEM);

    const int M = BB * TT;
    dim3 blk(256);
    dim3 tp32(32, 32);
    dim3 gD(DD / 128, M / 128);
    dim3 gF(DFFN / 128, M / 128);
    dim3 scoreG(TT / 256, TT / 128, BB * HH);
    dim3 smaxG(TT, BB * HH);
    dim3 avG(TT / 64, BB * HH);
    dim3 vtG(TT / 32, DD / 32, BB);
    dim3 lnG(M);
    const int ACT_BLKS = M * DD / 4 / 256;
    float* NC = (float*)0;
    __nv_bfloat16* NO3 = (__nv_bfloat16*)0;

    // ---- self-attn weights + first GEMMs (launch #6 = gemm_mma for ncu) ----
    split_act<<<ACT_BLKS, blk>>>(x, A3);                                   // 1
    split_w<<<dim3(32, 32), tp32>>>(wq_s, WT3 + 0 * W3D, DD, DD);          // 2
    split_w<<<dim3(32, 32), tp32>>>(wk_s, WT3 + 1 * W3D, DD, DD);          // 3
    split_w<<<dim3(32, 32), tp32>>>(wv_s, WT3 + 2 * W3D, DD, DD);          // 4
    split_w<<<dim3(32, 32), tp32>>>(wo_s, WT3 + 3 * W3D, DD, DD);          // 5
    gemm_mma<<<gD, blk, GEMM_SMEM>>>(A3, WT3 + 0 * W3D, bq_s, Q, NO3, DD, 3072, 0);  // 6 <- ncu
    gemm_mma<<<gD, blk, GEMM_SMEM>>>(A3, WT3 + 1 * W3D, bk_s, K, NO3, DD, 3072, 0);
    gemm_mma<<<gD, blk, GEMM_SMEM>>>(A3, WT3 + 2 * W3D, bv_s, V, NO3, DD, 3072, 0);
    vt_split<<<vtG, tp32>>>(V, VT3);
    attn_scores_mma<<<scoreG, blk, SCORES_SMEM>>>(Q, K, self_w, 1);
    softmax_mask<<<smaxG, blk>>>(self_w, src_mask, 0);
    attn_av_mma<<<avG, blk, AV_SMEM>>>(self_w, VT3, A3, 1);
    gemm_mma<<<gD, blk, GEMM_SMEM>>>(A3, WT3 + 3 * W3D, bo_s, T1, NO3, DD, 3072, 0);
    add_ln<<<lnG, blk>>>(x, T1, g1, be1, X1, A3);

    // ---- remaining weight splits ----
    split_w<<<dim3(32, 32), tp32>>>(wq_c, WT3 + 4 * W3D, DD, DD);
    split_w<<<dim3(32, 32), tp32>>>(wk_c, WT3 + 5 * W3D, DD, DD);
    split_w<<<dim3(32, 32), tp32>>>(wv_c, WT3 + 6 * W3D, DD, DD);
    split_w<<<dim3(32, 32), tp32>>>(wo_c, WT3 + 7 * W3D, DD, DD);
    split_w<<<dim3(128, 32), tp32>>>(w1, WT3 + W1OFF, DD, DFFN);
    split_w<<<dim3(32, 128), tp32>>>(w2, WT3 + W2OFF, DFFN, DD);

    // ---- cross attention ----
    gemm_mma<<<gD, blk, GEMM_SMEM>>>(A3, WT3 + 4 * W3D, bq_c, Q, NO3, DD, 3072, 0);
    split_act<<<ACT_BLKS, blk>>>(enc, A3);
    gemm_mma<<<gD, blk, GEMM_SMEM>>>(A3, WT3 + 5 * W3D, bk_c, K, NO3, DD, 3072, 0);
    gemm_mma<<<gD, blk, GEMM_SMEM>>>(A3, WT3 + 6 * W3D, bv_c, V, NO3, DD, 3072, 0);
    vt_split<<<vtG, tp32>>>(V, VT3);
    attn_scores_mma<<<scoreG, blk, SCORES_SMEM>>>(Q, K, cross_w, 0);
    softmax_mask<<<smaxG, blk>>>(cross_w, src_mask, 1);
    attn_av_mma<<<avG, blk, AV_SMEM>>>(cross_w, VT3, A3, 0);
    gemm_mma<<<gD, blk, GEMM_SMEM>>>(A3, WT3 + 7 * W3D, bo_c, T1, NO3, DD, 3072, 0);
    add_ln<<<lnG, blk>>>(X1, T1, g2, be2, X2, A3);

    // ---- feed-forward ----
    gemm_mma<<<gF, blk, GEMM_SMEM>>>(A3, WT3 + W1OFF, b1, NC, FF3, DFFN, 3072, 1);
    gemm_mma<<<gD, blk, GEMM_SMEM>>>(FF3, WT3 + W2OFF, b2, T1, NO3, DD, 12288, 0);
    add_ln<<<lnG, blk>>>(X2, T1, g3, be3, out, NO3);

    (void)in_sizes; (void)n_in; (void)out_size;
}

// round 9
// speedup vs baseline: 1.1035x; 1.0144x over previous
#include <cuda_runtime.h>
#include <cuda_bf16.h>
#include <math.h>
#include <stdint.h>

#define BB 4
#define TT 1024
#define SS 1024
#define DD 1024
#define HH 16
#define DKD 64
#define DFFN 4096
#define LN_EPS 1e-6f

// ===================== scratch (no allocations) =====================
__device__ float g_q [BB*TT*DD];
__device__ float g_k [BB*TT*DD];
__device__ float g_v [BB*TT*DD];
__device__ float g_t1[BB*TT*DD];
__device__ float g_x1[BB*TT*DD];
__device__ float g_x2[BB*TT*DD];

__device__ __nv_bfloat16 g_a3 [4096ULL * 3072];   // activations [M,3K] (hi|lo|hi)
__device__ __nv_bfloat16 g_ff3[4096ULL * 12288];  // FF activations
__device__ __nv_bfloat16 g_vt3[4096ULL * 3072];   // V^T split per (b,h): [64 d][hi|hi|lo seq]
#define W3D (1024ULL*3072)
#define W1OFF (8*W3D)
#define W2OFF (8*W3D + 4096ULL*3072)
__device__ __nv_bfloat16 g_wt3[8*W3D + 4096ULL*3072 + 1024ULL*12288];

// ===================== helpers =====================
__device__ __forceinline__ uint32_t pack_hi2(float x, float y) {
    __nv_bfloat16 a = __float2bfloat16(x), b = __float2bfloat16(y);
    return (uint32_t)__bfloat16_as_ushort(a) | ((uint32_t)__bfloat16_as_ushort(b) << 16);
}
__device__ __forceinline__ uint32_t pack_lo2(float x, float y) {
    __nv_bfloat16 a = __float2bfloat16(x), b = __float2bfloat16(y);
    __nv_bfloat16 ra = __float2bfloat16(x - __bfloat162float(a));
    __nv_bfloat16 rb = __float2bfloat16(y - __bfloat162float(b));
    return (uint32_t)__bfloat16_as_ushort(ra) | ((uint32_t)__bfloat16_as_ushort(rb) << 16);
}
__device__ __forceinline__ void mma_bf16(
    float* d, const uint32_t* a, const uint32_t* b)
{
    asm volatile(
        "mma.sync.aligned.m16n8k16.row.col.f32.bf16.bf16.f32 "
        "{%0,%1,%2,%3}, {%4,%5,%6,%7}, {%8,%9}, {%0,%1,%2,%3};"
        : "+f"(d[0]), "+f"(d[1]), "+f"(d[2]), "+f"(d[3])
        : "r"(a[0]), "r"(a[1]), "r"(a[2]), "r"(a[3]), "r"(b[0]), "r"(b[1]));
}
__device__ __forceinline__ uint32_t smem_u32(const void* p) {
    uint32_t a;
    asm("{ .reg .u64 t; cvta.to.shared.u64 t, %1; cvt.u32.u64 %0, t; }" : "=r"(a) : "l"(p));
    return a;
}
__device__ __forceinline__ void cp16(uint32_t s, const void* g) {
    asm volatile("cp.async.cg.shared.global [%0], [%1], 16;" :: "r"(s), "l"(g));
}
#define CP_COMMIT() asm volatile("cp.async.commit_group;" ::: "memory")
#define CP_WAIT2()  asm volatile("cp.async.wait_group 2;" ::: "memory")
__device__ __forceinline__ void ldm4(uint32_t& r0, uint32_t& r1, uint32_t& r2, uint32_t& r3, uint32_t a) {
    asm volatile("ldmatrix.sync.aligned.m8n8.x4.shared.b16 {%0,%1,%2,%3}, [%4];"
        : "=r"(r0), "=r"(r1), "=r"(r2), "=r"(r3) : "r"(a));
}

// ===================== split/convert kernels =====================
__global__ __launch_bounds__(256) void split_act(
    const float* __restrict__ A, __nv_bfloat16* __restrict__ O)
{
    const int K = 1024;
    size_t idx = (size_t)blockIdx.x * 256 + threadIdx.x;
    size_t base = idx << 2;
    size_t m = base >> 10;
    int k = (int)(base & (size_t)(K - 1));
    float4 v = *(const float4*)(A + base);
    uint2 hh, ll;
    hh.x = pack_hi2(v.x, v.y); hh.y = pack_hi2(v.z, v.w);
    ll.x = pack_lo2(v.x, v.y); ll.y = pack_lo2(v.z, v.w);
    __nv_bfloat16* row = O + m * (size_t)(3 * K);
    *(uint2*)(row + k)         = hh;
    *(uint2*)(row + K + k)     = ll;
    *(uint2*)(row + 2 * K + k) = hh;
}

__global__ void split_w(
    const float* __restrict__ W, __nv_bfloat16* __restrict__ O, int K, int N)
{
    __shared__ float t[32][33];
    int k = blockIdx.y * 32 + threadIdx.y;
    int n = blockIdx.x * 32 + threadIdx.x;
    t[threadIdx.y][threadIdx.x] = W[(size_t)k * N + n];
    __syncthreads();
    int nn = blockIdx.x * 32 + threadIdx.y;
    int kk = blockIdx.y * 32 + threadIdx.x;
    float v = t[threadIdx.x][threadIdx.y];
    __nv_bfloat16 h = __float2bfloat16(v);
    __nv_bfloat16 l = __float2bfloat16(v - __bfloat162float(h));
    size_t ro = (size_t)nn * (size_t)(3 * K);
    O[ro + kk]         = h;
    O[ro + K + kk]     = h;
    O[ro + 2 * K + kk] = l;
}

__global__ void vt_split(
    const float* __restrict__ V, __nv_bfloat16* __restrict__ VT3)
{
    __shared__ float t[32][33];
    const int b = blockIdx.z;
    int k = blockIdx.x * 32 + threadIdx.y;
    int d = blockIdx.y * 32 + threadIdx.x;
    t[threadIdx.y][threadIdx.x] = V[((size_t)(b * TT + k)) * DD + d];
    __syncthreads();
    int dg = blockIdx.y * 32 + threadIdx.y;
    int kg = blockIdx.x * 32 + threadIdx.x;
    float v = t[threadIdx.x][threadIdx.y];
    __nv_bfloat16 h = __float2bfloat16(v);
    __nv_bfloat16 l = __float2bfloat16(v - __bfloat162float(h));
    int hh = dg >> 6, dk = dg & 63;
    size_t row = ((size_t)(b * HH + hh) * 64 + dk) * 3072;
    VT3[row + kg]        = h;
    VT3[row + 1024 + kg] = h;
    VT3[row + 2048 + kg] = l;
}

// ===================== HMMA GEMM, cp.async pipelined =====================
#define PADK 40
#define STAGES 4
#define SSTRIDE (2 * 128 * PADK * 2)
#define GEMM_SMEM (STAGES * SSTRIDE)

__global__ __launch_bounds__(256) void gemm_mma(
    const __nv_bfloat16* __restrict__ A3, const __nv_bfloat16* __restrict__ WT3,
    const float* __restrict__ bias, float* __restrict__ C,
    __nv_bfloat16* __restrict__ O3, int N, int K3, int relu)
{
    extern __shared__ char dsm[];
    const uint32_t sb = smem_u32(dsm);
    const int tid = threadIdx.x;
    const int lane = tid & 31, wid = tid >> 5;
    const int wm = wid >> 2, wn = wid & 3;
    const int grp = lane >> 2, tg = lane & 3;

    const size_t arow0 = (size_t)blockIdx.y * 128;
    const size_t bcol0 = (size_t)blockIdx.x * 128;

    const int r0 = tid >> 2, s0c = (tid & 3) * 8;
    const int r1 = r0 + 64;
    const __nv_bfloat16* gA0 = A3  + (arow0 + r0) * (size_t)K3 + s0c;
    const __nv_bfloat16* gA1 = A3  + (arow0 + r1) * (size_t)K3 + s0c;
    const __nv_bfloat16* gB0 = WT3 + (bcol0 + r0) * (size_t)K3 + s0c;
    const __nv_bfloat16* gB1 = WT3 + (bcol0 + r1) * (size_t)K3 + s0c;
    const uint32_t so0 = (uint32_t)(r0 * PADK + s0c) * 2;
    const uint32_t so1 = (uint32_t)(r1 * PADK + s0c) * 2;

    const uint32_t aLM = (uint32_t)(((wm * 64) + (lane & 15)) * PADK + (lane >> 4) * 8) * 2;
    const uint32_t bLM = (uint32_t)(((wn * 32) + (lane & 15)) * PADK + (lane >> 4) * 8) * 2;

    float acc[4][4][4];
    #pragma unroll
    for (int i = 0; i < 4; i++)
        #pragma unroll
        for (int j = 0; j < 4; j++)
            #pragma unroll
            for (int q = 0; q < 4; q++) acc[i][j][q] = 0.f;

    const int NC = K3 >> 5;

    auto issue = [&](int c, int s) {
        uint32_t ab = sb + s * SSTRIDE;
        uint32_t bb = ab + 128 * PADK * 2;
        size_t off = (size_t)c * 32;
        cp16(ab + so0, gA0 + off);
        cp16(ab + so1, gA1 + off);
        cp16(bb + so0, gB0 + off);
        cp16(bb + so1, gB1 + off);
        CP_COMMIT();
    };

    issue(0, 0); issue(1, 1); issue(2, 2);

    for (int c = 0; c < NC; c++) {
        CP_WAIT2();
        __syncthreads();
        const int nxt = c + 3;
        if (nxt < NC) issue(nxt, nxt & 3); else CP_COMMIT();

        const uint32_t As0 = sb + (c & 3) * SSTRIDE;
        const uint32_t Bs0 = As0 + 128 * PADK * 2;
        #pragma unroll
        for (int ks = 0; ks < 2; ks++) {
            const uint32_t ko = ks * 32;
            uint32_t a[4][4], b[4][2];
            #pragma unroll
            for (int ms = 0; ms < 4; ms++)
                ldm4(a[ms][0], a[ms][1], a[ms][2], a[ms][3],
                     As0 + aLM + ms * (16 * PADK * 2) + ko);
            ldm4(b[0][0], b[1][0], b[0][1], b[1][1], Bs0 + bLM + ko);
            ldm4(b[2][0], b[3][0], b[2][1], b[3][1], Bs0 + bLM + 16 * PADK * 2 + ko);
            #pragma unroll
            for (int ms = 0; ms < 4; ms++)
                #pragma unroll
                for (int ns = 0; ns < 4; ns++)
                    mma_bf16(acc[ms][ns], a[ms], b[ns]);
        }
    }

    if (O3) {
        const size_t rstride = (size_t)3 * N;
        #pragma unroll
        for (int ms = 0; ms < 4; ms++) {
            const size_t rr0 = arow0 + wm * 64 + ms * 16 + grp;
            #pragma unroll
            for (int ns = 0; ns < 4; ns++) {
                const size_t cc = bcol0 + wn * 32 + ns * 8 + tg * 2;
                float bx = bias[cc], by = bias[cc + 1];
                float v0 = fmaxf(acc[ms][ns][0] + bx, 0.f);
                float v1 = fmaxf(acc[ms][ns][1] + by, 0.f);
                float v2 = fmaxf(acc[ms][ns][2] + bx, 0.f);
                float v3 = fmaxf(acc[ms][ns][3] + by, 0.f);
                __nv_bfloat16* R0 = O3 + rr0 * rstride;
                __nv_bfloat16* R1 = O3 + (rr0 + 8) * rstride;
                *(uint32_t*)(R0 + cc)         = pack_hi2(v0, v1);
                *(uint32_t*)(R0 + N + cc)     = pack_lo2(v0, v1);
                *(uint32_t*)(R0 + 2 * N + cc) = pack_hi2(v0, v1);
                *(uint32_t*)(R1 + cc)         = pack_hi2(v2, v3);
                *(uint32_t*)(R1 + N + cc)     = pack_lo2(v2, v3);
                *(uint32_t*)(R1 + 2 * N + cc) = pack_hi2(v2, v3);
            }
        }
    } else {
        #pragma unroll
        for (int ms = 0; ms < 4; ms++) {
            const size_t rr0 = arow0 + wm * 64 + ms * 16 + grp;
            #pragma unroll
            for (int ns = 0; ns < 4; ns++) {
                const size_t cc = bcol0 + wn * 32 + ns * 8 + tg * 2;
                float bx = bias[cc], by = bias[cc + 1];
                float v0 = acc[ms][ns][0] + bx;
                float v1 = acc[ms][ns][1] + by;
                float v2 = acc[ms][ns][2] + bx;
                float v3 = acc[ms][ns][3] + by;
                if (relu) {
                    v0 = fmaxf(v0, 0.f); v1 = fmaxf(v1, 0.f);
                    v2 = fmaxf(v2, 0.f); v3 = fmaxf(v3, 0.f);
                }
                *(float2*)(C + rr0 * N + cc)       = make_float2(v0, v1);
                *(float2*)(C + (rr0 + 8) * N + cc) = make_float2(v2, v3);
            }
        }
    }
}

// ===================== attention scores (raw scaled logits) ======
#define SPADK 200
#define SCORES_SMEM ((128 + 64) * SPADK * 2)
__global__ __launch_bounds__(256) void attn_scores_mma(
    const float* __restrict__ Q, const float* __restrict__ Kv,
    float* __restrict__ Sc, int causal)
{
    extern __shared__ __nv_bfloat16 sm[];
    __nv_bfloat16* As = sm;                 // [128][SPADK]  Q: [hi|lo|hi]
    __nv_bfloat16* Bs = sm + 128 * SPADK;   // [64][SPADK]   K: [hi|hi|lo]
    const int z = blockIdx.z, b = z >> 4, h = z & 15;
    const int q0 = blockIdx.y * 128;
    const int kbase = blockIdx.x * 256;
    if (causal && kbase >= q0 + 128) return;

    const int tid = threadIdx.x, lane = tid & 31, wid = tid >> 5;
    const int wm = wid >> 1, wn = wid & 1;
    const int grp = lane >> 2, tg = lane & 3;

    const float* Qb = Q + ((size_t)(b * TT + q0)) * DD + h * DKD;

    #pragma unroll
    for (int i = 0; i < 8; i++) {
        int f = tid + i * 256;
        int r = f >> 4, c = (f & 15) << 2;
        float4 v = *(const float4*)(Qb + (size_t)r * DD + c);
        uint2 hh, ll;
        hh.x = pack_hi2(v.x, v.y); hh.y = pack_hi2(v.z, v.w);
        ll.x = pack_lo2(v.x, v.y); ll.y = pack_lo2(v.z, v.w);
        __nv_bfloat16* R = As + r * SPADK;
        *(uint2*)(R + c)       = hh;
        *(uint2*)(R + 64 + c)  = ll;
        *(uint2*)(R + 128 + c) = hh;
    }

    const uint32_t AsU = smem_u32(As), BsU = smem_u32(Bs);
    const uint32_t aLM = AsU + (uint32_t)(((wm * 32) + (lane & 15)) * SPADK + (lane >> 4) * 8) * 2;
    const uint32_t bLM = BsU + (uint32_t)(((wn * 32) + (lane & 15)) * SPADK + (lane >> 4) * 8) * 2;

    for (int kt = 0; kt < 4; kt++) {
        const int k0 = kbase + kt * 64;
        if (causal && k0 >= q0 + 128) break;

        __syncthreads();
        const float* Kb = Kv + ((size_t)(b * TT + k0)) * DD + h * DKD;
        #pragma unroll
        for (int i = 0; i < 4; i++) {
            int f = tid + i * 256;
            int r = f >> 4, c = (f & 15) << 2;
            float4 v = *(const float4*)(Kb + (size_t)r * DD + c);
            uint2 hh, ll;
            hh.x = pack_hi2(v.x, v.y); hh.y = pack_hi2(v.z, v.w);
            ll.x = pack_lo2(v.x, v.y); ll.y = pack_lo2(v.z, v.w);
            __nv_bfloat16* R = Bs + r * SPADK;
            *(uint2*)(R + c)       = hh;
            *(uint2*)(R + 64 + c)  = hh;
            *(uint2*)(R + 128 + c) = ll;
        }
        __syncthreads();

        float acc[2][4][4];
        #pragma unroll
        for (int i = 0; i < 2; i++)
            #pragma unroll
            for (int j = 0; j < 4; j++)
                #pragma unroll
                for (int q = 0; q < 4; q++) acc[i][j][q] = 0.f;

        #pragma unroll
        for (int ks = 0; ks < 12; ks++) {
            const uint32_t ko = ks * 32;
            uint32_t a[2][4], bfr[4][2];
            #pragma unroll
            for (int mi = 0; mi < 2; mi++)
                ldm4(a[mi][0], a[mi][1], a[mi][2], a[mi][3],
                     aLM + mi * (16 * SPADK * 2) + ko);
            ldm4(bfr[0][0], bfr[1][0], bfr[0][1], bfr[1][1], bLM + ko);
            ldm4(bfr[2][0], bfr[3][0], bfr[2][1], bfr[3][1], bLM + 16 * SPADK * 2 + ko);
            #pragma unroll
            for (int mi = 0; mi < 2; mi++)
                #pragma unroll
                for (int ni = 0; ni < 4; ni++)
                    mma_bf16(acc[mi][ni], a[mi], bfr[ni]);
        }

        float* Out = Sc + ((size_t)z * TT + q0) * TT + k0;
        #pragma unroll
        for (int mi = 0; mi < 2; mi++) {
            const size_t r = wm * 32 + mi * 16 + grp;
            #pragma unroll
            for (int ni = 0; ni < 4; ni++) {
                const size_t c = wn * 32 + ni * 8 + tg * 2;
                *(float2*)(Out + r * TT + c) =
                    make_float2(acc[mi][ni][0] * 0.125f, acc[mi][ni][1] * 0.125f);
                *(float2*)(Out + (r + 8) * TT + c) =
                    make_float2(acc[mi][ni][2] * 0.125f, acc[mi][ni][3] * 0.125f);
            }
        }
    }
}

// ===================== attn @ V with fused softmax =====================
// Pass 1: online row max/sum over raw logits. Pass 2: p=exp(s-m)*inv, write P
// (the required output) once, and feed P into the P@V HMMA.
#define AV_SMEM ((64 + 64) * SPADK * 2 + 512)
__global__ __launch_bounds__(256) void attn_av_mma(
    float* __restrict__ Sc, const __nv_bfloat16* __restrict__ VT3,
    const int* __restrict__ mask, __nv_bfloat16* __restrict__ A3out, int causal)
{
    extern __shared__ __nv_bfloat16 sm[];
    __nv_bfloat16* As = sm;                // [64][SPADK]  P: [hi|lo|hi]
    __nv_bfloat16* Bs = sm + 64 * SPADK;   // [64][SPADK]  V^T: [hi|hi|lo]
    float* stats = (float*)(sm + (64 + 64) * SPADK);  // [0:64) m, [64:128) inv
    const int z = blockIdx.y, b = z >> 4, h = z & 15;
    const int q0 = blockIdx.x * 64;

    const int tid = threadIdx.x, lane = tid & 31, wid = tid >> 5;
    const int wm = wid >> 1, wn = wid & 1;
    const int grp = lane >> 2, tg = lane & 3;

    const int kend = causal ? (q0 + 64) : TT;

    // ---- pass 1: per-row online max / exp-sum ----
    {
        const int rloc = wid * 8 + (lane >> 2);  // 0..63
        const int qd = lane & 3;
        const int qabs = q0 + rloc;
        const float* Srow = Sc + ((size_t)z * TT + qabs) * TT;
        float m = -3.0e38f, s = 0.f;
        for (int j = 0; j < (kend >> 4); j++) {
            int k = qd * 4 + j * 16;
            float4 v4 = *(const float4*)(Srow + k);
            float v0, v1, v2, v3;
            if (causal) {
                v0 = (k     <= qabs) ? v4.x : -1e9f;
                v1 = (k + 1 <= qabs) ? v4.y : -1e9f;
                v2 = (k + 2 <= qabs) ? v4.z : -1e9f;
                v3 = (k + 3 <= qabs) ? v4.w : -1e9f;
            } else {
                int4 mk = *(const int4*)(mask + b * SS + k);
                v0 = mk.x ? v4.x : -1e9f;
                v1 = mk.y ? v4.y : -1e9f;
                v2 = mk.z ? v4.z : -1e9f;
                v3 = mk.w ? v4.w : -1e9f;
            }
            float tm = fmaxf(fmaxf(v0, v1), fmaxf(v2, v3));
            float nm = fmaxf(m, tm);
            s = s * __expf(m - nm)
              + __expf(v0 - nm) + __expf(v1 - nm)
              + __expf(v2 - nm) + __expf(v3 - nm);
            m = nm;
        }
        #pragma unroll
        for (int o = 1; o <= 2; o <<= 1) {
            float mo = __shfl_xor_sync(0xffffffffu, m, o);
            float so = __shfl_xor_sync(0xffffffffu, s, o);
            float nm = fmaxf(m, mo);
            s = s * __expf(m - nm) + so * __expf(mo - nm);
            m = nm;
        }
        if (qd == 0) { stats[rloc] = m; stats[64 + rloc] = 1.0f / s; }
    }
    __syncthreads();

    const __nv_bfloat16* Vt = VT3 + (size_t)z * 64 * 3072;
    const uint32_t AsU = smem_u32(As), BsU = smem_u32(Bs);
    const uint32_t aLM = AsU + (uint32_t)(((wm * 16) + (lane & 15)) * SPADK + (lane >> 4) * 8) * 2;
    const uint32_t bLM = BsU + (uint32_t)(((wn * 32) + (lane & 15)) * SPADK + (lane >> 4) * 8) * 2;

    float acc[4][4];
    #pragma unroll
    for (int i = 0; i < 4; i++)
        #pragma unroll
        for (int j = 0; j < 4; j++) acc[i][j] = 0.f;

    // ---- pass 2: apply softmax, write P, run P@V ----
    for (int k0 = 0; k0 < kend; k0 += 64) {
        float* Pb = Sc + ((size_t)z * TT + q0) * TT + k0;
        #pragma unroll
        for (int i = 0; i < 4; i++) {
            int f = tid + i * 256;
            int r = f >> 4, c = (f & 15) << 2;
            float4 pv = *(float4*)(Pb + (size_t)r * TT + c);
            const int qabs = q0 + r;
            const int kg = k0 + c;
            float v0, v1, v2, v3;
            if (causal) {
                v0 = (kg     <= qabs) ? pv.x : -1e9f;
                v1 = (kg + 1 <= qabs) ? pv.y : -1e9f;
                v2 = (kg + 2 <= qabs) ? pv.z : -1e9f;
                v3 = (kg + 3 <= qabs) ? pv.w : -1e9f;
            } else {
                int4 mk = *(const int4*)(mask + b * SS + kg);
                v0 = mk.x ? pv.x : -1e9f;
                v1 = mk.y ? pv.y : -1e9f;
                v2 = mk.z ? pv.z : -1e9f;
                v3 = mk.w ? pv.w : -1e9f;
            }
            const float mm = stats[r], iv = stats[64 + r];
            float p0 = __expf(v0 - mm) * iv;
            float p1 = __expf(v1 - mm) * iv;
            float p2 = __expf(v2 - mm) * iv;
            float p3 = __expf(v3 - mm) * iv;
            *(float4*)(Pb + (size_t)r * TT + c) = make_float4(p0, p1, p2, p3);
            uint2 hh, ll;
            hh.x = pack_hi2(p0, p1); hh.y = pack_hi2(p2, p3);
            ll.x = pack_lo2(p0, p1); ll.y = pack_lo2(p2, p3);
            __nv_bfloat16* R = As + r * SPADK;
            *(uint2*)(R + c)       = hh;
            *(uint2*)(R + 64 + c)  = ll;
            *(uint2*)(R + 128 + c) = hh;
        }
        #pragma unroll
        for (int i = 0; i < 6; i++) {
            int idx = tid + i * 256;
            int d = idx / 24, rem = idx - d * 24;
            int band = rem >> 3, j = rem & 7;
            uint4 v = *(const uint4*)(Vt + (size_t)d * 3072 + band * 1024 + k0 + j * 8);
            *(uint4*)(Bs + d * SPADK + band * 64 + j * 8) = v;
        }
        __syncthreads();
        #pragma unroll
        for (int ks = 0; ks < 12; ks++) {
            const uint32_t ko = ks * 32;
            uint32_t a[4], bfr[4][2];
            ldm4(a[0], a[1], a[2], a[3], aLM + ko);
            ldm4(bfr[0][0], bfr[1][0], bfr[0][1], bfr[1][1], bLM + ko);
            ldm4(bfr[2][0], bfr[3][0], bfr[2][1], bfr[3][1], bLM + 16 * SPADK * 2 + ko);
            #pragma unroll
            for (int ni = 0; ni < 4; ni++)
                mma_bf16(acc[ni], a, bfr[ni]);
        }
        __syncthreads();
    }

    // zero untouched causal region [kend, TT)
    if (causal && kend < TT) {
        const int Z = TT - kend;
        const int zw = Z >> 2;
        const int n4 = 64 * zw;
        const float4 z4 = make_float4(0.f, 0.f, 0.f, 0.f);
        for (int i = tid; i < n4; i += 256) {
            int r = i / zw, c = kend + (i - r * zw) * 4;
            *(float4*)(Sc + ((size_t)z * TT + q0 + r) * TT + c) = z4;
        }
    }

    const size_t m0 = (size_t)b * TT + q0 + wm * 16 + grp;
    const size_t m1 = m0 + 8;
    __nv_bfloat16* R0 = A3out + m0 * 3072;
    __nv_bfloat16* R1 = A3out + m1 * 3072;
    #pragma unroll
    for (int ni = 0; ni < 4; ni++) {
        const int cc = h * DKD + wn * 32 + ni * 8 + tg * 2;
        float v0 = acc[ni][0], v1 = acc[ni][1];
        float v2 = acc[ni][2], v3 = acc[ni][3];
        *(uint32_t*)(R0 + cc)        = pack_hi2(v0, v1);
        *(uint32_t*)(R0 + 1024 + cc) = pack_lo2(v0, v1);
        *(uint32_t*)(R0 + 2048 + cc) = pack_hi2(v0, v1);
        *(uint32_t*)(R1 + cc)        = pack_hi2(v2, v3);
        *(uint32_t*)(R1 + 1024 + cc) = pack_lo2(v2, v3);
        *(uint32_t*)(R1 + 2048 + cc) = pack_hi2(v2, v3);
    }
}

// ===================== residual add + LayerNorm =====================
__global__ __launch_bounds__(256) void add_ln(
    const float* __restrict__ X, const float* __restrict__ Dl,
    const float* __restrict__ g, const float* __restrict__ be,
    float* __restrict__ O, __nv_bfloat16* __restrict__ S3)
{
    const int row = blockIdx.x;
    const float* x  = X  + (size_t)row * DD;
    const float* dl = Dl + (size_t)row * DD;
    const int tid = threadIdx.x;

    float v[4];
    float s = 0.f;
    #pragma unroll
    for (int i = 0; i < 4; i++) {
        int c = tid + i * 256;
        v[i] = x[c] + dl[c];
        s += v[i];
    }
    __shared__ float red[8];
    #pragma unroll
    for (int o = 16; o > 0; o >>= 1) s += __shfl_xor_sync(0xffffffffu, s, o);
    if ((tid & 31) == 0) red[tid >> 5] = s;
    __syncthreads();
    s = 0.f;
    #pragma unroll
    for (int w = 0; w < 8; w++) s += red[w];
    float mean = s * (1.0f / 1024.0f);

    float qq = 0.f;
    #pragma unroll
    for (int i = 0; i < 4; i++) { float d = v[i] - mean; qq += d * d; }
    __syncthreads();
    #pragma unroll
    for (int o = 16; o > 0; o >>= 1) qq += __shfl_xor_sync(0xffffffffu, qq, o);
    if ((tid & 31) == 0) red[tid >> 5] = qq;
    __syncthreads();
    qq = 0.f;
    #pragma unroll
    for (int w = 0; w < 8; w++) qq += red[w];

    float stdv = sqrtf(qq * (1.0f / 1023.0f));
    float inv = 1.0f / (stdv + LN_EPS);
    __nv_bfloat16* R = S3 ? (S3 + (size_t)row * 3072) : (__nv_bfloat16*)0;
    #pragma unroll
    for (int i = 0; i < 4; i++) {
        int c = tid + i * 256;
        float o = g[c] * (v[i] - mean) * inv + be[c];
        O[(size_t)row * DD + c] = o;
        if (R) {
            __nv_bfloat16 h = __float2bfloat16(o);
            __nv_bfloat16 l = __float2bfloat16(o - __bfloat162float(h));
            R[c]        = h;
            R[1024 + c] = l;
            R[2048 + c] = h;
        }
    }
}

// ===================== orchestration =====================
extern "C" void kernel_launch(void* const* d_in, const int* in_sizes, int n_in,
                              void* d_out, int out_size)
{
    const float* x        = (const float*)d_in[0];
    const float* enc      = (const float*)d_in[1];
    const int*   src_mask = (const int*)  d_in[2];
    const float* wq_s = (const float*)d_in[4],  *bq_s = (const float*)d_in[5];
    const float* wk_s = (const float*)d_in[6],  *bk_s = (const float*)d_in[7];
    const float* wv_s = (const float*)d_in[8],  *bv_s = (const float*)d_in[9];
    const float* wo_s = (const float*)d_in[10], *bo_s = (const float*)d_in[11];
    const float* wq_c = (const float*)d_in[12], *bq_c = (const float*)d_in[13];
    const float* wk_c = (const float*)d_in[14], *bk_c = (const float*)d_in[15];
    const float* wv_c = (const float*)d_in[16], *bv_c = (const float*)d_in[17];
    const float* wo_c = (const float*)d_in[18], *bo_c = (const float*)d_in[19];
    const float* w1   = (const float*)d_in[20], *b1   = (const float*)d_in[21];
    const float* w2   = (const float*)d_in[22], *b2   = (const float*)d_in[23];
    const float* g1   = (const float*)d_in[24], *be1  = (const float*)d_in[25];
    const float* g2   = (const float*)d_in[26], *be2  = (const float*)d_in[27];
    const float* g3   = (const float*)d_in[28], *be3  = (const float*)d_in[29];

    float* out     = (float*)d_out;
    float* self_w  = out + (size_t)BB * TT * DD;
    float* cross_w = self_w + (size_t)BB * HH * TT * TT;

    float *Q, *K, *V, *T1, *X1, *X2;
    __nv_bfloat16 *A3, *FF3, *WT3, *VT3;
    cudaGetSymbolAddress((void**)&Q,   g_q);
    cudaGetSymbolAddress((void**)&K,   g_k);
    cudaGetSymbolAddress((void**)&V,   g_v);
    cudaGetSymbolAddress((void**)&T1,  g_t1);
    cudaGetSymbolAddress((void**)&X1,  g_x1);
    cudaGetSymbolAddress((void**)&X2,  g_x2);
    cudaGetSymbolAddress((void**)&A3,  g_a3);
    cudaGetSymbolAddress((void**)&FF3, g_ff3);
    cudaGetSymbolAddress((void**)&WT3, g_wt3);
    cudaGetSymbolAddress((void**)&VT3, g_vt3);

    cudaFuncSetAttribute(gemm_mma,        cudaFuncAttributeMaxDynamicSharedMemorySize, GEMM_SMEM);
    cudaFuncSetAttribute(attn_scores_mma, cudaFuncAttributeMaxDynamicSharedMemorySize, SCORES_SMEM);
    cudaFuncSetAttribute(attn_av_mma,     cudaFuncAttributeMaxDynamicSharedMemorySize, AV_SMEM);

    const int M = BB * TT;
    dim3 blk(256);
    dim3 tp32(32, 32);
    dim3 gD(DD / 128, M / 128);
    dim3 gF(DFFN / 128, M / 128);
    dim3 scoreG(TT / 256, TT / 128, BB * HH);
    dim3 avG(TT / 64, BB * HH);
    dim3 vtG(TT / 32, DD / 32, BB);
    dim3 lnG(M);
    const int ACT_BLKS = M * DD / 4 / 256;
    float* NC = (float*)0;
    __nv_bfloat16* NO3 = (__nv_bfloat16*)0;

    // ---- self attention ----
    split_act<<<ACT_BLKS, blk>>>(x, A3);
    split_w<<<dim3(32, 32), tp32>>>(wq_s, WT3 + 0 * W3D, DD, DD);
    split_w<<<dim3(32, 32), tp32>>>(wk_s, WT3 + 1 * W3D, DD, DD);
    split_w<<<dim3(32, 32), tp32>>>(wv_s, WT3 + 2 * W3D, DD, DD);
    split_w<<<dim3(32, 32), tp32>>>(wo_s, WT3 + 3 * W3D, DD, DD);
    gemm_mma<<<gD, blk, GEMM_SMEM>>>(A3, WT3 + 0 * W3D, bq_s, Q, NO3, DD, 3072, 0);
    gemm_mma<<<gD, blk, GEMM_SMEM>>>(A3, WT3 + 1 * W3D, bk_s, K, NO3, DD, 3072, 0);
    gemm_mma<<<gD, blk, GEMM_SMEM>>>(A3, WT3 + 2 * W3D, bv_s, V, NO3, DD, 3072, 0);
    vt_split<<<vtG, tp32>>>(V, VT3);
    attn_scores_mma<<<scoreG, blk, SCORES_SMEM>>>(Q, K, self_w, 1);
    attn_av_mma<<<avG, blk, AV_SMEM>>>(self_w, VT3, src_mask, A3, 1);
    gemm_mma<<<gD, blk, GEMM_SMEM>>>(A3, WT3 + 3 * W3D, bo_s, T1, NO3, DD, 3072, 0);
    add_ln<<<lnG, blk>>>(x, T1, g1, be1, X1, A3);

    // ---- remaining weight splits ----
    split_w<<<dim3(32, 32), tp32>>>(wq_c, WT3 + 4 * W3D, DD, DD);
    split_w<<<dim3(32, 32), tp32>>>(wk_c, WT3 + 5 * W3D, DD, DD);
    split_w<<<dim3(32, 32), tp32>>>(wv_c, WT3 + 6 * W3D, DD, DD);
    split_w<<<dim3(32, 32), tp32>>>(wo_c, WT3 + 7 * W3D, DD, DD);
    split_w<<<dim3(128, 32), tp32>>>(w1, WT3 + W1OFF, DD, DFFN);
    split_w<<<dim3(32, 128), tp32>>>(w2, WT3 + W2OFF, DFFN, DD);

    // ---- cross attention ----
    gemm_mma<<<gD, blk, GEMM_SMEM>>>(A3, WT3 + 4 * W3D, bq_c, Q, NO3, DD, 3072, 0);
    split_act<<<ACT_BLKS, blk>>>(enc, A3);
    gemm_mma<<<gD, blk, GEMM_SMEM>>>(A3, WT3 + 5 * W3D, bk_c, K, NO3, DD, 3072, 0);
    gemm_mma<<<gD, blk, GEMM_SMEM>>>(A3, WT3 + 6 * W3D, bv_c, V, NO3, DD, 3072, 0);
    vt_split<<<vtG, tp32>>>(V, VT3);
    attn_scores_mma<<<scoreG, blk, SCORES_SMEM>>>(Q, K, cross_w, 0);
    attn_av_mma<<<avG, blk, AV_SMEM>>>(cross_w, VT3, src_mask, A3, 0);
    gemm_mma<<<gD, blk, GEMM_SMEM>>>(A3, WT3 + 7 * W3D, bo_c, T1, NO3, DD, 3072, 0);
    add_ln<<<lnG, blk>>>(X1, T1, g2, be2, X2, A3);

    // ---- feed-forward ----
    gemm_mma<<<gF, blk, GEMM_SMEM>>>(A3, WT3 + W1OFF, b1, NC, FF3, DFFN, 3072, 1);
    gemm_mma<<<gD, blk, GEMM_SMEM>>>(FF3, WT3 + W2OFF, b2, T1, NO3, DD, 12288, 0);
    add_ln<<<lnG, blk>>>(X2, T1, g3, be3, out, NO3);

    (void)in_sizes; (void)n_in; (void)out_size;
}

// round 10
// speedup vs baseline: 1.1931x; 1.0812x over previous
#include <cuda_runtime.h>
#include <cuda_bf16.h>
#include <math.h>
#include <stdint.h>

#define BB 4
#define TT 1024
#define SS 1024
#define DD 1024
#define HH 16
#define DKD 64
#define DFFN 4096
#define LN_EPS 1e-6f

// ===================== scratch (no allocations) =====================
__device__ float g_q [BB*TT*DD];
__device__ float g_k [BB*TT*DD];
__device__ float g_v [BB*TT*DD];
__device__ float g_t1[BB*TT*DD];
__device__ float g_x1[BB*TT*DD];
__device__ float g_x2[BB*TT*DD];

__device__ __nv_bfloat16 g_a2 [4096ULL * 2048];   // activations [M,2K] (hi|lo)
__device__ __nv_bfloat16 g_ff2[4096ULL * 8192];   // FF activations (hi|lo)
__device__ __nv_bfloat16 g_vt3[4096ULL * 3072];   // V^T split per (b,h): [64 d][hi|hi|lo seq]
#define W2D (1024ULL*2048)
#define W1OFF (8*W2D)
#define W2OFF (8*W2D + 4096ULL*2048)
__device__ __nv_bfloat16 g_wt2[8*W2D + 4096ULL*2048 + 1024ULL*8192];

// ===================== helpers =====================
__device__ __forceinline__ uint32_t pack_hi2(float x, float y) {
    __nv_bfloat16 a = __float2bfloat16(x), b = __float2bfloat16(y);
    return (uint32_t)__bfloat16_as_ushort(a) | ((uint32_t)__bfloat16_as_ushort(b) << 16);
}
__device__ __forceinline__ uint32_t pack_lo2(float x, float y) {
    __nv_bfloat16 a = __float2bfloat16(x), b = __float2bfloat16(y);
    __nv_bfloat16 ra = __float2bfloat16(x - __bfloat162float(a));
    __nv_bfloat16 rb = __float2bfloat16(y - __bfloat162float(b));
    return (uint32_t)__bfloat16_as_ushort(ra) | ((uint32_t)__bfloat16_as_ushort(rb) << 16);
}
__device__ __forceinline__ void mma_bf16(
    float* d, const uint32_t* a, const uint32_t* b)
{
    asm volatile(
        "mma.sync.aligned.m16n8k16.row.col.f32.bf16.bf16.f32 "
        "{%0,%1,%2,%3}, {%4,%5,%6,%7}, {%8,%9}, {%0,%1,%2,%3};"
        : "+f"(d[0]), "+f"(d[1]), "+f"(d[2]), "+f"(d[3])
        : "r"(a[0]), "r"(a[1]), "r"(a[2]), "r"(a[3]), "r"(b[0]), "r"(b[1]));
}
__device__ __forceinline__ uint32_t smem_u32(const void* p) {
    uint32_t a;
    asm("{ .reg .u64 t; cvta.to.shared.u64 t, %1; cvt.u32.u64 %0, t; }" : "=r"(a) : "l"(p));
    return a;
}
__device__ __forceinline__ void cp16(uint32_t s, const void* g) {
    asm volatile("cp.async.cg.shared.global [%0], [%1], 16;" :: "r"(s), "l"(g));
}
#define CP_COMMIT() asm volatile("cp.async.commit_group;" ::: "memory")
#define CP_WAIT1()  asm volatile("cp.async.wait_group 1;" ::: "memory")
__device__ __forceinline__ void ldm4(uint32_t& r0, uint32_t& r1, uint32_t& r2, uint32_t& r3, uint32_t a) {
    asm volatile("ldmatrix.sync.aligned.m8n8.x4.shared.b16 {%0,%1,%2,%3}, [%4];"
        : "=r"(r0), "=r"(r1), "=r"(r2), "=r"(r3) : "r"(a));
}

// ===================== split/convert kernels =====================
// A [M, 1024] fp32 -> O [M, 2048] bf16 as [hi | lo]
__global__ __launch_bounds__(256) void split_act(
    const float* __restrict__ A, __nv_bfloat16* __restrict__ O)
{
    const int K = 1024;
    size_t idx = (size_t)blockIdx.x * 256 + threadIdx.x;
    size_t base = idx << 2;
    size_t m = base >> 10;
    int k = (int)(base & (size_t)(K - 1));
    float4 v = *(const float4*)(A + base);
    uint2 hh, ll;
    hh.x = pack_hi2(v.x, v.y); hh.y = pack_hi2(v.z, v.w);
    ll.x = pack_lo2(v.x, v.y); ll.y = pack_lo2(v.z, v.w);
    __nv_bfloat16* row = O + m * (size_t)(2 * K);
    *(uint2*)(row + k)     = hh;
    *(uint2*)(row + K + k) = ll;
}

// W [K, N] fp32 -> O [N, 2K] bf16 as [hi | lo] (transposed)
__global__ void split_w(
    const float* __restrict__ W, __nv_bfloat16* __restrict__ O, int K, int N)
{
    __shared__ float t[32][33];
    int k = blockIdx.y * 32 + threadIdx.y;
    int n = blockIdx.x * 32 + threadIdx.x;
    t[threadIdx.y][threadIdx.x] = W[(size_t)k * N + n];
    __syncthreads();
    int nn = blockIdx.x * 32 + threadIdx.y;
    int kk = blockIdx.y * 32 + threadIdx.x;
    float v = t[threadIdx.x][threadIdx.y];
    __nv_bfloat16 h = __float2bfloat16(v);
    __nv_bfloat16 l = __float2bfloat16(v - __bfloat162float(h));
    size_t ro = (size_t)nn * (size_t)(2 * K);
    O[ro + kk]     = h;
    O[ro + K + kk] = l;
}

__global__ void vt_split(
    const float* __restrict__ V, __nv_bfloat16* __restrict__ VT3)
{
    __shared__ float t[32][33];
    const int b = blockIdx.z;
    int k = blockIdx.x * 32 + threadIdx.y;
    int d = blockIdx.y * 32 + threadIdx.x;
    t[threadIdx.y][threadIdx.x] = V[((size_t)(b * TT + k)) * DD + d];
    __syncthreads();
    int dg = blockIdx.y * 32 + threadIdx.y;
    int kg = blockIdx.x * 32 + threadIdx.x;
    float v = t[threadIdx.x][threadIdx.y];
    __nv_bfloat16 h = __float2bfloat16(v);
    __nv_bfloat16 l = __float2bfloat16(v - __bfloat162float(h));
    int hh = dg >> 6, dk = dg & 63;
    size_t row = ((size_t)(b * HH + hh) * 64 + dk) * 3072;
    VT3[row + kg]        = h;
    VT3[row + 1024 + kg] = h;
    VT3[row + 2048 + kg] = l;
}

// ===================== HMMA GEMM, 2-segment operands, 3 products in-smem ====
// A2[M, 2Kl] (hi|lo), W2[N, 2Kl] (hi|lo). Per 32-k chunk: Ah*Wh + Al*Wh + Ah*Wl.
#define PADK2 72                          // 64 cols (32 hi + 32 lo) + 8 pad
#define TSTG (128 * PADK2 * 2)            // one operand tile bytes = 18432
#define SSTG (2 * TSTG)                   // stage (A+B) = 36864
#define STAGES2 3
#define GEMM_SMEM (STAGES2 * SSTG)        // 110592

__global__ __launch_bounds__(256) void gemm_mma(
    const __nv_bfloat16* __restrict__ A2, const __nv_bfloat16* __restrict__ W2,
    const float* __restrict__ bias, float* __restrict__ C,
    __nv_bfloat16* __restrict__ O3, int N, int Kl, int relu)
{
    extern __shared__ char dsm[];
    const uint32_t sb = smem_u32(dsm);
    const int tid = threadIdx.x;
    const int lane = tid & 31, wid = tid >> 5;
    const int wm = wid >> 2, wn = wid & 3;
    const int grp = lane >> 2, tg = lane & 3;

    const size_t arow0 = (size_t)blockIdx.y * 128;
    const size_t bcol0 = (size_t)blockIdx.x * 128;
    const size_t rstr = (size_t)2 * Kl;

    // cp.async mapping: 1024 16B-segments per operand; 4 per thread per operand
    const uint32_t aLM = (uint32_t)(((wm * 64) + (lane & 15)) * PADK2 + (lane >> 4) * 8) * 2;
    const uint32_t bLM = (uint32_t)(((wn * 32) + (lane & 15)) * PADK2 + (lane >> 4) * 8) * 2;

    float acc[4][4][4];
    #pragma unroll
    for (int i = 0; i < 4; i++)
        #pragma unroll
        for (int j = 0; j < 4; j++)
            #pragma unroll
            for (int q = 0; q < 4; q++) acc[i][j][q] = 0.f;

    const int NC = Kl >> 5;

    auto issue = [&](int c, int st) {
        const uint32_t ab = sb + st * SSTG;
        const uint32_t bb = ab + TSTG;
        #pragma unroll
        for (int i = 0; i < 4; i++) {
            int idx = tid + i * 256;
            int r = idx >> 3, s = idx & 7;
            size_t go = (s < 4) ? ((size_t)c * 32 + s * 8)
                                : ((size_t)Kl + c * 32 + (s - 4) * 8);
            uint32_t so = (uint32_t)(r * PADK2 + s * 8) * 2;
            cp16(ab + so, A2 + (arow0 + r) * rstr + go);
            cp16(bb + so, W2 + (bcol0 + r) * rstr + go);
        }
        CP_COMMIT();
    };

    issue(0, 0); issue(1, 1);

    int st = 0;
    for (int c = 0; c < NC; c++) {
        CP_WAIT1();
        __syncthreads();
        if (c + 2 < NC) {
            int ns = st + 2; if (ns >= 3) ns -= 3;
            issue(c + 2, ns);
        } else CP_COMMIT();

        const uint32_t As0 = sb + st * SSTG;
        const uint32_t Bs0 = As0 + TSTG;
        #pragma unroll
        for (int ks = 0; ks < 2; ks++) {
            const uint32_t ko = ks * 32;          // 16 cols = 32 bytes
            uint32_t ah[4][4], al[4][4], b2[4][2];
            // hi A frags
            #pragma unroll
            for (int ms = 0; ms < 4; ms++)
                ldm4(ah[ms][0], ah[ms][1], ah[ms][2], ah[ms][3],
                     As0 + aLM + ms * (16 * PADK2 * 2) + ko);
            // hi B frags
            ldm4(b2[0][0], b2[1][0], b2[0][1], b2[1][1], Bs0 + bLM + ko);
            ldm4(b2[2][0], b2[3][0], b2[2][1], b2[3][1], Bs0 + bLM + 16 * PADK2 * 2 + ko);
            #pragma unroll
            for (int ms = 0; ms < 4; ms++)
                #pragma unroll
                for (int ns = 0; ns < 4; ns++)
                    mma_bf16(acc[ms][ns], ah[ms], b2[ns]);
            // lo A frags (cols +32 = +64B)
            #pragma unroll
            for (int ms = 0; ms < 4; ms++)
                ldm4(al[ms][0], al[ms][1], al[ms][2], al[ms][3],
                     As0 + aLM + ms * (16 * PADK2 * 2) + ko + 64);
            #pragma unroll
            for (int ms = 0; ms < 4; ms++)
                #pragma unroll
                for (int ns = 0; ns < 4; ns++)
                    mma_bf16(acc[ms][ns], al[ms], b2[ns]);
            // lo B frags overwrite b2
            ldm4(b2[0][0], b2[1][0], b2[0][1], b2[1][1], Bs0 + bLM + ko + 64);
            ldm4(b2[2][0], b2[3][0], b2[2][1], b2[3][1], Bs0 + bLM + 16 * PADK2 * 2 + ko + 64);
            #pragma unroll
            for (int ms = 0; ms < 4; ms++)
                #pragma unroll
                for (int ns = 0; ns < 4; ns++)
                    mma_bf16(acc[ms][ns], ah[ms], b2[ns]);
        }
        if (++st >= 3) st = 0;
    }

    if (O3) {
        const size_t ostr = (size_t)2 * N;
        #pragma unroll
        for (int ms = 0; ms < 4; ms++) {
            const size_t rr0 = arow0 + wm * 64 + ms * 16 + grp;
            #pragma unroll
            for (int ns = 0; ns < 4; ns++) {
                const size_t cc = bcol0 + wn * 32 + ns * 8 + tg * 2;
                float bx = bias[cc], by = bias[cc + 1];
                float v0 = fmaxf(acc[ms][ns][0] + bx, 0.f);
                float v1 = fmaxf(acc[ms][ns][1] + by, 0.f);
                float v2 = fmaxf(acc[ms][ns][2] + bx, 0.f);
                float v3 = fmaxf(acc[ms][ns][3] + by, 0.f);
                __nv_bfloat16* R0 = O3 + rr0 * ostr;
                __nv_bfloat16* R1 = O3 + (rr0 + 8) * ostr;
                *(uint32_t*)(R0 + cc)     = pack_hi2(v0, v1);
                *(uint32_t*)(R0 + N + cc) = pack_lo2(v0, v1);
                *(uint32_t*)(R1 + cc)     = pack_hi2(v2, v3);
                *(uint32_t*)(R1 + N + cc) = pack_lo2(v2, v3);
            }
        }
    } else {
        #pragma unroll
        for (int ms = 0; ms < 4; ms++) {
            const size_t rr0 = arow0 + wm * 64 + ms * 16 + grp;
            #pragma unroll
            for (int ns = 0; ns < 4; ns++) {
                const size_t cc = bcol0 + wn * 32 + ns * 8 + tg * 2;
                float bx = bias[cc], by = bias[cc + 1];
                float v0 = acc[ms][ns][0] + bx;
                float v1 = acc[ms][ns][1] + by;
                float v2 = acc[ms][ns][2] + bx;
                float v3 = acc[ms][ns][3] + by;
                if (relu) {
                    v0 = fmaxf(v0, 0.f); v1 = fmaxf(v1, 0.f);
                    v2 = fmaxf(v2, 0.f); v3 = fmaxf(v3, 0.f);
                }
                *(float2*)(C + rr0 * N + cc)       = make_float2(v0, v1);
                *(float2*)(C + (rr0 + 8) * N + cc) = make_float2(v2, v3);
            }
        }
    }
}

// ===================== attention scores (raw scaled logits) ======
#define SPADK 200
#define SCORES_SMEM ((128 + 64) * SPADK * 2)
__global__ __launch_bounds__(256) void attn_scores_mma(
    const float* __restrict__ Q, const float* __restrict__ Kv,
    float* __restrict__ Sc, int causal)
{
    extern __shared__ __nv_bfloat16 sm[];
    __nv_bfloat16* As = sm;                 // [128][SPADK]  Q: [hi|lo|hi]
    __nv_bfloat16* Bs = sm + 128 * SPADK;   // [64][SPADK]   K: [hi|hi|lo]
    const int z = blockIdx.z, b = z >> 4, h = z & 15;
    const int q0 = blockIdx.y * 128;
    const int kbase = blockIdx.x * 256;
    if (causal && kbase >= q0 + 128) return;

    const int tid = threadIdx.x, lane = tid & 31, wid = tid >> 5;
    const int wm = wid >> 1, wn = wid & 1;
    const int grp = lane >> 2, tg = lane & 3;

    const float* Qb = Q + ((size_t)(b * TT + q0)) * DD + h * DKD;

    #pragma unroll
    for (int i = 0; i < 8; i++) {
        int f = tid + i * 256;
        int r = f >> 4, c = (f & 15) << 2;
        float4 v = *(const float4*)(Qb + (size_t)r * DD + c);
        uint2 hh, ll;
        hh.x = pack_hi2(v.x, v.y); hh.y = pack_hi2(v.z, v.w);
        ll.x = pack_lo2(v.x, v.y); ll.y = pack_lo2(v.z, v.w);
        __nv_bfloat16* R = As + r * SPADK;
        *(uint2*)(R + c)       = hh;
        *(uint2*)(R + 64 + c)  = ll;
        *(uint2*)(R + 128 + c) = hh;
    }

    const uint32_t AsU = smem_u32(As), BsU = smem_u32(Bs);
    const uint32_t aLM = AsU + (uint32_t)(((wm * 32) + (lane & 15)) * SPADK + (lane >> 4) * 8) * 2;
    const uint32_t bLM = BsU + (uint32_t)(((wn * 32) + (lane & 15)) * SPADK + (lane >> 4) * 8) * 2;

    for (int kt = 0; kt < 4; kt++) {
        const int k0 = kbase + kt * 64;
        if (causal && k0 >= q0 + 128) break;

        __syncthreads();
        const float* Kb = Kv + ((size_t)(b * TT + k0)) * DD + h * DKD;
        #pragma unroll
        for (int i = 0; i < 4; i++) {
            int f = tid + i * 256;
            int r = f >> 4, c = (f & 15) << 2;
            float4 v = *(const float4*)(Kb + (size_t)r * DD + c);
            uint2 hh, ll;
            hh.x = pack_hi2(v.x, v.y); hh.y = pack_hi2(v.z, v.w);
            ll.x = pack_lo2(v.x, v.y); ll.y = pack_lo2(v.z, v.w);
            __nv_bfloat16* R = Bs + r * SPADK;
            *(uint2*)(R + c)       = hh;
            *(uint2*)(R + 64 + c)  = hh;
            *(uint2*)(R + 128 + c) = ll;
        }
        __syncthreads();

        float acc[2][4][4];
        #pragma unroll
        for (int i = 0; i < 2; i++)
            #pragma unroll
            for (int j = 0; j < 4; j++)
                #pragma unroll
                for (int q = 0; q < 4; q++) acc[i][j][q] = 0.f;

        #pragma unroll
        for (int ks = 0; ks < 12; ks++) {
            const uint32_t ko = ks * 32;
            uint32_t a[2][4], bfr[4][2];
            #pragma unroll
            for (int mi = 0; mi < 2; mi++)
                ldm4(a[mi][0], a[mi][1], a[mi][2], a[mi][3],
                     aLM + mi * (16 * SPADK * 2) + ko);
            ldm4(bfr[0][0], bfr[1][0], bfr[0][1], bfr[1][1], bLM + ko);
            ldm4(bfr[2][0], bfr[3][0], bfr[2][1], bfr[3][1], bLM + 16 * SPADK * 2 + ko);
            #pragma unroll
            for (int mi = 0; mi < 2; mi++)
                #pragma unroll
                for (int ni = 0; ni < 4; ni++)
                    mma_bf16(acc[mi][ni], a[mi], bfr[ni]);
        }

        float* Out = Sc + ((size_t)z * TT + q0) * TT + k0;
        #pragma unroll
        for (int mi = 0; mi < 2; mi++) {
            const size_t r = wm * 32 + mi * 16 + grp;
            #pragma unroll
            for (int ni = 0; ni < 4; ni++) {
                const size_t c = wn * 32 + ni * 8 + tg * 2;
                *(float2*)(Out + r * TT + c) =
                    make_float2(acc[mi][ni][0] * 0.125f, acc[mi][ni][1] * 0.125f);
                *(float2*)(Out + (r + 8) * TT + c) =
                    make_float2(acc[mi][ni][2] * 0.125f, acc[mi][ni][3] * 0.125f);
            }
        }
    }
}

// ===================== attn @ V with fused softmax =====================
#define AV_SMEM ((64 + 64) * SPADK * 2 + 512)
__global__ __launch_bounds__(256) void attn_av_mma(
    float* __restrict__ Sc, const __nv_bfloat16* __restrict__ VT3,
    const int* __restrict__ mask, __nv_bfloat16* __restrict__ A2out, int causal)
{
    extern __shared__ __nv_bfloat16 sm[];
    __nv_bfloat16* As = sm;                // [64][SPADK]  P: [hi|lo|hi]
    __nv_bfloat16* Bs = sm + 64 * SPADK;   // [64][SPADK]  V^T: [hi|hi|lo]
    float* stats = (float*)(sm + (64 + 64) * SPADK);
    const int z = blockIdx.y, b = z >> 4, h = z & 15;
    const int q0 = blockIdx.x * 64;

    const int tid = threadIdx.x, lane = tid & 31, wid = tid >> 5;
    const int wm = wid >> 1, wn = wid & 1;
    const int grp = lane >> 2, tg = lane & 3;

    const int kend = causal ? (q0 + 64) : TT;

    // ---- pass 1: per-row online max / exp-sum ----
    {
        const int rloc = wid * 8 + (lane >> 2);
        const int qd = lane & 3;
        const int qabs = q0 + rloc;
        const float* Srow = Sc + ((size_t)z * TT + qabs) * TT;
        float m = -3.0e38f, s = 0.f;
        for (int j = 0; j < (kend >> 4); j++) {
            int k = qd * 4 + j * 16;
            float4 v4 = *(const float4*)(Srow + k);
            float v0, v1, v2, v3;
            if (causal) {
                v0 = (k     <= qabs) ? v4.x : -1e9f;
                v1 = (k + 1 <= qabs) ? v4.y : -1e9f;
                v2 = (k + 2 <= qabs) ? v4.z : -1e9f;
                v3 = (k + 3 <= qabs) ? v4.w : -1e9f;
            } else {
                int4 mk = *(const int4*)(mask + b * SS + k);
                v0 = mk.x ? v4.x : -1e9f;
                v1 = mk.y ? v4.y : -1e9f;
                v2 = mk.z ? v4.z : -1e9f;
                v3 = mk.w ? v4.w : -1e9f;
            }
            float tm = fmaxf(fmaxf(v0, v1), fmaxf(v2, v3));
            float nm = fmaxf(m, tm);
            s = s * __expf(m - nm)
              + __expf(v0 - nm) + __expf(v1 - nm)
              + __expf(v2 - nm) + __expf(v3 - nm);
            m = nm;
        }
        #pragma unroll
        for (int o = 1; o <= 2; o <<= 1) {
            float mo = __shfl_xor_sync(0xffffffffu, m, o);
            float so = __shfl_xor_sync(0xffffffffu, s, o);
            float nm = fmaxf(m, mo);
            s = s * __expf(m - nm) + so * __expf(mo - nm);
            m = nm;
        }
        if (qd == 0) { stats[rloc] = m; stats[64 + rloc] = 1.0f / s; }
    }
    __syncthreads();

    const __nv_bfloat16* Vt = VT3 + (size_t)z * 64 * 3072;
    const uint32_t AsU = smem_u32(As), BsU = smem_u32(Bs);
    const uint32_t aLM = AsU + (uint32_t)(((wm * 16) + (lane & 15)) * SPADK + (lane >> 4) * 8) * 2;
    const uint32_t bLM = BsU + (uint32_t)(((wn * 32) + (lane & 15)) * SPADK + (lane >> 4) * 8) * 2;

    float acc[4][4];
    #pragma unroll
    for (int i = 0; i < 4; i++)
        #pragma unroll
        for (int j = 0; j < 4; j++) acc[i][j] = 0.f;

    for (int k0 = 0; k0 < kend; k0 += 64) {
        float* Pb = Sc + ((size_t)z * TT + q0) * TT + k0;
        #pragma unroll
        for (int i = 0; i < 4; i++) {
            int f = tid + i * 256;
            int r = f >> 4, c = (f & 15) << 2;
            float4 pv = *(float4*)(Pb + (size_t)r * TT + c);
            const int qabs = q0 + r;
            const int kg = k0 + c;
            float v0, v1, v2, v3;
            if (causal) {
                v0 = (kg     <= qabs) ? pv.x : -1e9f;
                v1 = (kg + 1 <= qabs) ? pv.y : -1e9f;
                v2 = (kg + 2 <= qabs) ? pv.z : -1e9f;
                v3 = (kg + 3 <= qabs) ? pv.w : -1e9f;
            } else {
                int4 mk = *(const int4*)(mask + b * SS + kg);
                v0 = mk.x ? pv.x : -1e9f;
                v1 = mk.y ? pv.y : -1e9f;
                v2 = mk.z ? pv.z : -1e9f;
                v3 = mk.w ? pv.w : -1e9f;
            }
            const float mm = stats[r], iv = stats[64 + r];
            float p0 = __expf(v0 - mm) * iv;
            float p1 = __expf(v1 - mm) * iv;
            float p2 = __expf(v2 - mm) * iv;
            float p3 = __expf(v3 - mm) * iv;
            *(float4*)(Pb + (size_t)r * TT + c) = make_float4(p0, p1, p2, p3);
            uint2 hh, ll;
            hh.x = pack_hi2(p0, p1); hh.y = pack_hi2(p2, p3);
            ll.x = pack_lo2(p0, p1); ll.y = pack_lo2(p2, p3);
            __nv_bfloat16* R = As + r * SPADK;
            *(uint2*)(R + c)       = hh;
            *(uint2*)(R + 64 + c)  = ll;
            *(uint2*)(R + 128 + c) = hh;
        }
        #pragma unroll
        for (int i = 0; i < 6; i++) {
            int idx = tid + i * 256;
            int d = idx / 24, rem = idx - d * 24;
            int band = rem >> 3, j = rem & 7;
            uint4 v = *(const uint4*)(Vt + (size_t)d * 3072 + band * 1024 + k0 + j * 8);
            *(uint4*)(Bs + d * SPADK + band * 64 + j * 8) = v;
        }
        __syncthreads();
        #pragma unroll
        for (int ks = 0; ks < 12; ks++) {
            const uint32_t ko = ks * 32;
            uint32_t a[4], bfr[4][2];
            ldm4(a[0], a[1], a[2], a[3], aLM + ko);
            ldm4(bfr[0][0], bfr[1][0], bfr[0][1], bfr[1][1], bLM + ko);
            ldm4(bfr[2][0], bfr[3][0], bfr[2][1], bfr[3][1], bLM + 16 * SPADK * 2 + ko);
            #pragma unroll
            for (int ni = 0; ni < 4; ni++)
                mma_bf16(acc[ni], a, bfr[ni]);
        }
        __syncthreads();
    }

    if (causal && kend < TT) {
        const int Z = TT - kend;
        const int zw = Z >> 2;
        const int n4 = 64 * zw;
        const float4 z4 = make_float4(0.f, 0.f, 0.f, 0.f);
        for (int i = tid; i < n4; i += 256) {
            int r = i / zw, c = kend + (i - r * zw) * 4;
            *(float4*)(Sc + ((size_t)z * TT + q0 + r) * TT + c) = z4;
        }
    }

    // epilogue -> A2 [hi|lo] (stride 2048)
    const size_t m0 = (size_t)b * TT + q0 + wm * 16 + grp;
    const size_t m1 = m0 + 8;
    __nv_bfloat16* R0 = A2out + m0 * 2048;
    __nv_bfloat16* R1 = A2out + m1 * 2048;
    #pragma unroll
    for (int ni = 0; ni < 4; ni++) {
        const int cc = h * DKD + wn * 32 + ni * 8 + tg * 2;
        float v0 = acc[ni][0], v1 = acc[ni][1];
        float v2 = acc[ni][2], v3 = acc[ni][3];
        *(uint32_t*)(R0 + cc)        = pack_hi2(v0, v1);
        *(uint32_t*)(R0 + 1024 + cc) = pack_lo2(v0, v1);
        *(uint32_t*)(R1 + cc)        = pack_hi2(v2, v3);
        *(uint32_t*)(R1 + 1024 + cc) = pack_lo2(v2, v3);
    }
}

// ===================== residual add + LayerNorm =====================
__global__ __launch_bounds__(256) void add_ln(
    const float* __restrict__ X, const float* __restrict__ Dl,
    const float* __restrict__ g, const float* __restrict__ be,
    float* __restrict__ O, __nv_bfloat16* __restrict__ S2)
{
    const int row = blockIdx.x;
    const float* x  = X  + (size_t)row * DD;
    const float* dl = Dl + (size_t)row * DD;
    const int tid = threadIdx.x;

    float v[4];
    float s = 0.f;
    #pragma unroll
    for (int i = 0; i < 4; i++) {
        int c = tid + i * 256;
        v[i] = x[c] + dl[c];
        s += v[i];
    }
    __shared__ float red[8];
    #pragma unroll
    for (int o = 16; o > 0; o >>= 1) s += __shfl_xor_sync(0xffffffffu, s, o);
    if ((tid & 31) == 0) red[tid >> 5] = s;
    __syncthreads();
    s = 0.f;
    #pragma unroll
    for (int w = 0; w < 8; w++) s += red[w];
    float mean = s * (1.0f / 1024.0f);

    float qq = 0.f;
    #pragma unroll
    for (int i = 0; i < 4; i++) { float d = v[i] - mean; qq += d * d; }
    __syncthreads();
    #pragma unroll
    for (int o = 16; o > 0; o >>= 1) qq += __shfl_xor_sync(0xffffffffu, qq, o);
    if ((tid & 31) == 0) red[tid >> 5] = qq;
    __syncthreads();
    qq = 0.f;
    #pragma unroll
    for (int w = 0; w < 8; w++) qq += red[w];

    float stdv = sqrtf(qq * (1.0f / 1023.0f));
    float inv = 1.0f / (stdv + LN_EPS);
    __nv_bfloat16* R = S2 ? (S2 + (size_t)row * 2048) : (__nv_bfloat16*)0;
    #pragma unroll
    for (int i = 0; i < 4; i++) {
        int c = tid + i * 256;
        float o = g[c] * (v[i] - mean) * inv + be[c];
        O[(size_t)row * DD + c] = o;
        if (R) {
            __nv_bfloat16 h = __float2bfloat16(o);
            __nv_bfloat16 l = __float2bfloat16(o - __bfloat162float(h));
            R[c]        = h;
            R[1024 + c] = l;
        }
    }
}

// ===================== orchestration =====================
extern "C" void kernel_launch(void* const* d_in, const int* in_sizes, int n_in,
                              void* d_out, int out_size)
{
    const float* x        = (const float*)d_in[0];
    const float* enc      = (const float*)d_in[1];
    const int*   src_mask = (const int*)  d_in[2];
    const float* wq_s = (const float*)d_in[4],  *bq_s = (const float*)d_in[5];
    const float* wk_s = (const float*)d_in[6],  *bk_s = (const float*)d_in[7];
    const float* wv_s = (const float*)d_in[8],  *bv_s = (const float*)d_in[9];
    const float* wo_s = (const float*)d_in[10], *bo_s = (const float*)d_in[11];
    const float* wq_c = (const float*)d_in[12], *bq_c = (const float*)d_in[13];
    const float* wk_c = (const float*)d_in[14], *bk_c = (const float*)d_in[15];
    const float* wv_c = (const float*)d_in[16], *bv_c = (const float*)d_in[17];
    const float* wo_c = (const float*)d_in[18], *bo_c = (const float*)d_in[19];
    const float* w1   = (const float*)d_in[20], *b1   = (const float*)d_in[21];
    const float* w2   = (const float*)d_in[22], *b2   = (const float*)d_in[23];
    const float* g1   = (const float*)d_in[24], *be1  = (const float*)d_in[25];
    const float* g2   = (const float*)d_in[26], *be2  = (const float*)d_in[27];
    const float* g3   = (const float*)d_in[28], *be3  = (const float*)d_in[29];

    float* out     = (float*)d_out;
    float* self_w  = out + (size_t)BB * TT * DD;
    float* cross_w = self_w + (size_t)BB * HH * TT * TT;

    float *Q, *K, *V, *T1, *X1, *X2;
    __nv_bfloat16 *A2, *FF2, *WT2, *VT3;
    cudaGetSymbolAddress((void**)&Q,   g_q);
    cudaGetSymbolAddress((void**)&K,   g_k);
    cudaGetSymbolAddress((void**)&V,   g_v);
    cudaGetSymbolAddress((void**)&T1,  g_t1);
    cudaGetSymbolAddress((void**)&X1,  g_x1);
    cudaGetSymbolAddress((void**)&X2,  g_x2);
    cudaGetSymbolAddress((void**)&A2,  g_a2);
    cudaGetSymbolAddress((void**)&FF2, g_ff2);
    cudaGetSymbolAddress((void**)&WT2, g_wt2);
    cudaGetSymbolAddress((void**)&VT3, g_vt3);

    cudaFuncSetAttribute(gemm_mma,        cudaFuncAttributeMaxDynamicSharedMemorySize, GEMM_SMEM);
    cudaFuncSetAttribute(attn_scores_mma, cudaFuncAttributeMaxDynamicSharedMemorySize, SCORES_SMEM);
    cudaFuncSetAttribute(attn_av_mma,     cudaFuncAttributeMaxDynamicSharedMemorySize, AV_SMEM);

    const int M = BB * TT;
    dim3 blk(256);
    dim3 tp32(32, 32);
    dim3 gD(DD / 128, M / 128);
    dim3 gF(DFFN / 128, M / 128);
    dim3 scoreG(TT / 256, TT / 128, BB * HH);
    dim3 avG(TT / 64, BB * HH);
    dim3 vtG(TT / 32, DD / 32, BB);
    dim3 lnG(M);
    const int ACT_BLKS = M * DD / 4 / 256;
    float* NC = (float*)0;
    __nv_bfloat16* NO3 = (__nv_bfloat16*)0;

    // ---- self attention ----
    split_act<<<ACT_BLKS, blk>>>(x, A2);
    split_w<<<dim3(32, 32), tp32>>>(wq_s, WT2 + 0 * W2D, DD, DD);
    split_w<<<dim3(32, 32), tp32>>>(wk_s, WT2 + 1 * W2D, DD, DD);
    split_w<<<dim3(32, 32), tp32>>>(wv_s, WT2 + 2 * W2D, DD, DD);
    split_w<<<dim3(32, 32), tp32>>>(wo_s, WT2 + 3 * W2D, DD, DD);
    gemm_mma<<<gD, blk, GEMM_SMEM>>>(A2, WT2 + 0 * W2D, bq_s, Q, NO3, DD, 1024, 0);
    gemm_mma<<<gD, blk, GEMM_SMEM>>>(A2, WT2 + 1 * W2D, bk_s, K, NO3, DD, 1024, 0);
    gemm_mma<<<gD, blk, GEMM_SMEM>>>(A2, WT2 + 2 * W2D, bv_s, V, NO3, DD, 1024, 0);
    vt_split<<<vtG, tp32>>>(V, VT3);
    attn_scores_mma<<<scoreG, blk, SCORES_SMEM>>>(Q, K, self_w, 1);
    attn_av_mma<<<avG, blk, AV_SMEM>>>(self_w, VT3, src_mask, A2, 1);
    gemm_mma<<<gD, blk, GEMM_SMEM>>>(A2, WT2 + 3 * W2D, bo_s, T1, NO3, DD, 1024, 0);
    add_ln<<<lnG, blk>>>(x, T1, g1, be1, X1, A2);

    // ---- remaining weight splits ----
    split_w<<<dim3(32, 32), tp32>>>(wq_c, WT2 + 4 * W2D, DD, DD);
    split_w<<<dim3(32, 32), tp32>>>(wk_c, WT2 + 5 * W2D, DD, DD);
    split_w<<<dim3(32, 32), tp32>>>(wv_c, WT2 + 6 * W2D, DD, DD);
    split_w<<<dim3(32, 32), tp32>>>(wo_c, WT2 + 7 * W2D, DD, DD);
    split_w<<<dim3(128, 32), tp32>>>(w1, WT2 + W1OFF, DD, DFFN);
    split_w<<<dim3(32, 128), tp32>>>(w2, WT2 + W2OFF, DFFN, DD);

    // ---- cross attention ----
    gemm_mma<<<gD, blk, GEMM_SMEM>>>(A2, WT2 + 4 * W2D, bq_c, Q, NO3, DD, 1024, 0);
    split_act<<<ACT_BLKS, blk>>>(enc, A2);
    gemm_mma<<<gD, blk, GEMM_SMEM>>>(A2, WT2 + 5 * W2D, bk_c, K, NO3, DD, 1024, 0);
    gemm_mma<<<gD, blk, GEMM_SMEM>>>(A2, WT2 + 6 * W2D, bv_c, V, NO3, DD, 1024, 0);
    vt_split<<<vtG, tp32>>>(V, VT3);
    attn_scores_mma<<<scoreG, blk, SCORES_SMEM>>>(Q, K, cross_w, 0);
    attn_av_mma<<<avG, blk, AV_SMEM>>>(cross_w, VT3, src_mask, A2, 0);
    gemm_mma<<<gD, blk, GEMM_SMEM>>>(A2, WT2 + 7 * W2D, bo_c, T1, NO3, DD, 1024, 0);
    add_ln<<<lnG, blk>>>(X1, T1, g2, be2, X2, A2);

    // ---- feed-forward ----
    gemm_mma<<<gF, blk, GEMM_SMEM>>>(A2, WT2 + W1OFF, b1, NC, FF2, DFFN, 1024, 1);
    gemm_mma<<<gD, blk, GEMM_SMEM>>>(FF2, WT2 + W2OFF, b2, T1, NO3, DD, 4096, 0);
    add_ln<<<lnG, blk>>>(X2, T1, g3, be3, out, NO3);

    (void)in_sizes; (void)n_in; (void)out_size;
}

// round 11
// speedup vs baseline: 1.2241x; 1.0260x over previous
#include <cuda_runtime.h>
#include <cuda_bf16.h>
#include <math.h>
#include <stdint.h>

#define BB 4
#define TT 1024
#define SS 1024
#define DD 1024
#define HH 16
#define DKD 64
#define DFFN 4096
#define LN_EPS 1e-6f

// ===================== scratch (no allocations) =====================
__device__ float g_q [BB*TT*DD];
__device__ float g_k [BB*TT*DD];
__device__ float g_v [BB*TT*DD];
__device__ float g_t1[BB*TT*DD];
__device__ float g_x1[BB*TT*DD];
__device__ float g_x2[BB*TT*DD];

__device__ __nv_bfloat16 g_a2 [4096ULL * 2048];   // activations [M,2K] (hi|lo)
__device__ __nv_bfloat16 g_ff2[4096ULL * 8192];   // FF activations (hi|lo)
__device__ __nv_bfloat16 g_vt2[4096ULL * 2048];   // V^T split per (b,h): [64 d][hi|lo seq]
#define W2D (1024ULL*2048)
#define W1OFF (8*W2D)
#define W2OFF (8*W2D + 4096ULL*2048)
__device__ __nv_bfloat16 g_wt2[8*W2D + 4096ULL*2048 + 1024ULL*8192];

// ===================== helpers =====================
__device__ __forceinline__ uint32_t pack_hi2(float x, float y) {
    __nv_bfloat16 a = __float2bfloat16(x), b = __float2bfloat16(y);
    return (uint32_t)__bfloat16_as_ushort(a) | ((uint32_t)__bfloat16_as_ushort(b) << 16);
}
__device__ __forceinline__ uint32_t pack_lo2(float x, float y) {
    __nv_bfloat16 a = __float2bfloat16(x), b = __float2bfloat16(y);
    __nv_bfloat16 ra = __float2bfloat16(x - __bfloat162float(a));
    __nv_bfloat16 rb = __float2bfloat16(y - __bfloat162float(b));
    return (uint32_t)__bfloat16_as_ushort(ra) | ((uint32_t)__bfloat16_as_ushort(rb) << 16);
}
__device__ __forceinline__ void mma_bf16(
    float* d, const uint32_t* a, const uint32_t* b)
{
    asm volatile(
        "mma.sync.aligned.m16n8k16.row.col.f32.bf16.bf16.f32 "
        "{%0,%1,%2,%3}, {%4,%5,%6,%7}, {%8,%9}, {%0,%1,%2,%3};"
        : "+f"(d[0]), "+f"(d[1]), "+f"(d[2]), "+f"(d[3])
        : "r"(a[0]), "r"(a[1]), "r"(a[2]), "r"(a[3]), "r"(b[0]), "r"(b[1]));
}
__device__ __forceinline__ uint32_t smem_u32(const void* p) {
    uint32_t a;
    asm("{ .reg .u64 t; cvta.to.shared.u64 t, %1; cvt.u32.u64 %0, t; }" : "=r"(a) : "l"(p));
    return a;
}
__device__ __forceinline__ void cp16(uint32_t s, const void* g) {
    asm volatile("cp.async.cg.shared.global [%0], [%1], 16;" :: "r"(s), "l"(g));
}
#define CP_COMMIT() asm volatile("cp.async.commit_group;" ::: "memory")
#define CP_WAIT1()  asm volatile("cp.async.wait_group 1;" ::: "memory")
__device__ __forceinline__ void ldm4(uint32_t& r0, uint32_t& r1, uint32_t& r2, uint32_t& r3, uint32_t a) {
    asm volatile("ldmatrix.sync.aligned.m8n8.x4.shared.b16 {%0,%1,%2,%3}, [%4];"
        : "=r"(r0), "=r"(r1), "=r"(r2), "=r"(r3) : "r"(a));
}

// ===================== split/convert kernels =====================
__global__ __launch_bounds__(256) void split_act(
    const float* __restrict__ A, __nv_bfloat16* __restrict__ O)
{
    const int K = 1024;
    size_t idx = (size_t)blockIdx.x * 256 + threadIdx.x;
    size_t base = idx << 2;
    size_t m = base >> 10;
    int k = (int)(base & (size_t)(K - 1));
    float4 v = *(const float4*)(A + base);
    uint2 hh, ll;
    hh.x = pack_hi2(v.x, v.y); hh.y = pack_hi2(v.z, v.w);
    ll.x = pack_lo2(v.x, v.y); ll.y = pack_lo2(v.z, v.w);
    __nv_bfloat16* row = O + m * (size_t)(2 * K);
    *(uint2*)(row + k)     = hh;
    *(uint2*)(row + K + k) = ll;
}

__global__ void split_w(
    const float* __restrict__ W, __nv_bfloat16* __restrict__ O, int K, int N)
{
    __shared__ float t[32][33];
    int k = blockIdx.y * 32 + threadIdx.y;
    int n = blockIdx.x * 32 + threadIdx.x;
    t[threadIdx.y][threadIdx.x] = W[(size_t)k * N + n];
    __syncthreads();
    int nn = blockIdx.x * 32 + threadIdx.y;
    int kk = blockIdx.y * 32 + threadIdx.x;
    float v = t[threadIdx.x][threadIdx.y];
    __nv_bfloat16 h = __float2bfloat16(v);
    __nv_bfloat16 l = __float2bfloat16(v - __bfloat162float(h));
    size_t ro = (size_t)nn * (size_t)(2 * K);
    O[ro + kk]     = h;
    O[ro + K + kk] = l;
}

__global__ void vt_split(
    const float* __restrict__ V, __nv_bfloat16* __restrict__ VT2)
{
    __shared__ float t[32][33];
    const int b = blockIdx.z;
    int k = blockIdx.x * 32 + threadIdx.y;
    int d = blockIdx.y * 32 + threadIdx.x;
    t[threadIdx.y][threadIdx.x] = V[((size_t)(b * TT + k)) * DD + d];
    __syncthreads();
    int dg = blockIdx.y * 32 + threadIdx.y;
    int kg = blockIdx.x * 32 + threadIdx.x;
    float v = t[threadIdx.x][threadIdx.y];
    __nv_bfloat16 h = __float2bfloat16(v);
    __nv_bfloat16 l = __float2bfloat16(v - __bfloat162float(h));
    int hh = dg >> 6, dk = dg & 63;
    size_t row = ((size_t)(b * HH + hh) * 64 + dk) * 2048;
    VT2[row + kg]        = h;
    VT2[row + 1024 + kg] = l;
}

// ===================== HMMA GEMM, 2-segment operands, 3 products in-smem ====
#define PADK2 72
#define TSTG (128 * PADK2 * 2)
#define SSTG (2 * TSTG)
#define STAGES2 3
#define GEMM_SMEM (STAGES2 * SSTG)

__global__ __launch_bounds__(256) void gemm_mma(
    const __nv_bfloat16* __restrict__ A2, const __nv_bfloat16* __restrict__ W2,
    const float* __restrict__ bias, float* __restrict__ C,
    __nv_bfloat16* __restrict__ O3, int N, int Kl, int relu)
{
    extern __shared__ char dsm[];
    const uint32_t sb = smem_u32(dsm);
    const int tid = threadIdx.x;
    const int lane = tid & 31, wid = tid >> 5;
    const int wm = wid >> 2, wn = wid & 3;
    const int grp = lane >> 2, tg = lane & 3;

    const size_t arow0 = (size_t)blockIdx.y * 128;
    const size_t bcol0 = (size_t)blockIdx.x * 128;
    const size_t rstr = (size_t)2 * Kl;

    const uint32_t aLM = (uint32_t)(((wm * 64) + (lane & 15)) * PADK2 + (lane >> 4) * 8) * 2;
    const uint32_t bLM = (uint32_t)(((wn * 32) + (lane & 15)) * PADK2 + (lane >> 4) * 8) * 2;

    float acc[4][4][4];
    #pragma unroll
    for (int i = 0; i < 4; i++)
        #pragma unroll
        for (int j = 0; j < 4; j++)
            #pragma unroll
            for (int q = 0; q < 4; q++) acc[i][j][q] = 0.f;

    const int NC = Kl >> 5;

    auto issue = [&](int c, int st) {
        const uint32_t ab = sb + st * SSTG;
        const uint32_t bb = ab + TSTG;
        #pragma unroll
        for (int i = 0; i < 4; i++) {
            int idx = tid + i * 256;
            int r = idx >> 3, s = idx & 7;
            size_t go = (s < 4) ? ((size_t)c * 32 + s * 8)
                                : ((size_t)Kl + c * 32 + (s - 4) * 8);
            uint32_t so = (uint32_t)(r * PADK2 + s * 8) * 2;
            cp16(ab + so, A2 + (arow0 + r) * rstr + go);
            cp16(bb + so, W2 + (bcol0 + r) * rstr + go);
        }
        CP_COMMIT();
    };

    issue(0, 0); issue(1, 1);

    int st = 0;
    for (int c = 0; c < NC; c++) {
        CP_WAIT1();
        __syncthreads();
        if (c + 2 < NC) {
            int ns = st + 2; if (ns >= 3) ns -= 3;
            issue(c + 2, ns);
        } else CP_COMMIT();

        const uint32_t As0 = sb + st * SSTG;
        const uint32_t Bs0 = As0 + TSTG;
        #pragma unroll
        for (int ks = 0; ks < 2; ks++) {
            const uint32_t ko = ks * 32;
            uint32_t ah[4][4], al[4][4], b2[4][2];
            #pragma unroll
            for (int ms = 0; ms < 4; ms++)
                ldm4(ah[ms][0], ah[ms][1], ah[ms][2], ah[ms][3],
                     As0 + aLM + ms * (16 * PADK2 * 2) + ko);
            ldm4(b2[0][0], b2[1][0], b2[0][1], b2[1][1], Bs0 + bLM + ko);
            ldm4(b2[2][0], b2[3][0], b2[2][1], b2[3][1], Bs0 + bLM + 16 * PADK2 * 2 + ko);
            #pragma unroll
            for (int ms = 0; ms < 4; ms++)
                #pragma unroll
                for (int ns = 0; ns < 4; ns++)
                    mma_bf16(acc[ms][ns], ah[ms], b2[ns]);
            #pragma unroll
            for (int ms = 0; ms < 4; ms++)
                ldm4(al[ms][0], al[ms][1], al[ms][2], al[ms][3],
                     As0 + aLM + ms * (16 * PADK2 * 2) + ko + 64);
            #pragma unroll
            for (int ms = 0; ms < 4; ms++)
                #pragma unroll
                for (int ns = 0; ns < 4; ns++)
                    mma_bf16(acc[ms][ns], al[ms], b2[ns]);
            ldm4(b2[0][0], b2[1][0], b2[0][1], b2[1][1], Bs0 + bLM + ko + 64);
            ldm4(b2[2][0], b2[3][0], b2[2][1], b2[3][1], Bs0 + bLM + 16 * PADK2 * 2 + ko + 64);
            #pragma unroll
            for (int ms = 0; ms < 4; ms++)
                #pragma unroll
                for (int ns = 0; ns < 4; ns++)
                    mma_bf16(acc[ms][ns], ah[ms], b2[ns]);
        }
        if (++st >= 3) st = 0;
    }

    if (O3) {
        const size_t ostr = (size_t)2 * N;
        #pragma unroll
        for (int ms = 0; ms < 4; ms++) {
            const size_t rr0 = arow0 + wm * 64 + ms * 16 + grp;
            #pragma unroll
            for (int ns = 0; ns < 4; ns++) {
                const size_t cc = bcol0 + wn * 32 + ns * 8 + tg * 2;
                float bx = bias[cc], by = bias[cc + 1];
                float v0 = fmaxf(acc[ms][ns][0] + bx, 0.f);
                float v1 = fmaxf(acc[ms][ns][1] + by, 0.f);
                float v2 = fmaxf(acc[ms][ns][2] + bx, 0.f);
                float v3 = fmaxf(acc[ms][ns][3] + by, 0.f);
                __nv_bfloat16* R0 = O3 + rr0 * ostr;
                __nv_bfloat16* R1 = O3 + (rr0 + 8) * ostr;
                *(uint32_t*)(R0 + cc)     = pack_hi2(v0, v1);
                *(uint32_t*)(R0 + N + cc) = pack_lo2(v0, v1);
                *(uint32_t*)(R1 + cc)     = pack_hi2(v2, v3);
                *(uint32_t*)(R1 + N + cc) = pack_lo2(v2, v3);
            }
        }
    } else {
        #pragma unroll
        for (int ms = 0; ms < 4; ms++) {
            const size_t rr0 = arow0 + wm * 64 + ms * 16 + grp;
            #pragma unroll
            for (int ns = 0; ns < 4; ns++) {
                const size_t cc = bcol0 + wn * 32 + ns * 8 + tg * 2;
                float bx = bias[cc], by = bias[cc + 1];
                float v0 = acc[ms][ns][0] + bx;
                float v1 = acc[ms][ns][1] + by;
                float v2 = acc[ms][ns][2] + bx;
                float v3 = acc[ms][ns][3] + by;
                if (relu) {
                    v0 = fmaxf(v0, 0.f); v1 = fmaxf(v1, 0.f);
                    v2 = fmaxf(v2, 0.f); v3 = fmaxf(v3, 0.f);
                }
                *(float2*)(C + rr0 * N + cc)       = make_float2(v0, v1);
                *(float2*)(C + (rr0 + 8) * N + cc) = make_float2(v2, v3);
            }
        }
    }
}

// ===================== attention scores (2-seg smem, 3 products) ======
#define SPAD2 136
#define SCORES_SMEM ((128 + 64) * SPAD2 * 2)
__global__ __launch_bounds__(256) void attn_scores_mma(
    const float* __restrict__ Q, const float* __restrict__ Kv,
    float* __restrict__ Sc, int causal)
{
    extern __shared__ __nv_bfloat16 sm[];
    __nv_bfloat16* As = sm;                 // [128][SPAD2]  Q: [hi|lo]
    __nv_bfloat16* Bs = sm + 128 * SPAD2;   // [64][SPAD2]   K: [hi|lo]
    const int z = blockIdx.z, b = z >> 4, h = z & 15;
    const int q0 = blockIdx.y * 128;
    const int kbase = blockIdx.x * 256;
    if (causal && kbase >= q0 + 128) return;

    const int tid = threadIdx.x, lane = tid & 31, wid = tid >> 5;
    const int wm = wid >> 1, wn = wid & 1;
    const int grp = lane >> 2, tg = lane & 3;

    const float* Qb = Q + ((size_t)(b * TT + q0)) * DD + h * DKD;

    #pragma unroll
    for (int i = 0; i < 8; i++) {
        int f = tid + i * 256;
        int r = f >> 4, c = (f & 15) << 2;
        float4 v = *(const float4*)(Qb + (size_t)r * DD + c);
        uint2 hh, ll;
        hh.x = pack_hi2(v.x, v.y); hh.y = pack_hi2(v.z, v.w);
        ll.x = pack_lo2(v.x, v.y); ll.y = pack_lo2(v.z, v.w);
        __nv_bfloat16* R = As + r * SPAD2;
        *(uint2*)(R + c)      = hh;
        *(uint2*)(R + 64 + c) = ll;
    }

    const uint32_t AsU = smem_u32(As), BsU = smem_u32(Bs);
    const uint32_t aLM = AsU + (uint32_t)(((wm * 32) + (lane & 15)) * SPAD2 + (lane >> 4) * 8) * 2;
    const uint32_t bLM = BsU + (uint32_t)(((wn * 32) + (lane & 15)) * SPAD2 + (lane >> 4) * 8) * 2;

    for (int kt = 0; kt < 4; kt++) {
        const int k0 = kbase + kt * 64;
        if (causal && k0 >= q0 + 128) break;

        __syncthreads();
        const float* Kb = Kv + ((size_t)(b * TT + k0)) * DD + h * DKD;
        #pragma unroll
        for (int i = 0; i < 4; i++) {
            int f = tid + i * 256;
            int r = f >> 4, c = (f & 15) << 2;
            float4 v = *(const float4*)(Kb + (size_t)r * DD + c);
            uint2 hh, ll;
            hh.x = pack_hi2(v.x, v.y); hh.y = pack_hi2(v.z, v.w);
            ll.x = pack_lo2(v.x, v.y); ll.y = pack_lo2(v.z, v.w);
            __nv_bfloat16* R = Bs + r * SPAD2;
            *(uint2*)(R + c)      = hh;
            *(uint2*)(R + 64 + c) = ll;
        }
        __syncthreads();

        float acc[2][4][4];
        #pragma unroll
        for (int i = 0; i < 2; i++)
            #pragma unroll
            for (int j = 0; j < 4; j++)
                #pragma unroll
                for (int q = 0; q < 4; q++) acc[i][j][q] = 0.f;

        #pragma unroll
        for (int ks = 0; ks < 4; ks++) {
            const uint32_t ko = ks * 32;
            uint32_t ah[2][4], al[2][4], bb[4][2];
            #pragma unroll
            for (int mi = 0; mi < 2; mi++)
                ldm4(ah[mi][0], ah[mi][1], ah[mi][2], ah[mi][3],
                     aLM + mi * (16 * SPAD2 * 2) + ko);
            ldm4(bb[0][0], bb[1][0], bb[0][1], bb[1][1], bLM + ko);
            ldm4(bb[2][0], bb[3][0], bb[2][1], bb[3][1], bLM + 16 * SPAD2 * 2 + ko);
            #pragma unroll
            for (int mi = 0; mi < 2; mi++)
                #pragma unroll
                for (int ni = 0; ni < 4; ni++)
                    mma_bf16(acc[mi][ni], ah[mi], bb[ni]);
            #pragma unroll
            for (int mi = 0; mi < 2; mi++)
                ldm4(al[mi][0], al[mi][1], al[mi][2], al[mi][3],
                     aLM + mi * (16 * SPAD2 * 2) + ko + 128);
            #pragma unroll
            for (int mi = 0; mi < 2; mi++)
                #pragma unroll
                for (int ni = 0; ni < 4; ni++)
                    mma_bf16(acc[mi][ni], al[mi], bb[ni]);
            ldm4(bb[0][0], bb[1][0], bb[0][1], bb[1][1], bLM + ko + 128);
            ldm4(bb[2][0], bb[3][0], bb[2][1], bb[3][1], bLM + 16 * SPAD2 * 2 + ko + 128);
            #pragma unroll
            for (int mi = 0; mi < 2; mi++)
                #pragma unroll
                for (int ni = 0; ni < 4; ni++)
                    mma_bf16(acc[mi][ni], ah[mi], bb[ni]);
        }

        float* Out = Sc + ((size_t)z * TT + q0) * TT + k0;
        #pragma unroll
        for (int mi = 0; mi < 2; mi++) {
            const size_t r = wm * 32 + mi * 16 + grp;
            #pragma unroll
            for (int ni = 0; ni < 4; ni++) {
                const size_t c = wn * 32 + ni * 8 + tg * 2;
                *(float2*)(Out + r * TT + c) =
                    make_float2(acc[mi][ni][0] * 0.125f, acc[mi][ni][1] * 0.125f);
                *(float2*)(Out + (r + 8) * TT + c) =
                    make_float2(acc[mi][ni][2] * 0.125f, acc[mi][ni][3] * 0.125f);
            }
        }
    }
}

// ===================== attn @ V with fused softmax (2-seg smem) =============
#define AV_SMEM ((64 + 64) * SPAD2 * 2 + 512)
__global__ __launch_bounds__(256) void attn_av_mma(
    float* __restrict__ Sc, const __nv_bfloat16* __restrict__ VT2,
    const int* __restrict__ mask, __nv_bfloat16* __restrict__ A2out, int causal)
{
    extern __shared__ __nv_bfloat16 sm[];
    __nv_bfloat16* As = sm;                // [64][SPAD2]  P: [hi|lo]
    __nv_bfloat16* Bs = sm + 64 * SPAD2;   // [64][SPAD2]  V^T: [hi|lo]
    float* stats = (float*)(sm + (64 + 64) * SPAD2);
    const int z = blockIdx.y, b = z >> 4, h = z & 15;
    const int q0 = blockIdx.x * 64;

    const int tid = threadIdx.x, lane = tid & 31, wid = tid >> 5;
    const int wm = wid >> 1, wn = wid & 1;
    const int grp = lane >> 2, tg = lane & 3;

    const int kend = causal ? (q0 + 64) : TT;

    // ---- pass 1: per-row online max / exp-sum ----
    {
        const int rloc = wid * 8 + (lane >> 2);
        const int qd = lane & 3;
        const int qabs = q0 + rloc;
        const float* Srow = Sc + ((size_t)z * TT + qabs) * TT;
        float m = -3.0e38f, s = 0.f;
        for (int j = 0; j < (kend >> 4); j++) {
            int k = qd * 4 + j * 16;
            float4 v4 = *(const float4*)(Srow + k);
            float v0, v1, v2, v3;
            if (causal) {
                v0 = (k     <= qabs) ? v4.x : -1e9f;
                v1 = (k + 1 <= qabs) ? v4.y : -1e9f;
                v2 = (k + 2 <= qabs) ? v4.z : -1e9f;
                v3 = (k + 3 <= qabs) ? v4.w : -1e9f;
            } else {
                int4 mk = *(const int4*)(mask + b * SS + k);
                v0 = mk.x ? v4.x : -1e9f;
                v1 = mk.y ? v4.y : -1e9f;
                v2 = mk.z ? v4.z : -1e9f;
                v3 = mk.w ? v4.w : -1e9f;
            }
            float tm = fmaxf(fmaxf(v0, v1), fmaxf(v2, v3));
            float nm = fmaxf(m, tm);
            s = s * __expf(m - nm)
              + __expf(v0 - nm) + __expf(v1 - nm)
              + __expf(v2 - nm) + __expf(v3 - nm);
            m = nm;
        }
        #pragma unroll
        for (int o = 1; o <= 2; o <<= 1) {
            float mo = __shfl_xor_sync(0xffffffffu, m, o);
            float so = __shfl_xor_sync(0xffffffffu, s, o);
            float nm = fmaxf(m, mo);
            s = s * __expf(m - nm) + so * __expf(mo - nm);
            m = nm;
        }
        if (qd == 0) { stats[rloc] = m; stats[64 + rloc] = 1.0f / s; }
    }
    __syncthreads();

    const __nv_bfloat16* Vt = VT2 + (size_t)z * 64 * 2048;
    const uint32_t AsU = smem_u32(As), BsU = smem_u32(Bs);
    const uint32_t aLM = AsU + (uint32_t)(((wm * 16) + (lane & 15)) * SPAD2 + (lane >> 4) * 8) * 2;
    const uint32_t bLM = BsU + (uint32_t)(((wn * 32) + (lane & 15)) * SPAD2 + (lane >> 4) * 8) * 2;

    float acc[4][4];
    #pragma unroll
    for (int i = 0; i < 4; i++)
        #pragma unroll
        for (int j = 0; j < 4; j++) acc[i][j] = 0.f;

    for (int k0 = 0; k0 < kend; k0 += 64) {
        float* Pb = Sc + ((size_t)z * TT + q0) * TT + k0;
        #pragma unroll
        for (int i = 0; i < 4; i++) {
            int f = tid + i * 256;
            int r = f >> 4, c = (f & 15) << 2;
            float4 pv = *(float4*)(Pb + (size_t)r * TT + c);
            const int qabs = q0 + r;
            const int kg = k0 + c;
            float v0, v1, v2, v3;
            if (causal) {
                v0 = (kg     <= qabs) ? pv.x : -1e9f;
                v1 = (kg + 1 <= qabs) ? pv.y : -1e9f;
                v2 = (kg + 2 <= qabs) ? pv.z : -1e9f;
                v3 = (kg + 3 <= qabs) ? pv.w : -1e9f;
            } else {
                int4 mk = *(const int4*)(mask + b * SS + kg);
                v0 = mk.x ? pv.x : -1e9f;
                v1 = mk.y ? pv.y : -1e9f;
                v2 = mk.z ? pv.z : -1e9f;
                v3 = mk.w ? pv.w : -1e9f;
            }
            const float mm = stats[r], iv = stats[64 + r];
            float p0 = __expf(v0 - mm) * iv;
            float p1 = __expf(v1 - mm) * iv;
            float p2 = __expf(v2 - mm) * iv;
            float p3 = __expf(v3 - mm) * iv;
            *(float4*)(Pb + (size_t)r * TT + c) = make_float4(p0, p1, p2, p3);
            uint2 hh, ll;
            hh.x = pack_hi2(p0, p1); hh.y = pack_hi2(p2, p3);
            ll.x = pack_lo2(p0, p1); ll.y = pack_lo2(p2, p3);
            __nv_bfloat16* R = As + r * SPAD2;
            *(uint2*)(R + c)      = hh;
            *(uint2*)(R + 64 + c) = ll;
        }
        #pragma unroll
        for (int i = 0; i < 4; i++) {
            int idx = tid + i * 256;
            int d = idx >> 4, rem = idx & 15;
            int band = rem >> 3, j = rem & 7;
            uint4 v = *(const uint4*)(Vt + (size_t)d * 2048 + band * 1024 + k0 + j * 8);
            *(uint4*)(Bs + d * SPAD2 + band * 64 + j * 8) = v;
        }
        __syncthreads();
        #pragma unroll
        for (int ks = 0; ks < 4; ks++) {
            const uint32_t ko = ks * 32;
            uint32_t ah[4], al[4], bb[4][2];
            ldm4(ah[0], ah[1], ah[2], ah[3], aLM + ko);
            ldm4(bb[0][0], bb[1][0], bb[0][1], bb[1][1], bLM + ko);
            ldm4(bb[2][0], bb[3][0], bb[2][1], bb[3][1], bLM + 16 * SPAD2 * 2 + ko);
            #pragma unroll
            for (int ni = 0; ni < 4; ni++)
                mma_bf16(acc[ni], ah, bb[ni]);
            ldm4(al[0], al[1], al[2], al[3], aLM + ko + 128);
            #pragma unroll
            for (int ni = 0; ni < 4; ni++)
                mma_bf16(acc[ni], al, bb[ni]);
            ldm4(bb[0][0], bb[1][0], bb[0][1], bb[1][1], bLM + ko + 128);
            ldm4(bb[2][0], bb[3][0], bb[2][1], bb[3][1], bLM + 16 * SPAD2 * 2 + ko + 128);
            #pragma unroll
            for (int ni = 0; ni < 4; ni++)
                mma_bf16(acc[ni], ah, bb[ni]);
        }
        __syncthreads();
    }

    if (causal && kend < TT) {
        const int Z = TT - kend;
        const int zw = Z >> 2;
        const int n4 = 64 * zw;
        const float4 z4 = make_float4(0.f, 0.f, 0.f, 0.f);
        for (int i = tid; i < n4; i += 256) {
            int r = i / zw, c = kend + (i - r * zw) * 4;
            *(float4*)(Sc + ((size_t)z * TT + q0 + r) * TT + c) = z4;
        }
    }

    const size_t m0 = (size_t)b * TT + q0 + wm * 16 + grp;
    const size_t m1 = m0 + 8;
    __nv_bfloat16* R0 = A2out + m0 * 2048;
    __nv_bfloat16* R1 = A2out + m1 * 2048;
    #pragma unroll
    for (int ni = 0; ni < 4; ni++) {
        const int cc = h * DKD + wn * 32 + ni * 8 + tg * 2;
        float v0 = acc[ni][0], v1 = acc[ni][1];
        float v2 = acc[ni][2], v3 = acc[ni][3];
        *(uint32_t*)(R0 + cc)        = pack_hi2(v0, v1);
        *(uint32_t*)(R0 + 1024 + cc) = pack_lo2(v0, v1);
        *(uint32_t*)(R1 + cc)        = pack_hi2(v2, v3);
        *(uint32_t*)(R1 + 1024 + cc) = pack_lo2(v2, v3);
    }
}

// ===================== residual add + LayerNorm =====================
__global__ __launch_bounds__(256) void add_ln(
    const float* __restrict__ X, const float* __restrict__ Dl,
    const float* __restrict__ g, const float* __restrict__ be,
    float* __restrict__ O, __nv_bfloat16* __restrict__ S2)
{
    const int row = blockIdx.x;
    const float* x  = X  + (size_t)row * DD;
    const float* dl = Dl + (size_t)row * DD;
    const int tid = threadIdx.x;

    float v[4];
    float s = 0.f;
    #pragma unroll
    for (int i = 0; i < 4; i++) {
        int c = tid + i * 256;
        v[i] = x[c] + dl[c];
        s += v[i];
    }
    __shared__ float red[8];
    #pragma unroll
    for (int o = 16; o > 0; o >>= 1) s += __shfl_xor_sync(0xffffffffu, s, o);
    if ((tid & 31) == 0) red[tid >> 5] = s;
    __syncthreads();
    s = 0.f;
    #pragma unroll
    for (int w = 0; w < 8; w++) s += red[w];
    float mean = s * (1.0f / 1024.0f);

    float qq = 0.f;
    #pragma unroll
    for (int i = 0; i < 4; i++) { float d = v[i] - mean; qq += d * d; }
    __syncthreads();
    #pragma unroll
    for (int o = 16; o > 0; o >>= 1) qq += __shfl_xor_sync(0xffffffffu, qq, o);
    if ((tid & 31) == 0) red[tid >> 5] = qq;
    __syncthreads();
    qq = 0.f;
    #pragma unroll
    for (int w = 0; w < 8; w++) qq += red[w];

    float stdv = sqrtf(qq * (1.0f / 1023.0f));
    float inv = 1.0f / (stdv + LN_EPS);
    __nv_bfloat16* R = S2 ? (S2 + (size_t)row * 2048) : (__nv_bfloat16*)0;
    #pragma unroll
    for (int i = 0; i < 4; i++) {
        int c = tid + i * 256;
        float o = g[c] * (v[i] - mean) * inv + be[c];
        O[(size_t)row * DD + c] = o;
        if (R) {
            __nv_bfloat16 h = __float2bfloat16(o);
            __nv_bfloat16 l = __float2bfloat16(o - __bfloat162float(h));
            R[c]        = h;
            R[1024 + c] = l;
        }
    }
}

// ===================== orchestration =====================
extern "C" void kernel_launch(void* const* d_in, const int* in_sizes, int n_in,
                              void* d_out, int out_size)
{
    const float* x        = (const float*)d_in[0];
    const float* enc      = (const float*)d_in[1];
    const int*   src_mask = (const int*)  d_in[2];
    const float* wq_s = (const float*)d_in[4],  *bq_s = (const float*)d_in[5];
    const float* wk_s = (const float*)d_in[6],  *bk_s = (const float*)d_in[7];
    const float* wv_s = (const float*)d_in[8],  *bv_s = (const float*)d_in[9];
    const float* wo_s = (const float*)d_in[10], *bo_s = (const float*)d_in[11];
    const float* wq_c = (const float*)d_in[12], *bq_c = (const float*)d_in[13];
    const float* wk_c = (const float*)d_in[14], *bk_c = (const float*)d_in[15];
    const float* wv_c = (const float*)d_in[16], *bv_c = (const float*)d_in[17];
    const float* wo_c = (const float*)d_in[18], *bo_c = (const float*)d_in[19];
    const float* w1   = (const float*)d_in[20], *b1   = (const float*)d_in[21];
    const float* w2   = (const float*)d_in[22], *b2   = (const float*)d_in[23];
    const float* g1   = (const float*)d_in[24], *be1  = (const float*)d_in[25];
    const float* g2   = (const float*)d_in[26], *be2  = (const float*)d_in[27];
    const float* g3   = (const float*)d_in[28], *be3  = (const float*)d_in[29];

    float* out     = (float*)d_out;
    float* self_w  = out + (size_t)BB * TT * DD;
    float* cross_w = self_w + (size_t)BB * HH * TT * TT;

    float *Q, *K, *V, *T1, *X1, *X2;
    __nv_bfloat16 *A2, *FF2, *WT2, *VT2;
    cudaGetSymbolAddress((void**)&Q,   g_q);
    cudaGetSymbolAddress((void**)&K,   g_k);
    cudaGetSymbolAddress((void**)&V,   g_v);
    cudaGetSymbolAddress((void**)&T1,  g_t1);
    cudaGetSymbolAddress((void**)&X1,  g_x1);
    cudaGetSymbolAddress((void**)&X2,  g_x2);
    cudaGetSymbolAddress((void**)&A2,  g_a2);
    cudaGetSymbolAddress((void**)&FF2, g_ff2);
    cudaGetSymbolAddress((void**)&WT2, g_wt2);
    cudaGetSymbolAddress((void**)&VT2, g_vt2);

    cudaFuncSetAttribute(gemm_mma,        cudaFuncAttributeMaxDynamicSharedMemorySize, GEMM_SMEM);
    cudaFuncSetAttribute(attn_scores_mma, cudaFuncAttributeMaxDynamicSharedMemorySize, SCORES_SMEM);
    cudaFuncSetAttribute(attn_av_mma,     cudaFuncAttributeMaxDynamicSharedMemorySize, AV_SMEM);

    const int M = BB * TT;
    dim3 blk(256);
    dim3 tp32(32, 32);
    dim3 gD(DD / 128, M / 128);
    dim3 gF(DFFN / 128, M / 128);
    dim3 scoreG(TT / 256, TT / 128, BB * HH);
    dim3 avG(TT / 64, BB * HH);
    dim3 vtG(TT / 32, DD / 32, BB);
    dim3 lnG(M);
    const int ACT_BLKS = M * DD / 4 / 256;
    float* NC = (float*)0;
    __nv_bfloat16* NO3 = (__nv_bfloat16*)0;

    // ---- self attention ----
    split_act<<<ACT_BLKS, blk>>>(x, A2);
    split_w<<<dim3(32, 32), tp32>>>(wq_s, WT2 + 0 * W2D, DD, DD);
    split_w<<<dim3(32, 32), tp32>>>(wk_s, WT2 + 1 * W2D, DD, DD);
    split_w<<<dim3(32, 32), tp32>>>(wv_s, WT2 + 2 * W2D, DD, DD);
    split_w<<<dim3(32, 32), tp32>>>(wo_s, WT2 + 3 * W2D, DD, DD);
    gemm_mma<<<gD, blk, GEMM_SMEM>>>(A2, WT2 + 0 * W2D, bq_s, Q, NO3, DD, 1024, 0);
    gemm_mma<<<gD, blk, GEMM_SMEM>>>(A2, WT2 + 1 * W2D, bk_s, K, NO3, DD, 1024, 0);
    gemm_mma<<<gD, blk, GEMM_SMEM>>>(A2, WT2 + 2 * W2D, bv_s, V, NO3, DD, 1024, 0);
    vt_split<<<vtG, tp32>>>(V, VT2);
    attn_scores_mma<<<scoreG, blk, SCORES_SMEM>>>(Q, K, self_w, 1);
    attn_av_mma<<<avG, blk, AV_SMEM>>>(self_w, VT2, src_mask, A2, 1);
    gemm_mma<<<gD, blk, GEMM_SMEM>>>(A2, WT2 + 3 * W2D, bo_s, T1, NO3, DD, 1024, 0);
    add_ln<<<lnG, blk>>>(x, T1, g1, be1, X1, A2);

    // ---- remaining weight splits ----
    split_w<<<dim3(32, 32), tp32>>>(wq_c, WT2 + 4 * W2D, DD, DD);
    split_w<<<dim3(32, 32), tp32>>>(wk_c, WT2 + 5 * W2D, DD, DD);
    split_w<<<dim3(32, 32), tp32>>>(wv_c, WT2 + 6 * W2D, DD, DD);
    split_w<<<dim3(32, 32), tp32>>>(wo_c, WT2 + 7 * W2D, DD, DD);
    split_w<<<dim3(128, 32), tp32>>>(w1, WT2 + W1OFF, DD, DFFN);
    split_w<<<dim3(32, 128), tp32>>>(w2, WT2 + W2OFF, DFFN, DD);

    // ---- cross attention ----
    gemm_mma<<<gD, blk, GEMM_SMEM>>>(A2, WT2 + 4 * W2D, bq_c, Q, NO3, DD, 1024, 0);
    split_act<<<ACT_BLKS, blk>>>(enc, A2);
    gemm_mma<<<gD, blk, GEMM_SMEM>>>(A2, WT2 + 5 * W2D, bk_c, K, NO3, DD, 1024, 0);
    gemm_mma<<<gD, blk, GEMM_SMEM>>>(A2, WT2 + 6 * W2D, bv_c, V, NO3, DD, 1024, 0);
    vt_split<<<vtG, tp32>>>(V, VT2);
    attn_scores_mma<<<scoreG, blk, SCORES_SMEM>>>(Q, K, cross_w, 0);
    attn_av_mma<<<avG, blk, AV_SMEM>>>(cross_w, VT2, src_mask, A2, 0);
    gemm_mma<<<gD, blk, GEMM_SMEM>>>(A2, WT2 + 7 * W2D, bo_c, T1, NO3, DD, 1024, 0);
    add_ln<<<lnG, blk>>>(X1, T1, g2, be2, X2, A2);

    // ---- feed-forward ----
    gemm_mma<<<gF, blk, GEMM_SMEM>>>(A2, WT2 + W1OFF, b1, NC, FF2, DFFN, 1024, 1);
    gemm_mma<<<gD, blk, GEMM_SMEM>>>(FF2, WT2 + W2OFF, b2, T1, NO3, DD, 4096, 0);
    add_ln<<<lnG, blk>>>(X2, T1, g3, be3, out, NO3);

    (void)in_sizes; (void)n_in; (void)out_size;
}

// round 12
// speedup vs baseline: 1.2407x; 1.0136x over previous
#include <cuda_runtime.h>
#include <cuda_bf16.h>
#include <math.h>
#include <stdint.h>

#define BB 4
#define TT 1024
#define SS 1024
#define DD 1024
#define HH 16
#define DKD 64
#define DFFN 4096
#define LN_EPS 1e-6f

// ===================== scratch (no allocations) =====================
__device__ float g_q [BB*TT*DD];
__device__ float g_k [BB*TT*DD];
__device__ float g_v [BB*TT*DD];
__device__ float g_t1[BB*TT*DD];
__device__ float g_x1[BB*TT*DD];
__device__ float g_x2[BB*TT*DD];
__device__ float g_st[64ULL * 1024 * 2];          // per (z,q): max, inv_sum

__device__ __nv_bfloat16 g_a2 [4096ULL * 2048];   // activations [M,2K] (hi|lo)
__device__ __nv_bfloat16 g_ff2[4096ULL * 8192];   // FF activations (hi|lo)
__device__ __nv_bfloat16 g_vt2[4096ULL * 2048];   // V^T split per (b,h): [64 d][hi|lo seq]
#define W2D (1024ULL*2048)
#define W1OFF (8*W2D)
#define W2OFF (8*W2D + 4096ULL*2048)
__device__ __nv_bfloat16 g_wt2[8*W2D + 4096ULL*2048 + 1024ULL*8192];

// ===================== helpers =====================
__device__ __forceinline__ uint32_t pack_hi2(float x, float y) {
    __nv_bfloat16 a = __float2bfloat16(x), b = __float2bfloat16(y);
    return (uint32_t)__bfloat16_as_ushort(a) | ((uint32_t)__bfloat16_as_ushort(b) << 16);
}
__device__ __forceinline__ uint32_t pack_lo2(float x, float y) {
    __nv_bfloat16 a = __float2bfloat16(x), b = __float2bfloat16(y);
    __nv_bfloat16 ra = __float2bfloat16(x - __bfloat162float(a));
    __nv_bfloat16 rb = __float2bfloat16(y - __bfloat162float(b));
    return (uint32_t)__bfloat16_as_ushort(ra) | ((uint32_t)__bfloat16_as_ushort(rb) << 16);
}
__device__ __forceinline__ void mma_bf16(
    float* d, const uint32_t* a, const uint32_t* b)
{
    asm volatile(
        "mma.sync.aligned.m16n8k16.row.col.f32.bf16.bf16.f32 "
        "{%0,%1,%2,%3}, {%4,%5,%6,%7}, {%8,%9}, {%0,%1,%2,%3};"
        : "+f"(d[0]), "+f"(d[1]), "+f"(d[2]), "+f"(d[3])
        : "r"(a[0]), "r"(a[1]), "r"(a[2]), "r"(a[3]), "r"(b[0]), "r"(b[1]));
}
__device__ __forceinline__ uint32_t smem_u32(const void* p) {
    uint32_t a;
    asm("{ .reg .u64 t; cvta.to.shared.u64 t, %1; cvt.u32.u64 %0, t; }" : "=r"(a) : "l"(p));
    return a;
}
__device__ __forceinline__ void cp16(uint32_t s, const void* g) {
    asm volatile("cp.async.cg.shared.global [%0], [%1], 16;" :: "r"(s), "l"(g));
}
#define CP_COMMIT() asm volatile("cp.async.commit_group;" ::: "memory")
#define CP_WAIT1()  asm volatile("cp.async.wait_group 1;" ::: "memory")
__device__ __forceinline__ void ldm4(uint32_t& r0, uint32_t& r1, uint32_t& r2, uint32_t& r3, uint32_t a) {
    asm volatile("ldmatrix.sync.aligned.m8n8.x4.shared.b16 {%0,%1,%2,%3}, [%4];"
        : "=r"(r0), "=r"(r1), "=r"(r2), "=r"(r3) : "r"(a));
}

// ===================== split/convert kernels =====================
__global__ __launch_bounds__(256) void split_act(
    const float* __restrict__ A, __nv_bfloat16* __restrict__ O)
{
    const int K = 1024;
    size_t idx = (size_t)blockIdx.x * 256 + threadIdx.x;
    size_t base = idx << 2;
    size_t m = base >> 10;
    int k = (int)(base & (size_t)(K - 1));
    float4 v = *(const float4*)(A + base);
    uint2 hh, ll;
    hh.x = pack_hi2(v.x, v.y); hh.y = pack_hi2(v.z, v.w);
    ll.x = pack_lo2(v.x, v.y); ll.y = pack_lo2(v.z, v.w);
    __nv_bfloat16* row = O + m * (size_t)(2 * K);
    *(uint2*)(row + k)     = hh;
    *(uint2*)(row + K + k) = ll;
}

__global__ void split_w(
    const float* __restrict__ W, __nv_bfloat16* __restrict__ O, int K, int N)
{
    __shared__ float t[32][33];
    int k = blockIdx.y * 32 + threadIdx.y;
    int n = blockIdx.x * 32 + threadIdx.x;
    t[threadIdx.y][threadIdx.x] = W[(size_t)k * N + n];
    __syncthreads();
    int nn = blockIdx.x * 32 + threadIdx.y;
    int kk = blockIdx.y * 32 + threadIdx.x;
    float v = t[threadIdx.x][threadIdx.y];
    __nv_bfloat16 h = __float2bfloat16(v);
    __nv_bfloat16 l = __float2bfloat16(v - __bfloat162float(h));
    size_t ro = (size_t)nn * (size_t)(2 * K);
    O[ro + kk]     = h;
    O[ro + K + kk] = l;
}

__global__ void vt_split(
    const float* __restrict__ V, __nv_bfloat16* __restrict__ VT2)
{
    __shared__ float t[32][33];
    const int b = blockIdx.z;
    int k = blockIdx.x * 32 + threadIdx.y;
    int d = blockIdx.y * 32 + threadIdx.x;
    t[threadIdx.y][threadIdx.x] = V[((size_t)(b * TT + k)) * DD + d];
    __syncthreads();
    int dg = blockIdx.y * 32 + threadIdx.y;
    int kg = blockIdx.x * 32 + threadIdx.x;
    float v = t[threadIdx.x][threadIdx.y];
    __nv_bfloat16 h = __float2bfloat16(v);
    __nv_bfloat16 l = __float2bfloat16(v - __bfloat162float(h));
    int hh = dg >> 6, dk = dg & 63;
    size_t row = ((size_t)(b * HH + hh) * 64 + dk) * 2048;
    VT2[row + kg]        = h;
    VT2[row + 1024 + kg] = l;
}

// ===================== HMMA GEMM, 2-segment operands, 3 products in-smem ====
#define PADK2 72
#define TSTG (128 * PADK2 * 2)
#define SSTG (2 * TSTG)
#define STAGES2 3
#define GEMM_SMEM (STAGES2 * SSTG)

__global__ __launch_bounds__(256) void gemm_mma(
    const __nv_bfloat16* __restrict__ A2, const __nv_bfloat16* __restrict__ W2,
    const float* __restrict__ bias, float* __restrict__ C,
    __nv_bfloat16* __restrict__ O3, int N, int Kl, int relu)
{
    extern __shared__ char dsm[];
    const uint32_t sb = smem_u32(dsm);
    const int tid = threadIdx.x;
    const int lane = tid & 31, wid = tid >> 5;
    const int wm = wid >> 2, wn = wid & 3;
    const int grp = lane >> 2, tg = lane & 3;

    const size_t arow0 = (size_t)blockIdx.y * 128;
    const size_t bcol0 = (size_t)blockIdx.x * 128;
    const size_t rstr = (size_t)2 * Kl;

    const uint32_t aLM = (uint32_t)(((wm * 64) + (lane & 15)) * PADK2 + (lane >> 4) * 8) * 2;
    const uint32_t bLM = (uint32_t)(((wn * 32) + (lane & 15)) * PADK2 + (lane >> 4) * 8) * 2;

    float acc[4][4][4];
    #pragma unroll
    for (int i = 0; i < 4; i++)
        #pragma unroll
        for (int j = 0; j < 4; j++)
            #pragma unroll
            for (int q = 0; q < 4; q++) acc[i][j][q] = 0.f;

    const int NC = Kl >> 5;

    auto issue = [&](int c, int st) {
        const uint32_t ab = sb + st * SSTG;
        const uint32_t bb = ab + TSTG;
        #pragma unroll
        for (int i = 0; i < 4; i++) {
            int idx = tid + i * 256;
            int r = idx >> 3, s = idx & 7;
            size_t go = (s < 4) ? ((size_t)c * 32 + s * 8)
                                : ((size_t)Kl + c * 32 + (s - 4) * 8);
            uint32_t so = (uint32_t)(r * PADK2 + s * 8) * 2;
            cp16(ab + so, A2 + (arow0 + r) * rstr + go);
            cp16(bb + so, W2 + (bcol0 + r) * rstr + go);
        }
        CP_COMMIT();
    };

    issue(0, 0); issue(1, 1);

    int st = 0;
    for (int c = 0; c < NC; c++) {
        CP_WAIT1();
        __syncthreads();
        if (c + 2 < NC) {
            int ns = st + 2; if (ns >= 3) ns -= 3;
            issue(c + 2, ns);
        } else CP_COMMIT();

        const uint32_t As0 = sb + st * SSTG;
        const uint32_t Bs0 = As0 + TSTG;
        #pragma unroll
        for (int ks = 0; ks < 2; ks++) {
            const uint32_t ko = ks * 32;
            uint32_t ah[4][4], al[4][4], b2[4][2];
            #pragma unroll
            for (int ms = 0; ms < 4; ms++)
                ldm4(ah[ms][0], ah[ms][1], ah[ms][2], ah[ms][3],
                     As0 + aLM + ms * (16 * PADK2 * 2) + ko);
            ldm4(b2[0][0], b2[1][0], b2[0][1], b2[1][1], Bs0 + bLM + ko);
            ldm4(b2[2][0], b2[3][0], b2[2][1], b2[3][1], Bs0 + bLM + 16 * PADK2 * 2 + ko);
            #pragma unroll
            for (int ms = 0; ms < 4; ms++)
                #pragma unroll
                for (int ns = 0; ns < 4; ns++)
                    mma_bf16(acc[ms][ns], ah[ms], b2[ns]);
            #pragma unroll
            for (int ms = 0; ms < 4; ms++)
                ldm4(al[ms][0], al[ms][1], al[ms][2], al[ms][3],
                     As0 + aLM + ms * (16 * PADK2 * 2) + ko + 64);
            #pragma unroll
            for (int ms = 0; ms < 4; ms++)
                #pragma unroll
                for (int ns = 0; ns < 4; ns++)
                    mma_bf16(acc[ms][ns], al[ms], b2[ns]);
            ldm4(b2[0][0], b2[1][0], b2[0][1], b2[1][1], Bs0 + bLM + ko + 64);
            ldm4(b2[2][0], b2[3][0], b2[2][1], b2[3][1], Bs0 + bLM + 16 * PADK2 * 2 + ko + 64);
            #pragma unroll
            for (int ms = 0; ms < 4; ms++)
                #pragma unroll
                for (int ns = 0; ns < 4; ns++)
                    mma_bf16(acc[ms][ns], ah[ms], b2[ns]);
        }
        if (++st >= 3) st = 0;
    }

    if (O3) {
        const size_t ostr = (size_t)2 * N;
        #pragma unroll
        for (int ms = 0; ms < 4; ms++) {
            const size_t rr0 = arow0 + wm * 64 + ms * 16 + grp;
            #pragma unroll
            for (int ns = 0; ns < 4; ns++) {
                const size_t cc = bcol0 + wn * 32 + ns * 8 + tg * 2;
                float bx = bias[cc], by = bias[cc + 1];
                float v0 = fmaxf(acc[ms][ns][0] + bx, 0.f);
                float v1 = fmaxf(acc[ms][ns][1] + by, 0.f);
                float v2 = fmaxf(acc[ms][ns][2] + bx, 0.f);
                float v3 = fmaxf(acc[ms][ns][3] + by, 0.f);
                __nv_bfloat16* R0 = O3 + rr0 * ostr;
                __nv_bfloat16* R1 = O3 + (rr0 + 8) * ostr;
                *(uint32_t*)(R0 + cc)     = pack_hi2(v0, v1);
                *(uint32_t*)(R0 + N + cc) = pack_lo2(v0, v1);
                *(uint32_t*)(R1 + cc)     = pack_hi2(v2, v3);
                *(uint32_t*)(R1 + N + cc) = pack_lo2(v2, v3);
            }
        }
    } else {
        #pragma unroll
        for (int ms = 0; ms < 4; ms++) {
            const size_t rr0 = arow0 + wm * 64 + ms * 16 + grp;
            #pragma unroll
            for (int ns = 0; ns < 4; ns++) {
                const size_t cc = bcol0 + wn * 32 + ns * 8 + tg * 2;
                float bx = bias[cc], by = bias[cc + 1];
                float v0 = acc[ms][ns][0] + bx;
                float v1 = acc[ms][ns][1] + by;
                float v2 = acc[ms][ns][2] + bx;
                float v3 = acc[ms][ns][3] + by;
                if (relu) {
                    v0 = fmaxf(v0, 0.f); v1 = fmaxf(v1, 0.f);
                    v2 = fmaxf(v2, 0.f); v3 = fmaxf(v3, 0.f);
                }
                *(float2*)(C + rr0 * N + cc)       = make_float2(v0, v1);
                *(float2*)(C + (rr0 + 8) * N + cc) = make_float2(v2, v3);
            }
        }
    }
}

// ===================== attention scores + fused softmax stats ======
// One CTA per (z, q0): loops all k-tiles, writes raw S and final (m, 1/sum).
#define SPAD2 136
#define SCORES_SMEM ((128 + 64) * SPAD2 * 2 + 128 * 16 + 4096)
__global__ __launch_bounds__(256) void attn_scores_mma(
    const float* __restrict__ Q, const float* __restrict__ Kv,
    float* __restrict__ Sc, float* __restrict__ st,
    const int* __restrict__ mask, int causal)
{
    extern __shared__ __nv_bfloat16 sm[];
    __nv_bfloat16* As = sm;                 // [128][SPAD2]  Q: [hi|lo]
    __nv_bfloat16* Bs = sm + 128 * SPAD2;   // [64][SPAD2]   K: [hi|lo]
    float* stg = (float*)(sm + (128 + 64) * SPAD2);   // [128][2][2]
    int*   msk = (int*)(stg + 128 * 4);               // [1024]
    const int z = blockIdx.y, b = z >> 4, h = z & 15;
    const int q0 = blockIdx.x * 128;

    const int tid = threadIdx.x, lane = tid & 31, wid = tid >> 5;
    const int wm = wid >> 1, wn = wid & 1;
    const int grp = lane >> 2, tg = lane & 3;

    const float* Qb = Q + ((size_t)(b * TT + q0)) * DD + h * DKD;

    #pragma unroll
    for (int i = 0; i < 8; i++) {
        int f = tid + i * 256;
        int r = f >> 4, c = (f & 15) << 2;
        float4 v = *(const float4*)(Qb + (size_t)r * DD + c);
        uint2 hh, ll;
        hh.x = pack_hi2(v.x, v.y); hh.y = pack_hi2(v.z, v.w);
        ll.x = pack_lo2(v.x, v.y); ll.y = pack_lo2(v.z, v.w);
        __nv_bfloat16* R = As + r * SPAD2;
        *(uint2*)(R + c)      = hh;
        *(uint2*)(R + 64 + c) = ll;
    }
    if (!causal) {
        #pragma unroll
        for (int i = 0; i < 4; i++) msk[tid + i * 256] = mask[b * SS + tid + i * 256];
    }

    const uint32_t AsU = smem_u32(As), BsU = smem_u32(Bs);
    const uint32_t aLM = AsU + (uint32_t)(((wm * 32) + (lane & 15)) * SPAD2 + (lane >> 4) * 8) * 2;
    const uint32_t bLM = BsU + (uint32_t)(((wn * 32) + (lane & 15)) * SPAD2 + (lane >> 4) * 8) * 2;

    // per-thread online stats over its 4 (mi, half) rows
    float ms_[2][2] = {{-3.0e38f, -3.0e38f}, {-3.0e38f, -3.0e38f}};
    float ss_[2][2] = {{0.f, 0.f}, {0.f, 0.f}};
    const int ktend = causal ? ((q0 >> 6) + 2) : 16;

    for (int kt = 0; kt < ktend; kt++) {
        const int k0 = kt * 64;
        __syncthreads();
        const float* Kb = Kv + ((size_t)(b * TT + k0)) * DD + h * DKD;
        #pragma unroll
        for (int i = 0; i < 4; i++) {
            int f = tid + i * 256;
            int r = f >> 4, c = (f & 15) << 2;
            float4 v = *(const float4*)(Kb + (size_t)r * DD + c);
            uint2 hh, ll;
            hh.x = pack_hi2(v.x, v.y); hh.y = pack_hi2(v.z, v.w);
            ll.x = pack_lo2(v.x, v.y); ll.y = pack_lo2(v.z, v.w);
            __nv_bfloat16* R = Bs + r * SPAD2;
            *(uint2*)(R + c)      = hh;
            *(uint2*)(R + 64 + c) = ll;
        }
        __syncthreads();

        float acc[2][4][4];
        #pragma unroll
        for (int i = 0; i < 2; i++)
            #pragma unroll
            for (int j = 0; j < 4; j++)
                #pragma unroll
                for (int q = 0; q < 4; q++) acc[i][j][q] = 0.f;

        #pragma unroll
        for (int ks = 0; ks < 4; ks++) {
            const uint32_t ko = ks * 32;
            uint32_t ah[2][4], al[2][4], bb[4][2];
            #pragma unroll
            for (int mi = 0; mi < 2; mi++)
                ldm4(ah[mi][0], ah[mi][1], ah[mi][2], ah[mi][3],
                     aLM + mi * (16 * SPAD2 * 2) + ko);
            ldm4(bb[0][0], bb[1][0], bb[0][1], bb[1][1], bLM + ko);
            ldm4(bb[2][0], bb[3][0], bb[2][1], bb[3][1], bLM + 16 * SPAD2 * 2 + ko);
            #pragma unroll
            for (int mi = 0; mi < 2; mi++)
                #pragma unroll
                for (int ni = 0; ni < 4; ni++)
                    mma_bf16(acc[mi][ni], ah[mi], bb[ni]);
            #pragma unroll
            for (int mi = 0; mi < 2; mi++)
                ldm4(al[mi][0], al[mi][1], al[mi][2], al[mi][3],
                     aLM + mi * (16 * SPAD2 * 2) + ko + 128);
            #pragma unroll
            for (int mi = 0; mi < 2; mi++)
                #pragma unroll
                for (int ni = 0; ni < 4; ni++)
                    mma_bf16(acc[mi][ni], al[mi], bb[ni]);
            ldm4(bb[0][0], bb[1][0], bb[0][1], bb[1][1], bLM + ko + 128);
            ldm4(bb[2][0], bb[3][0], bb[2][1], bb[3][1], bLM + 16 * SPAD2 * 2 + ko + 128);
            #pragma unroll
            for (int mi = 0; mi < 2; mi++)
                #pragma unroll
                for (int ni = 0; ni < 4; ni++)
                    mma_bf16(acc[mi][ni], ah[mi], bb[ni]);
        }

        // write raw S tile + update online stats
        float* Out = Sc + ((size_t)z * TT + q0) * TT + k0;
        #pragma unroll
        for (int mi = 0; mi < 2; mi++) {
            const size_t r = wm * 32 + mi * 16 + grp;
            #pragma unroll
            for (int ni = 0; ni < 4; ni++) {
                const size_t c = wn * 32 + ni * 8 + tg * 2;
                *(float2*)(Out + r * TT + c) =
                    make_float2(acc[mi][ni][0] * 0.125f, acc[mi][ni][1] * 0.125f);
                *(float2*)(Out + (r + 8) * TT + c) =
                    make_float2(acc[mi][ni][2] * 0.125f, acc[mi][ni][3] * 0.125f);
            }
        }
        #pragma unroll
        for (int mi = 0; mi < 2; mi++) {
            #pragma unroll
            for (int half = 0; half < 2; half++) {
                const int q = q0 + wm * 32 + mi * 16 + half * 8 + grp;
                float vv[8];
                float tm = -3.0e38f;
                #pragma unroll
                for (int ni = 0; ni < 4; ni++) {
                    #pragma unroll
                    for (int e = 0; e < 2; e++) {
                        int k = k0 + wn * 32 + ni * 8 + tg * 2 + e;
                        float v = acc[mi][ni][half * 2 + e] * 0.125f;
                        int valid = causal ? (k <= q) : msk[k];
                        v = valid ? v : -1e9f;
                        vv[ni * 2 + e] = v;
                        tm = fmaxf(tm, v);
                    }
                }
                float m = ms_[mi][half];
                float nm = fmaxf(m, tm);
                float as = 0.f;
                #pragma unroll
                for (int i = 0; i < 8; i++) as += __expf(vv[i] - nm);
                ss_[mi][half] = ss_[mi][half] * __expf(m - nm) + as;
                ms_[mi][half] = nm;
            }
        }
    }

    // final reduction: over tg (shfl xor 1,2), then over wn via smem
    #pragma unroll
    for (int mi = 0; mi < 2; mi++) {
        #pragma unroll
        for (int half = 0; half < 2; half++) {
            float m = ms_[mi][half], s = ss_[mi][half];
            #pragma unroll
            for (int o = 1; o <= 2; o <<= 1) {
                float mo = __shfl_xor_sync(0xffffffffu, m, o);
                float so = __shfl_xor_sync(0xffffffffu, s, o);
                float nm = fmaxf(m, mo);
                s = s * __expf(m - nm) + so * __expf(mo - nm);
                m = nm;
            }
            if (tg == 0) {
                int row = wm * 32 + mi * 16 + half * 8 + grp;
                stg[(row * 2 + wn) * 2]     = m;
                stg[(row * 2 + wn) * 2 + 1] = s;
            }
        }
    }
    __syncthreads();
    if (tid < 128) {
        float m0 = stg[(tid * 2) * 2],     s0 = stg[(tid * 2) * 2 + 1];
        float m1 = stg[(tid * 2 + 1) * 2], s1 = stg[(tid * 2 + 1) * 2 + 1];
        float M = fmaxf(m0, m1);
        float S = s0 * __expf(m0 - M) + s1 * __expf(m1 - M);
        st[((size_t)z * TT + q0 + tid) * 2]     = M;
        st[((size_t)z * TT + q0 + tid) * 2 + 1] = 1.0f / S;
    }
}

// ===================== attn @ V with fused softmax-apply =====================
#define AV_SMEM ((64 + 64) * SPAD2 * 2 + 512)
__global__ __launch_bounds__(256) void attn_av_mma(
    float* __restrict__ Sc, const __nv_bfloat16* __restrict__ VT2,
    const float* __restrict__ st, const int* __restrict__ mask,
    __nv_bfloat16* __restrict__ A2out, int causal)
{
    extern __shared__ __nv_bfloat16 sm[];
    __nv_bfloat16* As = sm;                // [64][SPAD2]  P: [hi|lo]
    __nv_bfloat16* Bs = sm + 64 * SPAD2;   // [64][SPAD2]  V^T: [hi|lo]
    float* stats = (float*)(sm + (64 + 64) * SPAD2);
    const int z = blockIdx.y, b = z >> 4, h = z & 15;
    const int q0 = blockIdx.x * 64;

    const int tid = threadIdx.x, lane = tid & 31, wid = tid >> 5;
    const int wm = wid >> 1, wn = wid & 1;
    const int grp = lane >> 2, tg = lane & 3;

    const int kend = causal ? (q0 + 64) : TT;

    if (tid < 64) {
        stats[tid]      = st[((size_t)z * TT + q0 + tid) * 2];
        stats[64 + tid] = st[((size_t)z * TT + q0 + tid) * 2 + 1];
    }
    __syncthreads();

    const __nv_bfloat16* Vt = VT2 + (size_t)z * 64 * 2048;
    const uint32_t AsU = smem_u32(As), BsU = smem_u32(Bs);
    const uint32_t aLM = AsU + (uint32_t)(((wm * 16) + (lane & 15)) * SPAD2 + (lane >> 4) * 8) * 2;
    const uint32_t bLM = BsU + (uint32_t)(((wn * 32) + (lane & 15)) * SPAD2 + (lane >> 4) * 8) * 2;

    float acc[4][4];
    #pragma unroll
    for (int i = 0; i < 4; i++)
        #pragma unroll
        for (int j = 0; j < 4; j++) acc[i][j] = 0.f;

    for (int k0 = 0; k0 < kend; k0 += 64) {
        float* Pb = Sc + ((size_t)z * TT + q0) * TT + k0;
        #pragma unroll
        for (int i = 0; i < 4; i++) {
            int f = tid + i * 256;
            int r = f >> 4, c = (f & 15) << 2;
            float4 pv = *(float4*)(Pb + (size_t)r * TT + c);
            const int qabs = q0 + r;
            const int kg = k0 + c;
            float v0, v1, v2, v3;
            if (causal) {
                v0 = (kg     <= qabs) ? pv.x : -1e9f;
                v1 = (kg + 1 <= qabs) ? pv.y : -1e9f;
                v2 = (kg + 2 <= qabs) ? pv.z : -1e9f;
                v3 = (kg + 3 <= qabs) ? pv.w : -1e9f;
            } else {
                int4 mk = *(const int4*)(mask + b * SS + kg);
                v0 = mk.x ? pv.x : -1e9f;
                v1 = mk.y ? pv.y : -1e9f;
                v2 = mk.z ? pv.z : -1e9f;
                v3 = mk.w ? pv.w : -1e9f;
            }
            const float mm = stats[r], iv = stats[64 + r];
            float p0 = __expf(v0 - mm) * iv;
            float p1 = __expf(v1 - mm) * iv;
            float p2 = __expf(v2 - mm) * iv;
            float p3 = __expf(v3 - mm) * iv;
            *(float4*)(Pb + (size_t)r * TT + c) = make_float4(p0, p1, p2, p3);
            uint2 hh, ll;
            hh.x = pack_hi2(p0, p1); hh.y = pack_hi2(p2, p3);
            ll.x = pack_lo2(p0, p1); ll.y = pack_lo2(p2, p3);
            __nv_bfloat16* R = As + r * SPAD2;
            *(uint2*)(R + c)      = hh;
            *(uint2*)(R + 64 + c) = ll;
        }
        #pragma unroll
        for (int i = 0; i < 4; i++) {
            int idx = tid + i * 256;
            int d = idx >> 4, rem = idx & 15;
            int band = rem >> 3, j = rem & 7;
            uint4 v = *(const uint4*)(Vt + (size_t)d * 2048 + band * 1024 + k0 + j * 8);
            *(uint4*)(Bs + d * SPAD2 + band * 64 + j * 8) = v;
        }
        __syncthreads();
        #pragma unroll
        for (int ks = 0; ks < 4; ks++) {
            const uint32_t ko = ks * 32;
            uint32_t ah[4], al[4], bb[4][2];
            ldm4(ah[0], ah[1], ah[2], ah[3], aLM + ko);
            ldm4(bb[0][0], bb[1][0], bb[0][1], bb[1][1], bLM + ko);
            ldm4(bb[2][0], bb[3][0], bb[2][1], bb[3][1], bLM + 16 * SPAD2 * 2 + ko);
            #pragma unroll
            for (int ni = 0; ni < 4; ni++)
                mma_bf16(acc[ni], ah, bb[ni]);
            ldm4(al[0], al[1], al[2], al[3], aLM + ko + 128);
            #pragma unroll
            for (int ni = 0; ni < 4; ni++)
                mma_bf16(acc[ni], al, bb[ni]);
            ldm4(bb[0][0], bb[1][0], bb[0][1], bb[1][1], bLM + ko + 128);
            ldm4(bb[2][0], bb[3][0], bb[2][1], bb[3][1], bLM + 16 * SPAD2 * 2 + ko + 128);
            #pragma unroll
            for (int ni = 0; ni < 4; ni++)
                mma_bf16(acc[ni], ah, bb[ni]);
        }
        __syncthreads();
    }

    if (causal && kend < TT) {
        const int Z = TT - kend;
        const int zw = Z >> 2;
        const int n4 = 64 * zw;
        const float4 z4 = make_float4(0.f, 0.f, 0.f, 0.f);
        for (int i = tid; i < n4; i += 256) {
            int r = i / zw, c = kend + (i - r * zw) * 4;
            *(float4*)(Sc + ((size_t)z * TT + q0 + r) * TT + c) = z4;
        }
    }

    const size_t m0 = (size_t)b * TT + q0 + wm * 16 + grp;
    const size_t m1 = m0 + 8;
    __nv_bfloat16* R0 = A2out + m0 * 2048;
    __nv_bfloat16* R1 = A2out + m1 * 2048;
    #pragma unroll
    for (int ni = 0; ni < 4; ni++) {
        const int cc = h * DKD + wn * 32 + ni * 8 + tg * 2;
        float v0 = acc[ni][0], v1 = acc[ni][1];
        float v2 = acc[ni][2], v3 = acc[ni][3];
        *(uint32_t*)(R0 + cc)        = pack_hi2(v0, v1);
        *(uint32_t*)(R0 + 1024 + cc) = pack_lo2(v0, v1);
        *(uint32_t*)(R1 + cc)        = pack_hi2(v2, v3);
        *(uint32_t*)(R1 + 1024 + cc) = pack_lo2(v2, v3);
    }
}

// ===================== residual add + LayerNorm =====================
__global__ __launch_bounds__(256) void add_ln(
    const float* __restrict__ X, const float* __restrict__ Dl,
    const float* __restrict__ g, const float* __restrict__ be,
    float* __restrict__ O, __nv_bfloat16* __restrict__ S2)
{
    const int row = blockIdx.x;
    const float* x  = X  + (size_t)row * DD;
    const float* dl = Dl + (size_t)row * DD;
    const int tid = threadIdx.x;

    float v[4];
    float s = 0.f;
    #pragma unroll
    for (int i = 0; i < 4; i++) {
        int c = tid + i * 256;
        v[i] = x[c] + dl[c];
        s += v[i];
    }
    __shared__ float red[8];
    #pragma unroll
    for (int o = 16; o > 0; o >>= 1) s += __shfl_xor_sync(0xffffffffu, s, o);
    if ((tid & 31) == 0) red[tid >> 5] = s;
    __syncthreads();
    s = 0.f;
    #pragma unroll
    for (int w = 0; w < 8; w++) s += red[w];
    float mean = s * (1.0f / 1024.0f);

    float qq = 0.f;
    #pragma unroll
    for (int i = 0; i < 4; i++) { float d = v[i] - mean; qq += d * d; }
    __syncthreads();
    #pragma unroll
    for (int o = 16; o > 0; o >>= 1) qq += __shfl_xor_sync(0xffffffffu, qq, o);
    if ((tid & 31) == 0) red[tid >> 5] = qq;
    __syncthreads();
    qq = 0.f;
    #pragma unroll
    for (int w = 0; w < 8; w++) qq += red[w];

    float stdv = sqrtf(qq * (1.0f / 1023.0f));
    float inv = 1.0f / (stdv + LN_EPS);
    __nv_bfloat16* R = S2 ? (S2 + (size_t)row * 2048) : (__nv_bfloat16*)0;
    #pragma unroll
    for (int i = 0; i < 4; i++) {
        int c = tid + i * 256;
        float o = g[c] * (v[i] - mean) * inv + be[c];
        O[(size_t)row * DD + c] = o;
        if (R) {
            __nv_bfloat16 h = __float2bfloat16(o);
            __nv_bfloat16 l = __float2bfloat16(o - __bfloat162float(h));
            R[c]        = h;
            R[1024 + c] = l;
        }
    }
}

// ===================== orchestration =====================
extern "C" void kernel_launch(void* const* d_in, const int* in_sizes, int n_in,
                              void* d_out, int out_size)
{
    const float* x        = (const float*)d_in[0];
    const float* enc      = (const float*)d_in[1];
    const int*   src_mask = (const int*)  d_in[2];
    const float* wq_s = (const float*)d_in[4],  *bq_s = (const float*)d_in[5];
    const float* wk_s = (const float*)d_in[6],  *bk_s = (const float*)d_in[7];
    const float* wv_s = (const float*)d_in[8],  *bv_s = (const float*)d_in[9];
    const float* wo_s = (const float*)d_in[10], *bo_s = (const float*)d_in[11];
    const float* wq_c = (const float*)d_in[12], *bq_c = (const float*)d_in[13];
    const float* wk_c = (const float*)d_in[14], *bk_c = (const float*)d_in[15];
    const float* wv_c = (const float*)d_in[16], *bv_c = (const float*)d_in[17];
    const float* wo_c = (const float*)d_in[18], *bo_c = (const float*)d_in[19];
    const float* w1   = (const float*)d_in[20], *b1   = (const float*)d_in[21];
    const float* w2   = (const float*)d_in[22], *b2   = (const float*)d_in[23];
    const float* g1   = (const float*)d_in[24], *be1  = (const float*)d_in[25];
    const float* g2   = (const float*)d_in[26], *be2  = (const float*)d_in[27];
    const float* g3   = (const float*)d_in[28], *be3  = (const float*)d_in[29];

    float* out     = (float*)d_out;
    float* self_w  = out + (size_t)BB * TT * DD;
    float* cross_w = self_w + (size_t)BB * HH * TT * TT;

    float *Q, *K, *V, *T1, *X1, *X2, *ST;
    __nv_bfloat16 *A2, *FF2, *WT2, *VT2;
    cudaGetSymbolAddress((void**)&Q,   g_q);
    cudaGetSymbolAddress((void**)&K,   g_k);
    cudaGetSymbolAddress((void**)&V,   g_v);
    cudaGetSymbolAddress((void**)&T1,  g_t1);
    cudaGetSymbolAddress((void**)&X1,  g_x1);
    cudaGetSymbolAddress((void**)&X2,  g_x2);
    cudaGetSymbolAddress((void**)&ST,  g_st);
    cudaGetSymbolAddress((void**)&A2,  g_a2);
    cudaGetSymbolAddress((void**)&FF2, g_ff2);
    cudaGetSymbolAddress((void**)&WT2, g_wt2);
    cudaGetSymbolAddress((void**)&VT2, g_vt2);

    cudaFuncSetAttribute(gemm_mma,        cudaFuncAttributeMaxDynamicSharedMemorySize, GEMM_SMEM);
    cudaFuncSetAttribute(attn_scores_mma, cudaFuncAttributeMaxDynamicSharedMemorySize, SCORES_SMEM);
    cudaFuncSetAttribute(attn_av_mma,     cudaFuncAttributeMaxDynamicSharedMemorySize, AV_SMEM);

    const int M = BB * TT;
    dim3 blk(256);
    dim3 tp32(32, 32);
    dim3 gD(DD / 128, M / 128);
    dim3 gF(DFFN / 128, M / 128);
    dim3 scoreG(TT / 128, BB * HH);
    dim3 avG(TT / 64, BB * HH);
    dim3 vtG(TT / 32, DD / 32, BB);
    dim3 lnG(M);
    const int ACT_BLKS = M * DD / 4 / 256;
    float* NC = (float*)0;
    __nv_bfloat16* NO3 = (__nv_bfloat16*)0;

    // ---- self attention ----
    split_act<<<ACT_BLKS, blk>>>(x, A2);
    split_w<<<dim3(32, 32), tp32>>>(wq_s, WT2 + 0 * W2D, DD, DD);
    split_w<<<dim3(32, 32), tp32>>>(wk_s, WT2 + 1 * W2D, DD, DD);
    split_w<<<dim3(32, 32), tp32>>>(wv_s, WT2 + 2 * W2D, DD, DD);
    split_w<<<dim3(32, 32), tp32>>>(wo_s, WT2 + 3 * W2D, DD, DD);
    gemm_mma<<<gD, blk, GEMM_SMEM>>>(A2, WT2 + 0 * W2D, bq_s, Q, NO3, DD, 1024, 0);
    gemm_mma<<<gD, blk, GEMM_SMEM>>>(A2, WT2 + 1 * W2D, bk_s, K, NO3, DD, 1024, 0);
    gemm_mma<<<gD, blk, GEMM_SMEM>>>(A2, WT2 + 2 * W2D, bv_s, V, NO3, DD, 1024, 0);
    vt_split<<<vtG, tp32>>>(V, VT2);
    attn_scores_mma<<<scoreG, blk, SCORES_SMEM>>>(Q, K, self_w, ST, src_mask, 1);
    attn_av_mma<<<avG, blk, AV_SMEM>>>(self_w, VT2, ST, src_mask, A2, 1);
    gemm_mma<<<gD, blk, GEMM_SMEM>>>(A2, WT2 + 3 * W2D, bo_s, T1, NO3, DD, 1024, 0);
    add_ln<<<lnG, blk>>>(x, T1, g1, be1, X1, A2);

    // ---- remaining weight splits ----
    split_w<<<dim3(32, 32), tp32>>>(wq_c, WT2 + 4 * W2D, DD, DD);
    split_w<<<dim3(32, 32), tp32>>>(wk_c, WT2 + 5 * W2D, DD, DD);
    split_w<<<dim3(32, 32), tp32>>>(wv_c, WT2 + 6 * W2D, DD, DD);
    split_w<<<dim3(32, 32), tp32>>>(wo_c, WT2 + 7 * W2D, DD, DD);
    split_w<<<dim3(128, 32), tp32>>>(w1, WT2 + W1OFF, DD, DFFN);
    split_w<<<dim3(32, 128), tp32>>>(w2, WT2 + W2OFF, DFFN, DD);

    // ---- cross attention ----
    gemm_mma<<<gD, blk, GEMM_SMEM>>>(A2, WT2 + 4 * W2D, bq_c, Q, NO3, DD, 1024, 0);
    split_act<<<ACT_BLKS, blk>>>(enc, A2);
    gemm_mma<<<gD, blk, GEMM_SMEM>>>(A2, WT2 + 5 * W2D, bk_c, K, NO3, DD, 1024, 0);
    gemm_mma<<<gD, blk, GEMM_SMEM>>>(A2, WT2 + 6 * W2D, bv_c, V, NO3, DD, 1024, 0);
    vt_split<<<vtG, tp32>>>(V, VT2);
    attn_scores_mma<<<scoreG, blk, SCORES_SMEM>>>(Q, K, cross_w, ST, src_mask, 0);
    attn_av_mma<<<avG, blk, AV_SMEM>>>(cross_w, VT2, ST, src_mask, A2, 0);
    gemm_mma<<<gD, blk, GEMM_SMEM>>>(A2, WT2 + 7 * W2D, bo_c, T1, NO3, DD, 1024, 0);
    add_ln<<<lnG, blk>>>(X1, T1, g2, be2, X2, A2);

    // ---- feed-forward ----
    gemm_mma<<<gF, blk, GEMM_SMEM>>>(A2, WT2 + W1OFF, b1, NC, FF2, DFFN, 1024, 1);
    gemm_mma<<<gD, blk, GEMM_SMEM>>>(FF2, WT2 + W2OFF, b2, T1, NO3, DD, 4096, 0);
    add_ln<<<lnG, blk>>>(X2, T1, g3, be3, out, NO3);

    (void)in_sizes; (void)n_in; (void)out_size;
}